// round 13
// baseline (speedup 1.0000x reference)
#include <cuda_runtime.h>
#include <cuda_bf16.h>
#include <cuda_fp16.h>
#include <math.h>
#include <stdint.h>

// Problem constants
#define BB 8
#define NN 512
#define DD 512
#define DEG_ 16
#define EE 65536   // B*N*DEG
#define ROWS 4096  // B*N
#define GK 512     // K dim of all big GEMMs
#define SCALE 0.17677669529663687f  // 1/sqrt(32)
#define LOG2F_ 0.6931471805599453f

// ---------------- scratch (device globals; no allocs allowed) ----------------
__device__ float g_q[ROWS * DD];
__device__ float g_k[ROWS * DD];
__device__ float g_v[ROWS * DD];
__device__ float g_PQ[ROWS * 1024];
__device__ float g_ef[(size_t)EE * 256];

__device__ __half g_f1[(size_t)EE * DD];
__device__ __half g_eu[(size_t)EE * DD];
__device__ __half g_xK[ROWS * DD];
__device__ __half g_xQ[ROWS * DD];
__device__ __half g_xV[ROWS * DD];
__device__ __half g_xC[ROWS * DD];   // ctx in fp16

// weights fp16: 0 WkT,1 WqT,2 WvT,3 WoT,4 Wu1T(1024x512),6 Wu2T,7 We1T,8 We2T(256x512),9 Wo natural
__device__ __half g_WHi[10 * 262144];
__device__ __half g_WPQ[1024 * 512];   // W'^T = (Wo@Wu1)^T, [1024,512]
__device__ float g_biasPQ[1024];
__device__ float g_bPQ[1024];          // b' = bo@Wu1 + biasPQ

__device__ __forceinline__ float softplusf(float x) {
    return fmaxf(x, 0.f) + log1pf(expf(-fabsf(x)));
}

__device__ __forceinline__ uint32_t smem_to_u32(const void* smem_ptr) {
    uint32_t addr;
    asm("{ .reg .u64 tmp; cvta.to.shared.u64 tmp, %1; cvt.u32.u64 %0, tmp; }"
        : "=r"(addr) : "l"(smem_ptr));
    return addr;
}

// ---------------- PTX: cp.async / ldmatrix / mma (base-arch legal) ----------------
__device__ __forceinline__ void cpasync16(uint32_t saddr, const void* g) {
    asm volatile("cp.async.cg.shared.global [%0], [%1], 16;" :: "r"(saddr), "l"(g));
}
#define CP_COMMIT() asm volatile("cp.async.commit_group;")
#define CP_WAIT(n)  asm volatile("cp.async.wait_group %0;" :: "n"(n))

__device__ __forceinline__ void ldmx4(uint32_t r[4], uint32_t addr) {
    asm volatile("ldmatrix.sync.aligned.m8n8.x4.shared.b16 {%0,%1,%2,%3}, [%4];"
                 : "=r"(r[0]), "=r"(r[1]), "=r"(r[2]), "=r"(r[3]) : "r"(addr));
}

__device__ __forceinline__ void mma16816(float c[4], const uint32_t a[4],
                                         uint32_t b0, uint32_t b1) {
    asm volatile("mma.sync.aligned.m16n8k16.row.col.f32.f16.f16.f32 "
                 "{%0,%1,%2,%3}, {%4,%5,%6,%7}, {%8,%9}, {%0,%1,%2,%3};"
                 : "+f"(c[0]), "+f"(c[1]), "+f"(c[2]), "+f"(c[3])
                 : "r"(a[0]), "r"(a[1]), "r"(a[2]), "r"(a[3]), "r"(b0), "r"(b1));
}

__device__ __forceinline__ uint32_t packh2(float x, float y) {
    __half2 h = __floats2half2_rn(x, y);
    return *(uint32_t*)&h;
}

// ======================= tensor-core GEMM core (mma.sync fp16) ===============
#define ROWB 80
#define TILE_B (128 * ROWB)      // 10240
#define A_OFF 0
#define B_OFF (1 * TILE_B)
#define STAGE_B (2 * TILE_B)     // 20480
#define NSTAGE 4
#define TC_SMEM (NSTAGE * STAGE_B)  // 81920

// OUT: 0 = f32 only, 1 = fp16 only, 2 = f32 + fp16
template <int SOFTPLUS, int OUT>
__device__ __forceinline__ void tc_gemm_core(
    char* smem,
    const __half* __restrict__ A, const __half* __restrict__ B,
    const float* __restrict__ bias,
    float* __restrict__ Cf, __half* __restrict__ Ch,
    int N, int bm, int bn)
{
    const uint32_t sb = smem_to_u32(smem);
    const int t = threadIdx.x, lane = t & 31, w = t >> 5;
    const int wm = w & 3, wn = w >> 2;
    constexpr int KT = GK / 32;   // 16

    float acc[2][8][4] = {};

    const __half* pA[2];
    const __half* pB[2];
    uint32_t so[2];
#pragma unroll
    for (int i = 0; i < 2; i++) {
        const int id = t + i * 256;
        const int row = id >> 2, ch = id & 3;
        so[i] = row * ROWB + ch * 16;
        pA[i] = A + (size_t)(bm + row) * GK + ch * 8;
        pB[i] = B + (size_t)(bn + row) * GK + ch * 8;
    }

    auto issue = [&](int kcI, uint32_t stbase) {
#pragma unroll
        for (int i = 0; i < 2; i++) {
            cpasync16(stbase + A_OFF + so[i], pA[i] + kcI * 32);
            cpasync16(stbase + B_OFF + so[i], pB[i] + kcI * 32);
        }
    };

    const uint32_t aRow = (uint32_t)(wm * 32 + (lane & 15)) * ROWB + ((lane >> 4) << 4);
    const int n_off = (lane & 7) + ((lane >> 4) << 3);
    const int k_half = (lane >> 3) & 1;
    const uint32_t bRow = (uint32_t)(wn * 64 + n_off) * ROWB + (k_half << 4);

    issue(0, sb);               CP_COMMIT();
    issue(1, sb + STAGE_B);     CP_COMMIT();
    issue(2, sb + 2 * STAGE_B); CP_COMMIT();

#pragma unroll
    for (int kc = 0; kc < KT; kc++) {
        if (kc + 2 < KT)      { CP_WAIT(2); }
        else if (kc + 1 < KT) { CP_WAIT(1); }
        else                  { CP_WAIT(0); }
        __syncthreads();
        if (kc + 3 < KT) {
            issue(kc + 3, sb + ((kc + 3) & 3) * STAGE_B);
            CP_COMMIT();
        }
        const uint32_t cur = sb + (kc & 3) * STAGE_B;

#pragma unroll
        for (int ks = 0; ks < 2; ks++) {
            const uint32_t kb = ks * 32;
            uint32_t a[2][4], bh[4][4];
            ldmx4(a[0], cur + A_OFF + aRow + kb);
            ldmx4(a[1], cur + A_OFF + aRow + 16 * ROWB + kb);
#pragma unroll
            for (int jj = 0; jj < 4; jj++)
                ldmx4(bh[jj], cur + B_OFF + bRow + jj * 16 * ROWB + kb);
#pragma unroll
            for (int g = 0; g < 2; g++) {
#pragma unroll
                for (int j = 0; j < 8; j++) {
                    const int jj = j >> 1, hf = (j & 1) * 2;
                    mma16816(acc[g][j], a[g], bh[jj][hf], bh[jj][hf + 1]);
                }
            }
        }
    }

    float bcol[16];
    {
        const int col0 = bn + wn * 64 + (lane & 3) * 2;
#pragma unroll
        for (int j = 0; j < 8; j++) {
            bcol[j * 2]     = bias ? bias[col0 + j * 8]     : 0.f;
            bcol[j * 2 + 1] = bias ? bias[col0 + j * 8 + 1] : 0.f;
        }
    }
#pragma unroll
    for (int g = 0; g < 2; g++) {
#pragma unroll
        for (int j = 0; j < 8; j++) {
            const int row = bm + wm * 32 + g * 16 + (lane >> 2);
            const int col = bn + wn * 64 + j * 8 + (lane & 3) * 2;
            float v0 = acc[g][j][0] + bcol[j * 2], v1 = acc[g][j][1] + bcol[j * 2 + 1];
            float v2 = acc[g][j][2] + bcol[j * 2], v3 = acc[g][j][3] + bcol[j * 2 + 1];
            if (SOFTPLUS) {
                v0 = softplusf(v0) - LOG2F_; v1 = softplusf(v1) - LOG2F_;
                v2 = softplusf(v2) - LOG2F_; v3 = softplusf(v3) - LOG2F_;
            }
            if (OUT == 0 || OUT == 2) {
                *(float2*)(Cf + (size_t)row * N + col) = make_float2(v0, v1);
                *(float2*)(Cf + (size_t)(row + 8) * N + col) = make_float2(v2, v3);
            }
            if (OUT == 1 || OUT == 2) {
                *(uint32_t*)(Ch + (size_t)row * N + col) = packh2(v0, v1);
                *(uint32_t*)(Ch + (size_t)(row + 8) * N + col) = packh2(v2, v3);
            }
        }
    }
}

template <int SOFTPLUS, int OUT>
__global__ __launch_bounds__(256, 2) void tc_gemm(
    const __half* __restrict__ A, const __half* __restrict__ B,
    const float* __restrict__ bias,
    float* __restrict__ Cf, __half* __restrict__ Ch,
    int N)
{
    extern __shared__ char smem[];
    tc_gemm_core<SOFTPLUS, OUT>(smem, A, B, bias, Cf, Ch, N,
                                blockIdx.y * 128, blockIdx.x * 128);
}

// batched K/Q/V projection: blockIdx.z selects the triple
__global__ __launch_bounds__(256, 2) void tc_gemm_qkv(
    const __half* __restrict__ xK, const __half* __restrict__ xQ, const __half* __restrict__ xV,
    const __half* __restrict__ WkT, const __half* __restrict__ WqT, const __half* __restrict__ WvT,
    const float* __restrict__ bk, const float* __restrict__ bq, const float* __restrict__ bv,
    float* __restrict__ k_, float* __restrict__ q_, float* __restrict__ v_)
{
    extern __shared__ char smem[];
    const int z = blockIdx.z;
    const __half* A = (z == 0) ? xK : (z == 1) ? xQ : xV;
    const __half* B = (z == 0) ? WkT : (z == 1) ? WqT : WvT;
    const float* bias = (z == 0) ? bk : (z == 1) ? bq : bv;
    float* C = (z == 0) ? k_ : (z == 1) ? q_ : v_;
    tc_gemm_core<0, 0>(smem, A, B, bias, C, nullptr, 512,
                       blockIdx.y * 128, blockIdx.x * 128);
}

// ======================= MLP1 GEMM with fused f32->fp16 A conversion =======================
#define AF_A32 0
#define AF_B   18432
#define AF_STAGE (18432 + 10240) // 28672
#define AF_F16 (3 * AF_STAGE)    // 86016
#define AF_SMEM (AF_F16 + 10240) // 96256

__global__ __launch_bounds__(256, 2) void tc_gemm_f32a(
    const float* __restrict__ A, const __half* __restrict__ B,
    const float* __restrict__ bias, __half* __restrict__ Ch, int N)
{
    extern __shared__ char smem[];
    const uint32_t sb = smem_to_u32(smem);
    const int t = threadIdx.x, lane = t & 31, w = t >> 5;
    const int wm = w & 3, wn = w >> 2;
    const int bm = blockIdx.y * 128, bn = blockIdx.x * 128;
    constexpr int KT = GK / 32;   // 16

    float acc[2][8][4] = {};

    const float* pA[4];
    uint32_t soA[4];
#pragma unroll
    for (int i = 0; i < 4; i++) {
        const int id = t + i * 256;
        const int row = id >> 3, ch = id & 7;
        soA[i] = row * 144 + ch * 16;
        pA[i] = A + (size_t)(bm + row) * GK + ch * 4;
    }
    const __half* pB[2];
    uint32_t soB[2];
#pragma unroll
    for (int i = 0; i < 2; i++) {
        const int id = t + i * 256;
        const int row = id >> 2, ch = id & 3;
        soB[i] = row * ROWB + ch * 16;
        pB[i] = B + (size_t)(bn + row) * GK + ch * 8;
    }

    auto issue = [&](int kcI, uint32_t st) {
#pragma unroll
        for (int i = 0; i < 4; i++) cpasync16(st + AF_A32 + soA[i], pA[i] + kcI * 32);
#pragma unroll
        for (int i = 0; i < 2; i++) cpasync16(st + AF_B + soB[i], pB[i] + kcI * 32);
    };

    const uint32_t aRow = (uint32_t)(wm * 32 + (lane & 15)) * ROWB + ((lane >> 4) << 4);
    const int n_off = (lane & 7) + ((lane >> 4) << 3);
    const int k_half = (lane >> 3) & 1;
    const uint32_t bRow = (uint32_t)(wn * 64 + n_off) * ROWB + (k_half << 4);
    const uint32_t sF = sb + AF_F16;

    const int cr = t >> 1, chf = t & 1;
    const uint32_t cvtSrc = cr * 144 + chf * 64;
    char* const cvtDstP = smem + AF_F16 + cr * ROWB + chf * 32;

    issue(0, sb);            CP_COMMIT();
    issue(1, sb + AF_STAGE); CP_COMMIT();

#pragma unroll
    for (int kc = 0; kc < KT; kc++) {
        if (kc + 1 < KT) { CP_WAIT(1); } else { CP_WAIT(0); }
        __syncthreads();
        const int st = kc % 3;
        const uint32_t cur = sb + st * AF_STAGE;
        if (kc + 2 < KT) {
            issue(kc + 2, sb + ((kc + 2) % 3) * AF_STAGE);
            CP_COMMIT();
        }
        {
            const char* srcp = smem + st * AF_STAGE + cvtSrc;
            float4 f0 = *(const float4*)(srcp);
            float4 f1v = *(const float4*)(srcp + 16);
            float4 f2 = *(const float4*)(srcp + 32);
            float4 f3 = *(const float4*)(srcp + 48);
            uint4 u0, u1;
            u0.x = packh2(f0.x, f0.y);  u0.y = packh2(f0.z, f0.w);
            u0.z = packh2(f1v.x, f1v.y); u0.w = packh2(f1v.z, f1v.w);
            u1.x = packh2(f2.x, f2.y);  u1.y = packh2(f2.z, f2.w);
            u1.z = packh2(f3.x, f3.y);  u1.w = packh2(f3.z, f3.w);
            *(uint4*)(cvtDstP)      = u0;
            *(uint4*)(cvtDstP + 16) = u1;
        }
        __syncthreads();

#pragma unroll
        for (int ks = 0; ks < 2; ks++) {
            const uint32_t kb = ks * 32;
            uint32_t a[2][4], bh[4][4];
            ldmx4(a[0], sF + aRow + kb);
            ldmx4(a[1], sF + aRow + 16 * ROWB + kb);
#pragma unroll
            for (int jj = 0; jj < 4; jj++)
                ldmx4(bh[jj], cur + AF_B + bRow + jj * 16 * ROWB + kb);
#pragma unroll
            for (int g = 0; g < 2; g++) {
#pragma unroll
                for (int j = 0; j < 8; j++) {
                    const int jj = j >> 1, hf = (j & 1) * 2;
                    mma16816(acc[g][j], a[g], bh[jj][hf], bh[jj][hf + 1]);
                }
            }
        }
    }

    float bcol[16];
    {
        const int col0 = bn + wn * 64 + (lane & 3) * 2;
#pragma unroll
        for (int j = 0; j < 8; j++) {
            bcol[j * 2]     = bias[col0 + j * 8];
            bcol[j * 2 + 1] = bias[col0 + j * 8 + 1];
        }
    }
#pragma unroll
    for (int g = 0; g < 2; g++) {
#pragma unroll
        for (int j = 0; j < 8; j++) {
            const int row = bm + wm * 32 + g * 16 + (lane >> 2);
            const int col = bn + wn * 64 + j * 8 + (lane & 3) * 2;
            float v0 = softplusf(acc[g][j][0] + bcol[j * 2]) - LOG2F_;
            float v1 = softplusf(acc[g][j][1] + bcol[j * 2 + 1]) - LOG2F_;
            float v2 = softplusf(acc[g][j][2] + bcol[j * 2]) - LOG2F_;
            float v3 = softplusf(acc[g][j][3] + bcol[j * 2 + 1]) - LOG2F_;
            *(uint32_t*)(Ch + (size_t)row * N + col) = packh2(v0, v1);
            *(uint32_t*)(Ch + (size_t)(row + 8) * N + col) = packh2(v2, v3);
        }
    }
}

// key/query/value conversions in one launch, ILP4.
__global__ __launch_bounds__(256) void conv3_f16(
    const float* __restrict__ k, const float* __restrict__ q, const float* __restrict__ v,
    __half* __restrict__ xk, __half* __restrict__ xq, __half* __restrict__ xv)
{
    const int seg = blockIdx.x >> 9;
    const size_t base = (size_t)(blockIdx.x & 511) * 1024 + threadIdx.x;
    const float* x = (seg == 0) ? k : (seg == 1) ? q : v;
    __half* y = (seg == 0) ? xk : (seg == 1) ? xq : xv;
    float4 val[4];
#pragma unroll
    for (int kk = 0; kk < 4; kk++) val[kk] = ((const float4*)x)[base + kk * 256];
#pragma unroll
    for (int kk = 0; kk < 4; kk++) {
        uint2 u;
        u.x = packh2(val[kk].x, val[kk].y);
        u.y = packh2(val[kk].z, val[kk].w);
        *(uint2*)(y + (base + kk * 256) * 4) = u;
    }
}

// ---------------- weights: coalesced SMEM-tile transpose + fp16 ----------------
// bids 0..511: eight 512x512 matrices (transposed); seg 3 (Wo) also writes natural copy slot 9;
// 512..543: We2; 544: biasPQ.
__global__ __launch_bounds__(256) void wsplit_all_t(
    const float* __restrict__ Wk, const float* __restrict__ Wq, const float* __restrict__ Wv,
    const float* __restrict__ Wo, const float* __restrict__ Wu1, const float* __restrict__ Wu2,
    const float* __restrict__ We1, const float* __restrict__ We2,
    const float* __restrict__ bu1,
    __half* __restrict__ WHi, float* __restrict__ biasPQ)
{
    __shared__ float S[64][68];
    const int bid = blockIdx.x, t = threadIdx.x;

    if (bid == 544) {
#pragma unroll
        for (int it = 0; it < 4; it++) {
            const int i = it * 256 + t;
            biasPQ[i] = (i < 512) ? bu1[i] : 0.f;
        }
        return;
    }

    const float* src;
    int segOut, Ndim, tk, tn;
    if (bid < 512) {
        const int seg = bid >> 6;
        switch (seg) {
            case 0: src = Wk; break;
            case 1: src = Wq; break;
            case 2: src = Wv; break;
            case 3: src = Wo; break;
            case 4: src = Wu1; break;
            case 5: src = Wu1 + 262144; break;
            case 6: src = Wu2; break;
            default: src = We1; break;
        }
        segOut = seg; Ndim = 512;
        const int tile = bid & 63;
        tk = tile >> 3; tn = tile & 7;
    } else {
        src = We2; segOut = 8; Ndim = 256;
        const int tile = bid - 512;
        tk = tile >> 2; tn = tile & 3;
    }

    {
        const int c4 = (t & 15) * 4;
#pragma unroll
        for (int it = 0; it < 4; it++) {
            const int r = it * 16 + (t >> 4);
            float4 v = *(const float4*)(src + (size_t)(tk * 64 + r) * Ndim + tn * 64 + c4);
            S[r][c4] = v.x; S[r][c4 + 1] = v.y; S[r][c4 + 2] = v.z; S[r][c4 + 3] = v.w;
        }
    }
    __syncthreads();

    {
        __half* dst = WHi + (size_t)segOut * 262144;
        const int kg = (t & 15) * 4;
#pragma unroll
        for (int it = 0; it < 4; it++) {
            const int n = it * 16 + (t >> 4);
            uint2 u;
            u.x = packh2(S[kg][n], S[kg + 1][n]);
            u.y = packh2(S[kg + 2][n], S[kg + 3][n]);
            *(uint2*)(dst + (size_t)(tn * 64 + n) * 512 + tk * 64 + kg) = u;
        }
    }
    // Wo natural fp16 copy (slot 9) for the W' = Wo@Wu1 fusion GEMM
    if (segOut == 3) {
        __half* dst9 = WHi + (size_t)9 * 262144;
        const int c4 = (t & 15) * 4;
#pragma unroll
        for (int it = 0; it < 4; it++) {
            const int r = it * 16 + (t >> 4);
            uint2 u;
            u.x = packh2(S[r][c4], S[r][c4 + 1]);
            u.y = packh2(S[r][c4 + 2], S[r][c4 + 3]);
            *(uint2*)(dst9 + (size_t)(tk * 64 + r) * 512 + tn * 64 + c4) = u;
        }
    }
}

// b' = bo @ Wu1 + biasPQ  (reads fp16 Wu1T slot 4)
__global__ __launch_bounds__(256) void bfuse(
    const float* __restrict__ bo, const __half* __restrict__ Wu1T,
    const float* __restrict__ biasPQ, float* __restrict__ bPQ)
{
    const int n = blockIdx.x * 256 + threadIdx.x;  // 0..1023
    float s = biasPQ[n];
    const __half* row = Wu1T + (size_t)n * 512;
#pragma unroll 8
    for (int j = 0; j < 512; j++)
        s = fmaf(bo[j], __half2float(row[j]), s);
    bPQ[n] = s;
}

// ---------------- local attention: one block per (b,i), ctx written fp16 ----------------
__global__ __launch_bounds__(256) void local_attn(
    const float* __restrict__ q, const float* __restrict__ k,
    const float* __restrict__ v, const float* __restrict__ ef,
    const int* __restrict__ pair_j, __half* __restrict__ ctx)
{
    const int bi = blockIdx.x;
    const int b = bi >> 9;
    const int t = threadIdx.x;

    __shared__ float qs[256];
    __shared__ int js[16];
    __shared__ float sc[16][8];
    __shared__ float wgt[16][8];

    if (t < 16) js[t] = pair_j[bi * 16 + t];
    qs[t] = q[(size_t)bi * DD + 256 + t];
    __syncthreads();

    if (t < 128) {
        const int d = t >> 3, h = t & 7;
        const int j = js[d];
        const float* kr = k + ((size_t)(b * NN + j)) * DD + 256 + h * 32;
        const float* er = ef + ((size_t)(bi * 16 + d)) * 256 + h * 32;
        const float* qr = qs + h * 32;
        float s = 0.f;
#pragma unroll
        for (int c4 = 0; c4 < 8; c4++) {
            float4 kk = *(const float4*)(kr + c4 * 4);
            float4 eee = *(const float4*)(er + c4 * 4);
            s = fmaf(qr[c4 * 4 + 0], kk.x * eee.x, s);
            s = fmaf(qr[c4 * 4 + 1], kk.y * eee.y, s);
            s = fmaf(qr[c4 * 4 + 2], kk.z * eee.z, s);
            s = fmaf(qr[c4 * 4 + 3], kk.w * eee.w, s);
        }
        sc[d][h] = s * SCALE;
    }
    __syncthreads();

    if (t < 8) {
        const int h = t;
        float m = -1e30f;
#pragma unroll
        for (int d = 0; d < 16; d++) {
            float s = sc[d][h];
            if (s > -10000.f && s > m) m = s;
        }
        float sum = 0.f;
#pragma unroll
        for (int d = 0; d < 16; d++) {
            float s = sc[d][h];
            float e = (s > -10000.f) ? expf(s - m) : 0.f;
            wgt[d][h] = e;
            sum += e;
        }
        float inv = (sum > 0.f) ? 1.f / sum : 0.f;
#pragma unroll
        for (int d = 0; d < 16; d++) wgt[d][h] *= inv;
    }
    __syncthreads();

    const int h = t >> 5, c = t & 31;
    float o = 0.f;
#pragma unroll
    for (int d = 0; d < 16; d++) {
        float w = wgt[d][h];
        o = fmaf(w, v[((size_t)(b * NN + js[d])) * DD + 256 + h * 32 + c], o);
    }
    ctx[(size_t)bi * DD + h * 64 + 32 + c] = __float2half_rn(o);
}

// ========== global attention: tensor-core flash kernel ==========
__global__ __launch_bounds__(128) void global_attn_tc(
    const float* __restrict__ qf, const float* __restrict__ kf,
    const float* __restrict__ vf, const unsigned char* __restrict__ mask,
    __half* __restrict__ ctx, float* __restrict__ top)
{
    const int qt = blockIdx.x, h = blockIdx.y, b = blockIdx.z;
    const int t = threadIdx.x, lane = t & 31, w = t >> 5;

    __shared__ __half Qhi[64 * 40], Qlo[64 * 40];
    __shared__ __half Khi[64 * 40], Klo[64 * 40];
    __shared__ __half Vt[32 * 72];
    __shared__ unsigned char Ms[64 * 64];

    const uint32_t sQh = smem_to_u32(Qhi), sQl = smem_to_u32(Qlo);
    const uint32_t sKh = smem_to_u32(Khi), sKl = smem_to_u32(Klo);
    const uint32_t sV = smem_to_u32(Vt);

#pragma unroll
    for (int i = 0; i < 4; i++) {
        const int id = t + i * 128;
        const int row = id >> 3, ch = id & 7;
        float4 v4 = *(const float4*)(qf + ((size_t)(b * NN) + qt * 64 + row) * DD + h * 32 + ch * 4);
        __half h0 = __float2half_rn(v4.x), h1 = __float2half_rn(v4.y);
        __half h2 = __float2half_rn(v4.z), h3 = __float2half_rn(v4.w);
        __half l0 = __float2half_rn(v4.x - __half2float(h0));
        __half l1 = __float2half_rn(v4.y - __half2float(h1));
        __half l2 = __float2half_rn(v4.z - __half2float(h2));
        __half l3 = __float2half_rn(v4.w - __half2float(h3));
        uint2 uh, ul;
        uh.x = ((uint32_t)__half_as_ushort(h1) << 16) | __half_as_ushort(h0);
        uh.y = ((uint32_t)__half_as_ushort(h3) << 16) | __half_as_ushort(h2);
        ul.x = ((uint32_t)__half_as_ushort(l1) << 16) | __half_as_ushort(l0);
        ul.y = ((uint32_t)__half_as_ushort(l3) << 16) | __half_as_ushort(l2);
        *(uint2*)&Qhi[row * 40 + ch * 4] = uh;
        *(uint2*)&Qlo[row * 40 + ch * 4] = ul;
    }

    const uint32_t aOff = (uint32_t)(w * 16 + (lane & 15)) * 80 + ((lane >> 4) << 4);
    const uint32_t bOffR = (uint32_t)((lane & 7) + ((lane >> 4) << 3));
    const uint32_t kOff = bOffR * 80 + (((lane >> 3) & 1) << 4);
    const uint32_t vOff = bOffR * 144 + (((lane >> 3) & 1) << 4);

    __syncthreads();
    uint32_t aHi[2][4], aLo[2][4];
    ldmx4(aHi[0], sQh + aOff);
    ldmx4(aHi[1], sQh + aOff + 32);
    ldmx4(aLo[0], sQl + aOff);
    ldmx4(aLo[1], sQl + aOff + 32);

    float o[4][4] = {};
    float mA = -1e30f, mB = -1e30f, lA = 0.f, lB = 0.f;
    const int rA = lane >> 2;
    const size_t qrow0 = (size_t)(b * NN) + qt * 64 + w * 16 + rA;

    for (int kt = 0; kt < 8; kt++) {
        __syncthreads();
#pragma unroll
        for (int i = 0; i < 4; i++) {
            const int id = t + i * 128;
            const int row = id >> 3, ch = id & 7;
            float4 v4 = *(const float4*)(kf + ((size_t)(b * NN) + kt * 64 + row) * DD + h * 32 + ch * 4);
            __half h0 = __float2half_rn(v4.x), h1 = __float2half_rn(v4.y);
            __half h2 = __float2half_rn(v4.z), h3 = __float2half_rn(v4.w);
            __half l0 = __float2half_rn(v4.x - __half2float(h0));
            __half l1 = __float2half_rn(v4.y - __half2float(h1));
            __half l2 = __float2half_rn(v4.z - __half2float(h2));
            __half l3 = __float2half_rn(v4.w - __half2float(h3));
            uint2 uh, ul;
            uh.x = ((uint32_t)__half_as_ushort(h1) << 16) | __half_as_ushort(h0);
            uh.y = ((uint32_t)__half_as_ushort(h3) << 16) | __half_as_ushort(h2);
            ul.x = ((uint32_t)__half_as_ushort(l1) << 16) | __half_as_ushort(l0);
            ul.y = ((uint32_t)__half_as_ushort(l3) << 16) | __half_as_ushort(l2);
            *(uint2*)&Khi[row * 40 + ch * 4] = uh;
            *(uint2*)&Klo[row * 40 + ch * 4] = ul;
        }
#pragma unroll
        for (int i = 0; i < 4; i++) {
            const int id = t + i * 128;
            const int key = id >> 3, dh = (id & 7) * 4;
            float4 v4 = *(const float4*)(vf + ((size_t)(b * NN) + kt * 64 + key) * DD + h * 32 + dh);
            Vt[(dh + 0) * 72 + key] = __float2half_rn(v4.x);
            Vt[(dh + 1) * 72 + key] = __float2half_rn(v4.y);
            Vt[(dh + 2) * 72 + key] = __float2half_rn(v4.z);
            Vt[(dh + 3) * 72 + key] = __float2half_rn(v4.w);
        }
#pragma unroll
        for (int i = 0; i < 2; i++) {
            const int id = t + i * 128;
            const int row = id >> 2, ch = id & 3;
            *(uint4*)&Ms[row * 64 + ch * 16] =
                *(const uint4*)(mask + ((size_t)(b * NN) + qt * 64 + row) * NN + kt * 64 + ch * 16);
        }
        __syncthreads();

        float s[8][4];
#pragma unroll
        for (int n = 0; n < 8; n++) { s[n][0] = s[n][1] = s[n][2] = s[n][3] = 0.f; }
#pragma unroll
        for (int ks = 0; ks < 2; ks++) {
#pragma unroll
            for (int jj = 0; jj < 4; jj++) {
                uint32_t bh[4], bl[4];
                ldmx4(bh, sKh + kOff + jj * (16 * 80) + ks * 32);
                ldmx4(bl, sKl + kOff + jj * (16 * 80) + ks * 32);
                mma16816(s[jj * 2],     aHi[ks], bh[0], bh[1]);
                mma16816(s[jj * 2 + 1], aHi[ks], bh[2], bh[3]);
                mma16816(s[jj * 2],     aHi[ks], bl[0], bl[1]);
                mma16816(s[jj * 2 + 1], aHi[ks], bl[2], bl[3]);
                mma16816(s[jj * 2],     aLo[ks], bh[0], bh[1]);
                mma16816(s[jj * 2 + 1], aLo[ks], bh[2], bh[3]);
            }
        }
#pragma unroll
        for (int n = 0; n < 8; n++) {
            s[n][0] *= SCALE; s[n][1] *= SCALE; s[n][2] *= SCALE; s[n][3] *= SCALE;
        }

        if (h == 0) {
#pragma unroll
            for (int n = 0; n < 8; n++) {
                const int col = kt * 64 + n * 8 + (lane & 3) * 2;
                *(float2*)(top + qrow0 * NN + col) = make_float2(s[n][0], s[n][1]);
                *(float2*)(top + (qrow0 + 8) * NN + col) = make_float2(s[n][2], s[n][3]);
            }
        }
        {
            const int lr = w * 16 + rA;
#pragma unroll
            for (int n = 0; n < 8; n++) {
                const int col = n * 8 + (lane & 3) * 2;
                if (Ms[lr * 64 + col])           s[n][0] = -1e18f;
                if (Ms[lr * 64 + col + 1])       s[n][1] = -1e18f;
                if (Ms[(lr + 8) * 64 + col])     s[n][2] = -1e18f;
                if (Ms[(lr + 8) * 64 + col + 1]) s[n][3] = -1e18f;
            }
        }

        float tmA = -1e30f, tmB = -1e30f;
#pragma unroll
        for (int n = 0; n < 8; n++) {
            tmA = fmaxf(tmA, fmaxf(s[n][0], s[n][1]));
            tmB = fmaxf(tmB, fmaxf(s[n][2], s[n][3]));
        }
        tmA = fmaxf(tmA, __shfl_xor_sync(0xffffffffu, tmA, 1));
        tmA = fmaxf(tmA, __shfl_xor_sync(0xffffffffu, tmA, 2));
        tmB = fmaxf(tmB, __shfl_xor_sync(0xffffffffu, tmB, 1));
        tmB = fmaxf(tmB, __shfl_xor_sync(0xffffffffu, tmB, 2));
        const float mAn = fmaxf(mA, tmA), mBn = fmaxf(mB, tmB);
        const float fAc = __expf(mA - mAn), fBc = __expf(mB - mBn);
        float sumA = 0.f, sumB = 0.f;
        uint32_t pf[4][4];
#pragma unroll
        for (int n = 0; n < 8; n++) {
            float p0 = __expf(s[n][0] - mAn), p1 = __expf(s[n][1] - mAn);
            float p2 = __expf(s[n][2] - mBn), p3 = __expf(s[n][3] - mBn);
            sumA += p0 + p1; sumB += p2 + p3;
            pf[n >> 1][(n & 1) * 2]     = packh2(p0, p1);
            pf[n >> 1][(n & 1) * 2 + 1] = packh2(p2, p3);
        }
        sumA += __shfl_xor_sync(0xffffffffu, sumA, 1);
        sumA += __shfl_xor_sync(0xffffffffu, sumA, 2);
        sumB += __shfl_xor_sync(0xffffffffu, sumB, 1);
        sumB += __shfl_xor_sync(0xffffffffu, sumB, 2);
        lA = lA * fAc + sumA;
        lB = lB * fBc + sumB;
#pragma unroll
        for (int n = 0; n < 4; n++) {
            o[n][0] *= fAc; o[n][1] *= fAc; o[n][2] *= fBc; o[n][3] *= fBc;
        }
        mA = mAn; mB = mBn;

#pragma unroll
        for (int kfi = 0; kfi < 4; kfi++) {
#pragma unroll
            for (int jj = 0; jj < 2; jj++) {
                uint32_t bv[4];
                ldmx4(bv, sV + vOff + jj * (16 * 144) + kfi * 32);
                mma16816(o[jj * 2],     pf[kfi], bv[0], bv[1]);
                mma16816(o[jj * 2 + 1], pf[kfi], bv[2], bv[3]);
            }
        }
    }

    const float iA = 1.f / lA, iB = 1.f / lB;
#pragma unroll
    for (int n = 0; n < 4; n++) {
        const int col = h * 64 + n * 8 + (lane & 3) * 2;
        *(uint32_t*)(ctx + qrow0 * DD + col) = packh2(o[n][0] * iA, o[n][1] * iA);
        *(uint32_t*)(ctx + (qrow0 + 8) * DD + col) = packh2(o[n][2] * iB, o[n][3] * iB);
    }
}

// ---------------- eu: one block per (b,i) with offset; 256 threads, 2 rows in flight ----------------
__global__ __launch_bounds__(256) void eu_kernel(
    const float* __restrict__ PQ,
    const int* __restrict__ pair_j,
    __half* __restrict__ eu, int bi0)
{
    const int bi = bi0 + blockIdx.x;
    const int b = bi >> 9;
    const int t = threadIdx.x;
    const int half = t >> 7;
    const int tc = t & 127;

    __shared__ int js[16];
    if (t < 16) js[t] = pair_j[bi * 16 + t];

    const float4 p = *(const float4*)(PQ + (size_t)bi * 1024 + tc * 4);
    __syncthreads();

#pragma unroll
    for (int dd = 0; dd < 8; dd += 2) {
        const int d0 = half * 8 + dd, d1 = d0 + 1;
        const int j0 = js[d0], j1 = js[d1];
        float4 c0 = *(const float4*)(PQ + ((size_t)(b * NN + j0)) * 1024 + 512 + tc * 4);
        float4 c1 = *(const float4*)(PQ + ((size_t)(b * NN + j1)) * 1024 + 512 + tc * 4);
        uint2 u0, u1;
        u0.x = packh2(softplusf(p.x + c0.x) - LOG2F_, softplusf(p.y + c0.y) - LOG2F_);
        u0.y = packh2(softplusf(p.z + c0.z) - LOG2F_, softplusf(p.w + c0.w) - LOG2F_);
        u1.x = packh2(softplusf(p.x + c1.x) - LOG2F_, softplusf(p.y + c1.y) - LOG2F_);
        u1.y = packh2(softplusf(p.z + c1.z) - LOG2F_, softplusf(p.w + c1.w) - LOG2F_);
        *(uint2*)(eu + ((size_t)(bi * 16 + d0)) * DD + tc * 4) = u0;
        *(uint2*)(eu + ((size_t)(bi * 16 + d1)) * DD + tc * 4) = u1;
    }
}

// ---------------- launch (fork-join on two streams) ----------------
extern "C" void kernel_launch(void* const* d_in, const int* in_sizes, int n_in,
                              void* d_out, int out_size)
{
    const float* key    = (const float*)d_in[0];
    const float* value  = (const float*)d_in[1];
    const float* query  = (const float*)d_in[2];
    const unsigned char* mask = (const unsigned char*)d_in[3];
    const float* edgef  = (const float*)d_in[4];
    const int* pair_b   = (const int*)d_in[5];
    const int* pair_i   = (const int*)d_in[6];
    const int* pair_j   = (const int*)d_in[7];
    const float* Wq = (const float*)d_in[8],  *bq = (const float*)d_in[9];
    const float* Wk = (const float*)d_in[10], *bk = (const float*)d_in[11];
    const float* Wv = (const float*)d_in[12], *bv = (const float*)d_in[13];
    const float* Wo = (const float*)d_in[14], *bo = (const float*)d_in[15];
    const float* We1 = (const float*)d_in[16], *be1 = (const float*)d_in[17];
    const float* We2 = (const float*)d_in[18], *be2 = (const float*)d_in[19];
    const float* Wu1 = (const float*)d_in[20], *bu1 = (const float*)d_in[21];
    const float* Wu2 = (const float*)d_in[22], *bu2 = (const float*)d_in[23];

    float* out  = (float*)d_out;
    float* top  = out + 2097152;
    float* eupd = out + 4194304;

    float *q_, *k_, *v_, *PQ_, *ef_, *biasPQ_, *bPQ_;
    __half *f1_, *eu_, *xK_, *xQ_, *xV_, *xC_, *WHi_, *WPQ_;
    cudaGetSymbolAddress((void**)&q_, g_q);
    cudaGetSymbolAddress((void**)&k_, g_k);
    cudaGetSymbolAddress((void**)&v_, g_v);
    cudaGetSymbolAddress((void**)&PQ_, g_PQ);
    cudaGetSymbolAddress((void**)&ef_, g_ef);
    cudaGetSymbolAddress((void**)&f1_, g_f1);
    cudaGetSymbolAddress((void**)&eu_, g_eu);
    cudaGetSymbolAddress((void**)&xK_, g_xK);
    cudaGetSymbolAddress((void**)&xQ_, g_xQ);
    cudaGetSymbolAddress((void**)&xV_, g_xV);
    cudaGetSymbolAddress((void**)&xC_, g_xC);
    cudaGetSymbolAddress((void**)&WHi_, g_WHi);
    cudaGetSymbolAddress((void**)&WPQ_, g_WPQ);
    cudaGetSymbolAddress((void**)&biasPQ_, g_biasPQ);
    cudaGetSymbolAddress((void**)&bPQ_, g_bPQ);

    cudaFuncSetAttribute((const void*)tc_gemm<0, 0>,
                         cudaFuncAttributeMaxDynamicSharedMemorySize, TC_SMEM);
    cudaFuncSetAttribute((const void*)tc_gemm<0, 1>,
                         cudaFuncAttributeMaxDynamicSharedMemorySize, TC_SMEM);
    cudaFuncSetAttribute((const void*)tc_gemm_qkv,
                         cudaFuncAttributeMaxDynamicSharedMemorySize, TC_SMEM);
    cudaFuncSetAttribute((const void*)tc_gemm_f32a,
                         cudaFuncAttributeMaxDynamicSharedMemorySize, AF_SMEM);

    const int WSZ = 262144;

    cudaStream_t s2;
    cudaStreamCreateWithFlags(&s2, cudaStreamNonBlocking);
    cudaEvent_t eW, eQKV, eL, eG, eE0, eE1;
    cudaEventCreateWithFlags(&eW, cudaEventDisableTiming);
    cudaEventCreateWithFlags(&eQKV, cudaEventDisableTiming);
    cudaEventCreateWithFlags(&eL, cudaEventDisableTiming);
    cudaEventCreateWithFlags(&eG, cudaEventDisableTiming);
    cudaEventCreateWithFlags(&eE0, cudaEventDisableTiming);
    cudaEventCreateWithFlags(&eE1, cudaEventDisableTiming);

    // s0: weight prep, then fork
    wsplit_all_t<<<545, 256>>>(Wk, Wq, Wv, Wo, Wu1, Wu2, We1, We2, bu1,
                               WHi_, biasPQ_);
    cudaEventRecord(eW, 0);

    // s2 (edge chain): MLP1 (fused f32 A) -> MLP2 -> ef
    cudaStreamWaitEvent(s2, eW, 0);
    tc_gemm_f32a<<<dim3(4, 512), 256, AF_SMEM, s2>>>(edgef, WHi_ + 7 * WSZ, be1, f1_, 512);
    tc_gemm<0, 0><<<dim3(2, 512), 256, TC_SMEM, s2>>>(f1_, WHi_ + 8 * WSZ,
                                                      be2, ef_, nullptr, 256);

    // s0: fused PQ weight W'^T = Wu1^T @ Wo (+ fused bias), then node chain
    bfuse<<<4, 256>>>(bo, WHi_ + 4 * WSZ, biasPQ_, bPQ_);
    tc_gemm<0, 1><<<dim3(4, 8), 256, TC_SMEM>>>(WHi_ + 4 * WSZ, WHi_ + 9 * WSZ,
                                                nullptr, nullptr, WPQ_, 512);
    conv3_f16<<<1536, 256>>>(key, query, value, xK_, xQ_, xV_);
    tc_gemm_qkv<<<dim3(4, 32, 3), 256, TC_SMEM>>>(xK_, xQ_, xV_,
                                                  WHi_ + 0 * WSZ, WHi_ + 1 * WSZ, WHi_ + 2 * WSZ,
                                                  bk, bq, bv, k_, q_, v_);
    cudaEventRecord(eQKV, 0);

    // s2: local attention (needs ef + qkv)
    cudaStreamWaitEvent(s2, eQKV, 0);
    local_attn<<<ROWS, 256, 0, s2>>>(q_, k_, v_, ef_, pair_j, xC_);
    cudaEventRecord(eL, s2);

    // s0: global attention (disjoint ctx columns)
    global_attn_tc<<<dim3(8, 8, 8), 128>>>(q_, k_, v_, mask, xC_, top);
    cudaEventRecord(eG, 0);

    // s2: PQ = ctx @ W' + b' (needs full ctx: eL already on s2, wait for eG)
    cudaStreamWaitEvent(s2, eG, 0);
    tc_gemm<0, 0><<<dim3(8, 32), 256, TC_SMEM, s2>>>(xC_, WPQ_, bPQ_, PQ_, nullptr, 1024);
    // s2: eu halves
    eu_kernel<<<2048, 256, 0, s2>>>(PQ_, pair_j, eu_, 0);
    cudaEventRecord(eE0, s2);
    eu_kernel<<<2048, 256, 0, s2>>>(PQ_, pair_j, eu_, 2048);
    cudaEventRecord(eE1, s2);

    // s0: output projection (needs full ctx: eG implicit on s0, wait eL)
    cudaStreamWaitEvent(0, eL, 0);
    tc_gemm<0, 0><<<dim3(4, 32), 256, TC_SMEM>>>(xC_, WHi_ + 3 * WSZ,
                                                 bo, out, nullptr, 512);

    // s0: Wu2 halves pipelined against eu halves
    cudaStreamWaitEvent(0, eE0, 0);
    tc_gemm<0, 0><<<dim3(4, 256), 256, TC_SMEM>>>(eu_, WHi_ + 6 * WSZ,
                                                  bu2, eupd, nullptr, 512);
    cudaStreamWaitEvent(0, eE1, 0);
    tc_gemm<0, 0><<<dim3(4, 256), 256, TC_SMEM>>>(eu_ + (size_t)32768 * 512, WHi_ + 6 * WSZ,
                                                  bu2, eupd + (size_t)32768 * 512, nullptr, 512);

    cudaEventDestroy(eW);
    cudaEventDestroy(eQKV);
    cudaEventDestroy(eL);
    cudaEventDestroy(eG);
    cudaEventDestroy(eE0);
    cudaEventDestroy(eE1);
    cudaStreamDestroy(s2);
}

// round 14
// speedup vs baseline: 1.0553x; 1.0553x over previous
#include <cuda_runtime.h>
#include <cuda_bf16.h>
#include <cuda_fp16.h>
#include <math.h>
#include <stdint.h>

// Problem constants
#define BB 8
#define NN 512
#define DD 512
#define DEG_ 16
#define EE 65536   // B*N*DEG
#define ROWS 4096  // B*N
#define GK 512     // K dim of all big GEMMs
#define SCALE 0.17677669529663687f  // 1/sqrt(32)
#define LOG2F_ 0.6931471805599453f

// ---------------- scratch (device globals; no allocs allowed) ----------------
__device__ float g_q[ROWS * DD];
__device__ float g_k[ROWS * DD];
__device__ float g_v[ROWS * DD];
__device__ float g_PQ[ROWS * 1024];
__device__ float g_ef[(size_t)EE * 256];

__device__ __half g_f1[(size_t)EE * DD];
__device__ __half g_eu[(size_t)EE * DD];
__device__ __half g_xK[ROWS * DD];
__device__ __half g_xQ[ROWS * DD];
__device__ __half g_xV[ROWS * DD];
__device__ __half g_xC[ROWS * DD];   // ctx in fp16

// weights fp16: 0 WkT,1 WqT,2 WvT,3 WoT,4 Wu1T(1024x512),6 Wu2T,7 We1T,8 We2T(256x512),9 Wo natural
__device__ __half g_WHi[10 * 262144];
__device__ __half g_WPQ[1024 * 512];   // W'^T = (Wo@Wu1)^T, [1024,512]
__device__ float g_biasPQ[1024];
__device__ float g_bPQ[1024];          // b' = bo@Wu1 + biasPQ

__device__ __forceinline__ float softplusf(float x) {
    return fmaxf(x, 0.f) + log1pf(expf(-fabsf(x)));
}

__device__ __forceinline__ uint32_t smem_to_u32(const void* smem_ptr) {
    uint32_t addr;
    asm("{ .reg .u64 tmp; cvta.to.shared.u64 tmp, %1; cvt.u32.u64 %0, tmp; }"
        : "=r"(addr) : "l"(smem_ptr));
    return addr;
}

// ---------------- PTX: cp.async / ldmatrix / mma (base-arch legal) ----------------
__device__ __forceinline__ void cpasync16(uint32_t saddr, const void* g) {
    asm volatile("cp.async.cg.shared.global [%0], [%1], 16;" :: "r"(saddr), "l"(g));
}
#define CP_COMMIT() asm volatile("cp.async.commit_group;")
#define CP_WAIT(n)  asm volatile("cp.async.wait_group %0;" :: "n"(n))

__device__ __forceinline__ void ldmx4(uint32_t r[4], uint32_t addr) {
    asm volatile("ldmatrix.sync.aligned.m8n8.x4.shared.b16 {%0,%1,%2,%3}, [%4];"
                 : "=r"(r[0]), "=r"(r[1]), "=r"(r[2]), "=r"(r[3]) : "r"(addr));
}

__device__ __forceinline__ void mma16816(float c[4], const uint32_t a[4],
                                         uint32_t b0, uint32_t b1) {
    asm volatile("mma.sync.aligned.m16n8k16.row.col.f32.f16.f16.f32 "
                 "{%0,%1,%2,%3}, {%4,%5,%6,%7}, {%8,%9}, {%0,%1,%2,%3};"
                 : "+f"(c[0]), "+f"(c[1]), "+f"(c[2]), "+f"(c[3])
                 : "r"(a[0]), "r"(a[1]), "r"(a[2]), "r"(a[3]), "r"(b0), "r"(b1));
}

__device__ __forceinline__ uint32_t packh2(float x, float y) {
    __half2 h = __floats2half2_rn(x, y);
    return *(uint32_t*)&h;
}

// ======================= tensor-core GEMM core (mma.sync fp16) ===============
#define ROWB 80
#define TILE_B (128 * ROWB)      // 10240
#define A_OFF 0
#define B_OFF (1 * TILE_B)
#define STAGE_B (2 * TILE_B)     // 20480
#define NSTAGE 4
#define TC_SMEM (NSTAGE * STAGE_B)  // 81920

// OUT: 0 = f32 only, 1 = fp16 only, 2 = f32 + fp16
template <int SOFTPLUS, int OUT>
__device__ __forceinline__ void tc_gemm_core(
    char* smem,
    const __half* __restrict__ A, const __half* __restrict__ B,
    const float* __restrict__ bias,
    float* __restrict__ Cf, __half* __restrict__ Ch,
    int N, int bm, int bn)
{
    const uint32_t sb = smem_to_u32(smem);
    const int t = threadIdx.x, lane = t & 31, w = t >> 5;
    const int wm = w & 3, wn = w >> 2;
    constexpr int KT = GK / 32;   // 16

    float acc[2][8][4] = {};

    const __half* pA[2];
    const __half* pB[2];
    uint32_t so[2];
#pragma unroll
    for (int i = 0; i < 2; i++) {
        const int id = t + i * 256;
        const int row = id >> 2, ch = id & 3;
        so[i] = row * ROWB + ch * 16;
        pA[i] = A + (size_t)(bm + row) * GK + ch * 8;
        pB[i] = B + (size_t)(bn + row) * GK + ch * 8;
    }

    auto issue = [&](int kcI, uint32_t stbase) {
#pragma unroll
        for (int i = 0; i < 2; i++) {
            cpasync16(stbase + A_OFF + so[i], pA[i] + kcI * 32);
            cpasync16(stbase + B_OFF + so[i], pB[i] + kcI * 32);
        }
    };

    const uint32_t aRow = (uint32_t)(wm * 32 + (lane & 15)) * ROWB + ((lane >> 4) << 4);
    const int n_off = (lane & 7) + ((lane >> 4) << 3);
    const int k_half = (lane >> 3) & 1;
    const uint32_t bRow = (uint32_t)(wn * 64 + n_off) * ROWB + (k_half << 4);

    issue(0, sb);               CP_COMMIT();
    issue(1, sb + STAGE_B);     CP_COMMIT();
    issue(2, sb + 2 * STAGE_B); CP_COMMIT();

#pragma unroll
    for (int kc = 0; kc < KT; kc++) {
        if (kc + 2 < KT)      { CP_WAIT(2); }
        else if (kc + 1 < KT) { CP_WAIT(1); }
        else                  { CP_WAIT(0); }
        __syncthreads();
        if (kc + 3 < KT) {
            issue(kc + 3, sb + ((kc + 3) & 3) * STAGE_B);
            CP_COMMIT();
        }
        const uint32_t cur = sb + (kc & 3) * STAGE_B;

#pragma unroll
        for (int ks = 0; ks < 2; ks++) {
            const uint32_t kb = ks * 32;
            uint32_t a[2][4], bh[4][4];
            ldmx4(a[0], cur + A_OFF + aRow + kb);
            ldmx4(a[1], cur + A_OFF + aRow + 16 * ROWB + kb);
#pragma unroll
            for (int jj = 0; jj < 4; jj++)
                ldmx4(bh[jj], cur + B_OFF + bRow + jj * 16 * ROWB + kb);
#pragma unroll
            for (int g = 0; g < 2; g++) {
#pragma unroll
                for (int j = 0; j < 8; j++) {
                    const int jj = j >> 1, hf = (j & 1) * 2;
                    mma16816(acc[g][j], a[g], bh[jj][hf], bh[jj][hf + 1]);
                }
            }
        }
    }

    float bcol[16];
    {
        const int col0 = bn + wn * 64 + (lane & 3) * 2;
#pragma unroll
        for (int j = 0; j < 8; j++) {
            bcol[j * 2]     = bias ? bias[col0 + j * 8]     : 0.f;
            bcol[j * 2 + 1] = bias ? bias[col0 + j * 8 + 1] : 0.f;
        }
    }
#pragma unroll
    for (int g = 0; g < 2; g++) {
#pragma unroll
        for (int j = 0; j < 8; j++) {
            const int row = bm + wm * 32 + g * 16 + (lane >> 2);
            const int col = bn + wn * 64 + j * 8 + (lane & 3) * 2;
            float v0 = acc[g][j][0] + bcol[j * 2], v1 = acc[g][j][1] + bcol[j * 2 + 1];
            float v2 = acc[g][j][2] + bcol[j * 2], v3 = acc[g][j][3] + bcol[j * 2 + 1];
            if (SOFTPLUS) {
                v0 = softplusf(v0) - LOG2F_; v1 = softplusf(v1) - LOG2F_;
                v2 = softplusf(v2) - LOG2F_; v3 = softplusf(v3) - LOG2F_;
            }
            if (OUT == 0 || OUT == 2) {
                *(float2*)(Cf + (size_t)row * N + col) = make_float2(v0, v1);
                *(float2*)(Cf + (size_t)(row + 8) * N + col) = make_float2(v2, v3);
            }
            if (OUT == 1 || OUT == 2) {
                *(uint32_t*)(Ch + (size_t)row * N + col) = packh2(v0, v1);
                *(uint32_t*)(Ch + (size_t)(row + 8) * N + col) = packh2(v2, v3);
            }
        }
    }
}

template <int SOFTPLUS, int OUT>
__global__ __launch_bounds__(256, 2) void tc_gemm(
    const __half* __restrict__ A, const __half* __restrict__ B,
    const float* __restrict__ bias,
    float* __restrict__ Cf, __half* __restrict__ Ch,
    int N)
{
    extern __shared__ char smem[];
    tc_gemm_core<SOFTPLUS, OUT>(smem, A, B, bias, Cf, Ch, N,
                                blockIdx.y * 128, blockIdx.x * 128);
}

// batched K/Q/V projection: blockIdx.z selects the triple
__global__ __launch_bounds__(256, 2) void tc_gemm_qkv(
    const __half* __restrict__ xK, const __half* __restrict__ xQ, const __half* __restrict__ xV,
    const __half* __restrict__ WkT, const __half* __restrict__ WqT, const __half* __restrict__ WvT,
    const float* __restrict__ bk, const float* __restrict__ bq, const float* __restrict__ bv,
    float* __restrict__ k_, float* __restrict__ q_, float* __restrict__ v_)
{
    extern __shared__ char smem[];
    const int z = blockIdx.z;
    const __half* A = (z == 0) ? xK : (z == 1) ? xQ : xV;
    const __half* B = (z == 0) ? WkT : (z == 1) ? WqT : WvT;
    const float* bias = (z == 0) ? bk : (z == 1) ? bq : bv;
    float* C = (z == 0) ? k_ : (z == 1) ? q_ : v_;
    tc_gemm_core<0, 0>(smem, A, B, bias, C, nullptr, 512,
                       blockIdx.y * 128, blockIdx.x * 128);
}

// ======================= MLP1 GEMM with fused f32->fp16 A conversion =======================
#define AF_A32 0
#define AF_B   18432
#define AF_STAGE (18432 + 10240) // 28672
#define AF_F16 (3 * AF_STAGE)    // 86016
#define AF_SMEM (AF_F16 + 10240) // 96256

__global__ __launch_bounds__(256, 2) void tc_gemm_f32a(
    const float* __restrict__ A, const __half* __restrict__ B,
    const float* __restrict__ bias, __half* __restrict__ Ch, int N)
{
    extern __shared__ char smem[];
    const uint32_t sb = smem_to_u32(smem);
    const int t = threadIdx.x, lane = t & 31, w = t >> 5;
    const int wm = w & 3, wn = w >> 2;
    const int bm = blockIdx.y * 128, bn = blockIdx.x * 128;
    constexpr int KT = GK / 32;   // 16

    float acc[2][8][4] = {};

    const float* pA[4];
    uint32_t soA[4];
#pragma unroll
    for (int i = 0; i < 4; i++) {
        const int id = t + i * 256;
        const int row = id >> 3, ch = id & 7;
        soA[i] = row * 144 + ch * 16;
        pA[i] = A + (size_t)(bm + row) * GK + ch * 4;
    }
    const __half* pB[2];
    uint32_t soB[2];
#pragma unroll
    for (int i = 0; i < 2; i++) {
        const int id = t + i * 256;
        const int row = id >> 2, ch = id & 3;
        soB[i] = row * ROWB + ch * 16;
        pB[i] = B + (size_t)(bn + row) * GK + ch * 8;
    }

    auto issue = [&](int kcI, uint32_t st) {
#pragma unroll
        for (int i = 0; i < 4; i++) cpasync16(st + AF_A32 + soA[i], pA[i] + kcI * 32);
#pragma unroll
        for (int i = 0; i < 2; i++) cpasync16(st + AF_B + soB[i], pB[i] + kcI * 32);
    };

    const uint32_t aRow = (uint32_t)(wm * 32 + (lane & 15)) * ROWB + ((lane >> 4) << 4);
    const int n_off = (lane & 7) + ((lane >> 4) << 3);
    const int k_half = (lane >> 3) & 1;
    const uint32_t bRow = (uint32_t)(wn * 64 + n_off) * ROWB + (k_half << 4);
    const uint32_t sF = sb + AF_F16;

    const int cr = t >> 1, chf = t & 1;
    const uint32_t cvtSrc = cr * 144 + chf * 64;
    char* const cvtDstP = smem + AF_F16 + cr * ROWB + chf * 32;

    issue(0, sb);            CP_COMMIT();
    issue(1, sb + AF_STAGE); CP_COMMIT();

#pragma unroll
    for (int kc = 0; kc < KT; kc++) {
        if (kc + 1 < KT) { CP_WAIT(1); } else { CP_WAIT(0); }
        __syncthreads();
        const int st = kc % 3;
        const uint32_t cur = sb + st * AF_STAGE;
        if (kc + 2 < KT) {
            issue(kc + 2, sb + ((kc + 2) % 3) * AF_STAGE);
            CP_COMMIT();
        }
        {
            const char* srcp = smem + st * AF_STAGE + cvtSrc;
            float4 f0 = *(const float4*)(srcp);
            float4 f1v = *(const float4*)(srcp + 16);
            float4 f2 = *(const float4*)(srcp + 32);
            float4 f3 = *(const float4*)(srcp + 48);
            uint4 u0, u1;
            u0.x = packh2(f0.x, f0.y);  u0.y = packh2(f0.z, f0.w);
            u0.z = packh2(f1v.x, f1v.y); u0.w = packh2(f1v.z, f1v.w);
            u1.x = packh2(f2.x, f2.y);  u1.y = packh2(f2.z, f2.w);
            u1.z = packh2(f3.x, f3.y);  u1.w = packh2(f3.z, f3.w);
            *(uint4*)(cvtDstP)      = u0;
            *(uint4*)(cvtDstP + 16) = u1;
        }
        __syncthreads();

#pragma unroll
        for (int ks = 0; ks < 2; ks++) {
            const uint32_t kb = ks * 32;
            uint32_t a[2][4], bh[4][4];
            ldmx4(a[0], sF + aRow + kb);
            ldmx4(a[1], sF + aRow + 16 * ROWB + kb);
#pragma unroll
            for (int jj = 0; jj < 4; jj++)
                ldmx4(bh[jj], cur + AF_B + bRow + jj * 16 * ROWB + kb);
#pragma unroll
            for (int g = 0; g < 2; g++) {
#pragma unroll
                for (int j = 0; j < 8; j++) {
                    const int jj = j >> 1, hf = (j & 1) * 2;
                    mma16816(acc[g][j], a[g], bh[jj][hf], bh[jj][hf + 1]);
                }
            }
        }
    }

    float bcol[16];
    {
        const int col0 = bn + wn * 64 + (lane & 3) * 2;
#pragma unroll
        for (int j = 0; j < 8; j++) {
            bcol[j * 2]     = bias[col0 + j * 8];
            bcol[j * 2 + 1] = bias[col0 + j * 8 + 1];
        }
    }
#pragma unroll
    for (int g = 0; g < 2; g++) {
#pragma unroll
        for (int j = 0; j < 8; j++) {
            const int row = bm + wm * 32 + g * 16 + (lane >> 2);
            const int col = bn + wn * 64 + j * 8 + (lane & 3) * 2;
            float v0 = softplusf(acc[g][j][0] + bcol[j * 2]) - LOG2F_;
            float v1 = softplusf(acc[g][j][1] + bcol[j * 2 + 1]) - LOG2F_;
            float v2 = softplusf(acc[g][j][2] + bcol[j * 2]) - LOG2F_;
            float v3 = softplusf(acc[g][j][3] + bcol[j * 2 + 1]) - LOG2F_;
            *(uint32_t*)(Ch + (size_t)row * N + col) = packh2(v0, v1);
            *(uint32_t*)(Ch + (size_t)(row + 8) * N + col) = packh2(v2, v3);
        }
    }
}

// key/query/value conversions in one launch, ILP4.
__global__ __launch_bounds__(256) void conv3_f16(
    const float* __restrict__ k, const float* __restrict__ q, const float* __restrict__ v,
    __half* __restrict__ xk, __half* __restrict__ xq, __half* __restrict__ xv)
{
    const int seg = blockIdx.x >> 9;
    const size_t base = (size_t)(blockIdx.x & 511) * 1024 + threadIdx.x;
    const float* x = (seg == 0) ? k : (seg == 1) ? q : v;
    __half* y = (seg == 0) ? xk : (seg == 1) ? xq : xv;
    float4 val[4];
#pragma unroll
    for (int kk = 0; kk < 4; kk++) val[kk] = ((const float4*)x)[base + kk * 256];
#pragma unroll
    for (int kk = 0; kk < 4; kk++) {
        uint2 u;
        u.x = packh2(val[kk].x, val[kk].y);
        u.y = packh2(val[kk].z, val[kk].w);
        *(uint2*)(y + (base + kk * 256) * 4) = u;
    }
}

// ---------------- weights: coalesced SMEM-tile transpose + fp16 ----------------
__global__ __launch_bounds__(256) void wsplit_all_t(
    const float* __restrict__ Wk, const float* __restrict__ Wq, const float* __restrict__ Wv,
    const float* __restrict__ Wo, const float* __restrict__ Wu1, const float* __restrict__ Wu2,
    const float* __restrict__ We1, const float* __restrict__ We2,
    const float* __restrict__ bu1,
    __half* __restrict__ WHi, float* __restrict__ biasPQ)
{
    __shared__ float S[64][68];
    const int bid = blockIdx.x, t = threadIdx.x;

    if (bid == 544) {
#pragma unroll
        for (int it = 0; it < 4; it++) {
            const int i = it * 256 + t;
            biasPQ[i] = (i < 512) ? bu1[i] : 0.f;
        }
        return;
    }

    const float* src;
    int segOut, Ndim, tk, tn;
    if (bid < 512) {
        const int seg = bid >> 6;
        switch (seg) {
            case 0: src = Wk; break;
            case 1: src = Wq; break;
            case 2: src = Wv; break;
            case 3: src = Wo; break;
            case 4: src = Wu1; break;
            case 5: src = Wu1 + 262144; break;
            case 6: src = Wu2; break;
            default: src = We1; break;
        }
        segOut = seg; Ndim = 512;
        const int tile = bid & 63;
        tk = tile >> 3; tn = tile & 7;
    } else {
        src = We2; segOut = 8; Ndim = 256;
        const int tile = bid - 512;
        tk = tile >> 2; tn = tile & 3;
    }

    {
        const int c4 = (t & 15) * 4;
#pragma unroll
        for (int it = 0; it < 4; it++) {
            const int r = it * 16 + (t >> 4);
            float4 v = *(const float4*)(src + (size_t)(tk * 64 + r) * Ndim + tn * 64 + c4);
            S[r][c4] = v.x; S[r][c4 + 1] = v.y; S[r][c4 + 2] = v.z; S[r][c4 + 3] = v.w;
        }
    }
    __syncthreads();

    {
        __half* dst = WHi + (size_t)segOut * 262144;
        const int kg = (t & 15) * 4;
#pragma unroll
        for (int it = 0; it < 4; it++) {
            const int n = it * 16 + (t >> 4);
            uint2 u;
            u.x = packh2(S[kg][n], S[kg + 1][n]);
            u.y = packh2(S[kg + 2][n], S[kg + 3][n]);
            *(uint2*)(dst + (size_t)(tn * 64 + n) * 512 + tk * 64 + kg) = u;
        }
    }
    if (segOut == 3) {
        __half* dst9 = WHi + (size_t)9 * 262144;
        const int c4 = (t & 15) * 4;
#pragma unroll
        for (int it = 0; it < 4; it++) {
            const int r = it * 16 + (t >> 4);
            uint2 u;
            u.x = packh2(S[r][c4], S[r][c4 + 1]);
            u.y = packh2(S[r][c4 + 2], S[r][c4 + 3]);
            *(uint2*)(dst9 + (size_t)(tk * 64 + r) * 512 + tn * 64 + c4) = u;
        }
    }
}

// b' = bo @ Wu1 + biasPQ  — one block per output n, 128-thread reduction
__global__ __launch_bounds__(128) void bfuse(
    const float* __restrict__ bo, const __half* __restrict__ Wu1T,
    const float* __restrict__ biasPQ, float* __restrict__ bPQ)
{
    const int n = blockIdx.x;           // 0..1023
    const int t = threadIdx.x;          // 0..127
    const __half* row = Wu1T + (size_t)n * 512;
    float s = 0.f;
#pragma unroll
    for (int i = 0; i < 4; i++) {
        const int j = t + i * 128;
        s = fmaf(bo[j], __half2float(row[j]), s);
    }
#pragma unroll
    for (int o = 16; o; o >>= 1) s += __shfl_xor_sync(0xffffffffu, s, o);
    __shared__ float ws[4];
    if ((t & 31) == 0) ws[t >> 5] = s;
    __syncthreads();
    if (t == 0) bPQ[n] = ws[0] + ws[1] + ws[2] + ws[3] + biasPQ[n];
}

// ---------------- local attention: one block per (b,i), ctx written fp16 ----------------
__global__ __launch_bounds__(256) void local_attn(
    const float* __restrict__ q, const float* __restrict__ k,
    const float* __restrict__ v, const float* __restrict__ ef,
    const int* __restrict__ pair_j, __half* __restrict__ ctx)
{
    const int bi = blockIdx.x;
    const int b = bi >> 9;
    const int t = threadIdx.x;

    __shared__ float qs[256];
    __shared__ int js[16];
    __shared__ float sc[16][8];
    __shared__ float wgt[16][8];

    if (t < 16) js[t] = pair_j[bi * 16 + t];
    qs[t] = q[(size_t)bi * DD + 256 + t];
    __syncthreads();

    if (t < 128) {
        const int d = t >> 3, h = t & 7;
        const int j = js[d];
        const float* kr = k + ((size_t)(b * NN + j)) * DD + 256 + h * 32;
        const float* er = ef + ((size_t)(bi * 16 + d)) * 256 + h * 32;
        const float* qr = qs + h * 32;
        float s = 0.f;
#pragma unroll
        for (int c4 = 0; c4 < 8; c4++) {
            float4 kk = *(const float4*)(kr + c4 * 4);
            float4 eee = *(const float4*)(er + c4 * 4);
            s = fmaf(qr[c4 * 4 + 0], kk.x * eee.x, s);
            s = fmaf(qr[c4 * 4 + 1], kk.y * eee.y, s);
            s = fmaf(qr[c4 * 4 + 2], kk.z * eee.z, s);
            s = fmaf(qr[c4 * 4 + 3], kk.w * eee.w, s);
        }
        sc[d][h] = s * SCALE;
    }
    __syncthreads();

    if (t < 8) {
        const int h = t;
        float m = -1e30f;
#pragma unroll
        for (int d = 0; d < 16; d++) {
            float s = sc[d][h];
            if (s > -10000.f && s > m) m = s;
        }
        float sum = 0.f;
#pragma unroll
        for (int d = 0; d < 16; d++) {
            float s = sc[d][h];
            float e = (s > -10000.f) ? expf(s - m) : 0.f;
            wgt[d][h] = e;
            sum += e;
        }
        float inv = (sum > 0.f) ? 1.f / sum : 0.f;
#pragma unroll
        for (int d = 0; d < 16; d++) wgt[d][h] *= inv;
    }
    __syncthreads();

    const int h = t >> 5, c = t & 31;
    float o = 0.f;
#pragma unroll
    for (int d = 0; d < 16; d++) {
        float w = wgt[d][h];
        o = fmaf(w, v[((size_t)(b * NN + js[d])) * DD + 256 + h * 32 + c], o);
    }
    ctx[(size_t)bi * DD + h * 64 + 32 + c] = __float2half_rn(o);
}

// ========== global attention: tensor-core flash kernel ==========
__global__ __launch_bounds__(128) void global_attn_tc(
    const float* __restrict__ qf, const float* __restrict__ kf,
    const float* __restrict__ vf, const unsigned char* __restrict__ mask,
    __half* __restrict__ ctx, float* __restrict__ top)
{
    const int qt = blockIdx.x, h = blockIdx.y, b = blockIdx.z;
    const int t = threadIdx.x, lane = t & 31, w = t >> 5;

    __shared__ __half Qhi[64 * 40], Qlo[64 * 40];
    __shared__ __half Khi[64 * 40], Klo[64 * 40];
    __shared__ __half Vt[32 * 72];
    __shared__ unsigned char Ms[64 * 64];

    const uint32_t sQh = smem_to_u32(Qhi), sQl = smem_to_u32(Qlo);
    const uint32_t sKh = smem_to_u32(Khi), sKl = smem_to_u32(Klo);
    const uint32_t sV = smem_to_u32(Vt);

#pragma unroll
    for (int i = 0; i < 4; i++) {
        const int id = t + i * 128;
        const int row = id >> 3, ch = id & 7;
        float4 v4 = *(const float4*)(qf + ((size_t)(b * NN) + qt * 64 + row) * DD + h * 32 + ch * 4);
        __half h0 = __float2half_rn(v4.x), h1 = __float2half_rn(v4.y);
        __half h2 = __float2half_rn(v4.z), h3 = __float2half_rn(v4.w);
        __half l0 = __float2half_rn(v4.x - __half2float(h0));
        __half l1 = __float2half_rn(v4.y - __half2float(h1));
        __half l2 = __float2half_rn(v4.z - __half2float(h2));
        __half l3 = __float2half_rn(v4.w - __half2float(h3));
        uint2 uh, ul;
        uh.x = ((uint32_t)__half_as_ushort(h1) << 16) | __half_as_ushort(h0);
        uh.y = ((uint32_t)__half_as_ushort(h3) << 16) | __half_as_ushort(h2);
        ul.x = ((uint32_t)__half_as_ushort(l1) << 16) | __half_as_ushort(l0);
        ul.y = ((uint32_t)__half_as_ushort(l3) << 16) | __half_as_ushort(l2);
        *(uint2*)&Qhi[row * 40 + ch * 4] = uh;
        *(uint2*)&Qlo[row * 40 + ch * 4] = ul;
    }

    const uint32_t aOff = (uint32_t)(w * 16 + (lane & 15)) * 80 + ((lane >> 4) << 4);
    const uint32_t bOffR = (uint32_t)((lane & 7) + ((lane >> 4) << 3));
    const uint32_t kOff = bOffR * 80 + (((lane >> 3) & 1) << 4);
    const uint32_t vOff = bOffR * 144 + (((lane >> 3) & 1) << 4);

    __syncthreads();
    uint32_t aHi[2][4], aLo[2][4];
    ldmx4(aHi[0], sQh + aOff);
    ldmx4(aHi[1], sQh + aOff + 32);
    ldmx4(aLo[0], sQl + aOff);
    ldmx4(aLo[1], sQl + aOff + 32);

    float o[4][4] = {};
    float mA = -1e30f, mB = -1e30f, lA = 0.f, lB = 0.f;
    const int rA = lane >> 2;
    const size_t qrow0 = (size_t)(b * NN) + qt * 64 + w * 16 + rA;

    for (int kt = 0; kt < 8; kt++) {
        __syncthreads();
#pragma unroll
        for (int i = 0; i < 4; i++) {
            const int id = t + i * 128;
            const int row = id >> 3, ch = id & 7;
            float4 v4 = *(const float4*)(kf + ((size_t)(b * NN) + kt * 64 + row) * DD + h * 32 + ch * 4);
            __half h0 = __float2half_rn(v4.x), h1 = __float2half_rn(v4.y);
            __half h2 = __float2half_rn(v4.z), h3 = __float2half_rn(v4.w);
            __half l0 = __float2half_rn(v4.x - __half2float(h0));
            __half l1 = __float2half_rn(v4.y - __half2float(h1));
            __half l2 = __float2half_rn(v4.z - __half2float(h2));
            __half l3 = __float2half_rn(v4.w - __half2float(h3));
            uint2 uh, ul;
            uh.x = ((uint32_t)__half_as_ushort(h1) << 16) | __half_as_ushort(h0);
            uh.y = ((uint32_t)__half_as_ushort(h3) << 16) | __half_as_ushort(h2);
            ul.x = ((uint32_t)__half_as_ushort(l1) << 16) | __half_as_ushort(l0);
            ul.y = ((uint32_t)__half_as_ushort(l3) << 16) | __half_as_ushort(l2);
            *(uint2*)&Khi[row * 40 + ch * 4] = uh;
            *(uint2*)&Klo[row * 40 + ch * 4] = ul;
        }
#pragma unroll
        for (int i = 0; i < 4; i++) {
            const int id = t + i * 128;
            const int key = id >> 3, dh = (id & 7) * 4;
            float4 v4 = *(const float4*)(vf + ((size_t)(b * NN) + kt * 64 + key) * DD + h * 32 + dh);
            Vt[(dh + 0) * 72 + key] = __float2half_rn(v4.x);
            Vt[(dh + 1) * 72 + key] = __float2half_rn(v4.y);
            Vt[(dh + 2) * 72 + key] = __float2half_rn(v4.z);
            Vt[(dh + 3) * 72 + key] = __float2half_rn(v4.w);
        }
#pragma unroll
        for (int i = 0; i < 2; i++) {
            const int id = t + i * 128;
            const int row = id >> 2, ch = id & 3;
            *(uint4*)&Ms[row * 64 + ch * 16] =
                *(const uint4*)(mask + ((size_t)(b * NN) + qt * 64 + row) * NN + kt * 64 + ch * 16);
        }
        __syncthreads();

        float s[8][4];
#pragma unroll
        for (int n = 0; n < 8; n++) { s[n][0] = s[n][1] = s[n][2] = s[n][3] = 0.f; }
#pragma unroll
        for (int ks = 0; ks < 2; ks++) {
#pragma unroll
            for (int jj = 0; jj < 4; jj++) {
                uint32_t bh[4], bl[4];
                ldmx4(bh, sKh + kOff + jj * (16 * 80) + ks * 32);
                ldmx4(bl, sKl + kOff + jj * (16 * 80) + ks * 32);
                mma16816(s[jj * 2],     aHi[ks], bh[0], bh[1]);
                mma16816(s[jj * 2 + 1], aHi[ks], bh[2], bh[3]);
                mma16816(s[jj * 2],     aHi[ks], bl[0], bl[1]);
                mma16816(s[jj * 2 + 1], aHi[ks], bl[2], bl[3]);
                mma16816(s[jj * 2],     aLo[ks], bh[0], bh[1]);
                mma16816(s[jj * 2 + 1], aLo[ks], bh[2], bh[3]);
            }
        }
#pragma unroll
        for (int n = 0; n < 8; n++) {
            s[n][0] *= SCALE; s[n][1] *= SCALE; s[n][2] *= SCALE; s[n][3] *= SCALE;
        }

        if (h == 0) {
#pragma unroll
            for (int n = 0; n < 8; n++) {
                const int col = kt * 64 + n * 8 + (lane & 3) * 2;
                *(float2*)(top + qrow0 * NN + col) = make_float2(s[n][0], s[n][1]);
                *(float2*)(top + (qrow0 + 8) * NN + col) = make_float2(s[n][2], s[n][3]);
            }
        }
        {
            const int lr = w * 16 + rA;
#pragma unroll
            for (int n = 0; n < 8; n++) {
                const int col = n * 8 + (lane & 3) * 2;
                if (Ms[lr * 64 + col])           s[n][0] = -1e18f;
                if (Ms[lr * 64 + col + 1])       s[n][1] = -1e18f;
                if (Ms[(lr + 8) * 64 + col])     s[n][2] = -1e18f;
                if (Ms[(lr + 8) * 64 + col + 1]) s[n][3] = -1e18f;
            }
        }

        float tmA = -1e30f, tmB = -1e30f;
#pragma unroll
        for (int n = 0; n < 8; n++) {
            tmA = fmaxf(tmA, fmaxf(s[n][0], s[n][1]));
            tmB = fmaxf(tmB, fmaxf(s[n][2], s[n][3]));
        }
        tmA = fmaxf(tmA, __shfl_xor_sync(0xffffffffu, tmA, 1));
        tmA = fmaxf(tmA, __shfl_xor_sync(0xffffffffu, tmA, 2));
        tmB = fmaxf(tmB, __shfl_xor_sync(0xffffffffu, tmB, 1));
        tmB = fmaxf(tmB, __shfl_xor_sync(0xffffffffu, tmB, 2));
        const float mAn = fmaxf(mA, tmA), mBn = fmaxf(mB, tmB);
        const float fAc = __expf(mA - mAn), fBc = __expf(mB - mBn);
        float sumA = 0.f, sumB = 0.f;
        uint32_t pf[4][4];
#pragma unroll
        for (int n = 0; n < 8; n++) {
            float p0 = __expf(s[n][0] - mAn), p1 = __expf(s[n][1] - mAn);
            float p2 = __expf(s[n][2] - mBn), p3 = __expf(s[n][3] - mBn);
            sumA += p0 + p1; sumB += p2 + p3;
            pf[n >> 1][(n & 1) * 2]     = packh2(p0, p1);
            pf[n >> 1][(n & 1) * 2 + 1] = packh2(p2, p3);
        }
        sumA += __shfl_xor_sync(0xffffffffu, sumA, 1);
        sumA += __shfl_xor_sync(0xffffffffu, sumA, 2);
        sumB += __shfl_xor_sync(0xffffffffu, sumB, 1);
        sumB += __shfl_xor_sync(0xffffffffu, sumB, 2);
        lA = lA * fAc + sumA;
        lB = lB * fBc + sumB;
#pragma unroll
        for (int n = 0; n < 4; n++) {
            o[n][0] *= fAc; o[n][1] *= fAc; o[n][2] *= fBc; o[n][3] *= fBc;
        }
        mA = mAn; mB = mBn;

#pragma unroll
        for (int kfi = 0; kfi < 4; kfi++) {
#pragma unroll
            for (int jj = 0; jj < 2; jj++) {
                uint32_t bv[4];
                ldmx4(bv, sV + vOff + jj * (16 * 144) + kfi * 32);
                mma16816(o[jj * 2],     pf[kfi], bv[0], bv[1]);
                mma16816(o[jj * 2 + 1], pf[kfi], bv[2], bv[3]);
            }
        }
    }

    const float iA = 1.f / lA, iB = 1.f / lB;
#pragma unroll
    for (int n = 0; n < 4; n++) {
        const int col = h * 64 + n * 8 + (lane & 3) * 2;
        *(uint32_t*)(ctx + qrow0 * DD + col) = packh2(o[n][0] * iA, o[n][1] * iA);
        *(uint32_t*)(ctx + (qrow0 + 8) * DD + col) = packh2(o[n][2] * iB, o[n][3] * iB);
    }
}

// ---------------- eu: one block per (b,i) with offset; 256 threads, 2 rows in flight ----------------
__global__ __launch_bounds__(256) void eu_kernel(
    const float* __restrict__ PQ,
    const int* __restrict__ pair_j,
    __half* __restrict__ eu, int bi0)
{
    const int bi = bi0 + blockIdx.x;
    const int b = bi >> 9;
    const int t = threadIdx.x;
    const int half = t >> 7;
    const int tc = t & 127;

    __shared__ int js[16];
    if (t < 16) js[t] = pair_j[bi * 16 + t];

    const float4 p = *(const float4*)(PQ + (size_t)bi * 1024 + tc * 4);
    __syncthreads();

#pragma unroll
    for (int dd = 0; dd < 8; dd += 2) {
        const int d0 = half * 8 + dd, d1 = d0 + 1;
        const int j0 = js[d0], j1 = js[d1];
        float4 c0 = *(const float4*)(PQ + ((size_t)(b * NN + j0)) * 1024 + 512 + tc * 4);
        float4 c1 = *(const float4*)(PQ + ((size_t)(b * NN + j1)) * 1024 + 512 + tc * 4);
        uint2 u0, u1;
        u0.x = packh2(softplusf(p.x + c0.x) - LOG2F_, softplusf(p.y + c0.y) - LOG2F_);
        u0.y = packh2(softplusf(p.z + c0.z) - LOG2F_, softplusf(p.w + c0.w) - LOG2F_);
        u1.x = packh2(softplusf(p.x + c1.x) - LOG2F_, softplusf(p.y + c1.y) - LOG2F_);
        u1.y = packh2(softplusf(p.z + c1.z) - LOG2F_, softplusf(p.w + c1.w) - LOG2F_);
        *(uint2*)(eu + ((size_t)(bi * 16 + d0)) * DD + tc * 4) = u0;
        *(uint2*)(eu + ((size_t)(bi * 16 + d1)) * DD + tc * 4) = u1;
    }
}

// ---------------- launch (fork-join on two streams) ----------------
extern "C" void kernel_launch(void* const* d_in, const int* in_sizes, int n_in,
                              void* d_out, int out_size)
{
    const float* key    = (const float*)d_in[0];
    const float* value  = (const float*)d_in[1];
    const float* query  = (const float*)d_in[2];
    const unsigned char* mask = (const unsigned char*)d_in[3];
    const float* edgef  = (const float*)d_in[4];
    const int* pair_b   = (const int*)d_in[5];
    const int* pair_i   = (const int*)d_in[6];
    const int* pair_j   = (const int*)d_in[7];
    const float* Wq = (const float*)d_in[8],  *bq = (const float*)d_in[9];
    const float* Wk = (const float*)d_in[10], *bk = (const float*)d_in[11];
    const float* Wv = (const float*)d_in[12], *bv = (const float*)d_in[13];
    const float* Wo = (const float*)d_in[14], *bo = (const float*)d_in[15];
    const float* We1 = (const float*)d_in[16], *be1 = (const float*)d_in[17];
    const float* We2 = (const float*)d_in[18], *be2 = (const float*)d_in[19];
    const float* Wu1 = (const float*)d_in[20], *bu1 = (const float*)d_in[21];
    const float* Wu2 = (const float*)d_in[22], *bu2 = (const float*)d_in[23];

    float* out  = (float*)d_out;
    float* top  = out + 2097152;
    float* eupd = out + 4194304;

    float *q_, *k_, *v_, *PQ_, *ef_, *biasPQ_, *bPQ_;
    __half *f1_, *eu_, *xK_, *xQ_, *xV_, *xC_, *WHi_, *WPQ_;
    cudaGetSymbolAddress((void**)&q_, g_q);
    cudaGetSymbolAddress((void**)&k_, g_k);
    cudaGetSymbolAddress((void**)&v_, g_v);
    cudaGetSymbolAddress((void**)&PQ_, g_PQ);
    cudaGetSymbolAddress((void**)&ef_, g_ef);
    cudaGetSymbolAddress((void**)&f1_, g_f1);
    cudaGetSymbolAddress((void**)&eu_, g_eu);
    cudaGetSymbolAddress((void**)&xK_, g_xK);
    cudaGetSymbolAddress((void**)&xQ_, g_xQ);
    cudaGetSymbolAddress((void**)&xV_, g_xV);
    cudaGetSymbolAddress((void**)&xC_, g_xC);
    cudaGetSymbolAddress((void**)&WHi_, g_WHi);
    cudaGetSymbolAddress((void**)&WPQ_, g_WPQ);
    cudaGetSymbolAddress((void**)&biasPQ_, g_biasPQ);
    cudaGetSymbolAddress((void**)&bPQ_, g_bPQ);

    cudaFuncSetAttribute((const void*)tc_gemm<0, 0>,
                         cudaFuncAttributeMaxDynamicSharedMemorySize, TC_SMEM);
    cudaFuncSetAttribute((const void*)tc_gemm<0, 1>,
                         cudaFuncAttributeMaxDynamicSharedMemorySize, TC_SMEM);
    cudaFuncSetAttribute((const void*)tc_gemm_qkv,
                         cudaFuncAttributeMaxDynamicSharedMemorySize, TC_SMEM);
    cudaFuncSetAttribute((const void*)tc_gemm_f32a,
                         cudaFuncAttributeMaxDynamicSharedMemorySize, AF_SMEM);

    const int WSZ = 262144;

    cudaStream_t s2;
    cudaStreamCreateWithFlags(&s2, cudaStreamNonBlocking);
    cudaEvent_t eW, eQKV, eL, eG, eE0, eE1;
    cudaEventCreateWithFlags(&eW, cudaEventDisableTiming);
    cudaEventCreateWithFlags(&eQKV, cudaEventDisableTiming);
    cudaEventCreateWithFlags(&eL, cudaEventDisableTiming);
    cudaEventCreateWithFlags(&eG, cudaEventDisableTiming);
    cudaEventCreateWithFlags(&eE0, cudaEventDisableTiming);
    cudaEventCreateWithFlags(&eE1, cudaEventDisableTiming);

    // s0: weight prep, then fork
    wsplit_all_t<<<545, 256>>>(Wk, Wq, Wv, Wo, Wu1, Wu2, We1, We2, bu1,
                               WHi_, biasPQ_);
    cudaEventRecord(eW, 0);

    // s2 (edge chain): MLP1 (fused f32 A) -> MLP2 -> ef
    cudaStreamWaitEvent(s2, eW, 0);
    tc_gemm_f32a<<<dim3(4, 512), 256, AF_SMEM, s2>>>(edgef, WHi_ + 7 * WSZ, be1, f1_, 512);
    tc_gemm<0, 0><<<dim3(2, 512), 256, TC_SMEM, s2>>>(f1_, WHi_ + 8 * WSZ,
                                                      be2, ef_, nullptr, 256);

    // s0: fused PQ weight W'^T = Wu1^T @ Wo (+ fused bias), then node chain
    bfuse<<<1024, 128>>>(bo, WHi_ + 4 * WSZ, biasPQ_, bPQ_);
    tc_gemm<0, 1><<<dim3(4, 8), 256, TC_SMEM>>>(WHi_ + 4 * WSZ, WHi_ + 9 * WSZ,
                                                nullptr, nullptr, WPQ_, 512);
    conv3_f16<<<1536, 256>>>(key, query, value, xK_, xQ_, xV_);
    tc_gemm_qkv<<<dim3(4, 32, 3), 256, TC_SMEM>>>(xK_, xQ_, xV_,
                                                  WHi_ + 0 * WSZ, WHi_ + 1 * WSZ, WHi_ + 2 * WSZ,
                                                  bk, bq, bv, k_, q_, v_);
    cudaEventRecord(eQKV, 0);

    // s2: local attention (needs ef + qkv)
    cudaStreamWaitEvent(s2, eQKV, 0);
    local_attn<<<ROWS, 256, 0, s2>>>(q_, k_, v_, ef_, pair_j, xC_);
    cudaEventRecord(eL, s2);

    // s0: global attention (disjoint ctx columns)
    global_attn_tc<<<dim3(8, 8, 8), 128>>>(q_, k_, v_, mask, xC_, top);
    cudaEventRecord(eG, 0);

    // s2: PQ = ctx @ W' + b' (needs full ctx: eL already on s2, wait for eG)
    cudaStreamWaitEvent(s2, eG, 0);
    tc_gemm<0, 0><<<dim3(8, 32), 256, TC_SMEM, s2>>>(xC_, WPQ_, bPQ_, PQ_, nullptr, 1024);
    // s2: eu halves
    eu_kernel<<<2048, 256, 0, s2>>>(PQ_, pair_j, eu_, 0);
    cudaEventRecord(eE0, s2);
    eu_kernel<<<2048, 256, 0, s2>>>(PQ_, pair_j, eu_, 2048);
    cudaEventRecord(eE1, s2);

    // s0: output projection (needs full ctx: eG implicit on s0, wait eL)
    cudaStreamWaitEvent(0, eL, 0);
    tc_gemm<0, 0><<<dim3(4, 32), 256, TC_SMEM>>>(xC_, WHi_ + 3 * WSZ,
                                                 bo, out, nullptr, 512);

    // s0: Wu2 halves pipelined against eu halves
    cudaStreamWaitEvent(0, eE0, 0);
    tc_gemm<0, 0><<<dim3(4, 256), 256, TC_SMEM>>>(eu_, WHi_ + 6 * WSZ,
                                                  bu2, eupd, nullptr, 512);
    cudaStreamWaitEvent(0, eE1, 0);
    tc_gemm<0, 0><<<dim3(4, 256), 256, TC_SMEM>>>(eu_ + (size_t)32768 * 512, WHi_ + 6 * WSZ,
                                                  bu2, eupd + (size_t)32768 * 512, nullptr, 512);

    cudaEventDestroy(eW);
    cudaEventDestroy(eQKV);
    cudaEventDestroy(eL);
    cudaEventDestroy(eG);
    cudaEventDestroy(eE0);
    cudaEventDestroy(eE1);
    cudaStreamDestroy(s2);
}

// round 15
// speedup vs baseline: 1.0555x; 1.0002x over previous
#include <cuda_runtime.h>
#include <cuda_bf16.h>
#include <cuda_fp16.h>
#include <math.h>
#include <stdint.h>

// Problem constants
#define BB 8
#define NN 512
#define DD 512
#define DEG_ 16
#define EE 65536   // B*N*DEG
#define ROWS 4096  // B*N
#define GK 512     // K dim of all big GEMMs
#define SCALE 0.17677669529663687f  // 1/sqrt(32)
#define LOG2F_ 0.6931471805599453f

// ---------------- scratch (device globals; no allocs allowed) ----------------
__device__ float g_q[ROWS * DD];
__device__ float g_k[ROWS * DD];
__device__ float g_v[ROWS * DD];
__device__ float g_PQ[ROWS * 1024];
__device__ float g_ef[(size_t)EE * 256];

__device__ __half g_f1[(size_t)EE * DD];
__device__ __half g_eu[(size_t)EE * DD];
__device__ __half g_xK[ROWS * DD];
__device__ __half g_xQ[ROWS * DD];
__device__ __half g_xV[ROWS * DD];
__device__ __half g_xC[ROWS * DD];   // ctx in fp16

// weights fp16: 0 WkT,1 WqT,2 WvT,3 WoT,4 Wu1T(1024x512),6 Wu2T,7 We1T,8 We2T(256x512),9 Wo natural
__device__ __half g_WHi[10 * 262144];
__device__ __half g_WPQ[1024 * 512];   // W'^T = (Wo@Wu1)^T, [1024,512]
__device__ float g_biasPQ[1024];
__device__ float g_bPQ[1024];          // b' = bo@Wu1 + biasPQ

__device__ __forceinline__ float softplusf(float x) {
    return fmaxf(x, 0.f) + log1pf(expf(-fabsf(x)));
}

__device__ __forceinline__ uint32_t smem_to_u32(const void* smem_ptr) {
    uint32_t addr;
    asm("{ .reg .u64 tmp; cvta.to.shared.u64 tmp, %1; cvt.u32.u64 %0, tmp; }"
        : "=r"(addr) : "l"(smem_ptr));
    return addr;
}

// ---------------- PTX: cp.async / ldmatrix / mma (base-arch legal) ----------------
__device__ __forceinline__ void cpasync16(uint32_t saddr, const void* g) {
    asm volatile("cp.async.cg.shared.global [%0], [%1], 16;" :: "r"(saddr), "l"(g));
}
#define CP_COMMIT() asm volatile("cp.async.commit_group;")
#define CP_WAIT(n)  asm volatile("cp.async.wait_group %0;" :: "n"(n))

__device__ __forceinline__ void ldmx4(uint32_t r[4], uint32_t addr) {
    asm volatile("ldmatrix.sync.aligned.m8n8.x4.shared.b16 {%0,%1,%2,%3}, [%4];"
                 : "=r"(r[0]), "=r"(r[1]), "=r"(r[2]), "=r"(r[3]) : "r"(addr));
}

__device__ __forceinline__ void mma16816(float c[4], const uint32_t a[4],
                                         uint32_t b0, uint32_t b1) {
    asm volatile("mma.sync.aligned.m16n8k16.row.col.f32.f16.f16.f32 "
                 "{%0,%1,%2,%3}, {%4,%5,%6,%7}, {%8,%9}, {%0,%1,%2,%3};"
                 : "+f"(c[0]), "+f"(c[1]), "+f"(c[2]), "+f"(c[3])
                 : "r"(a[0]), "r"(a[1]), "r"(a[2]), "r"(a[3]), "r"(b0), "r"(b1));
}

__device__ __forceinline__ uint32_t packh2(float x, float y) {
    __half2 h = __floats2half2_rn(x, y);
    return *(uint32_t*)&h;
}

// ======================= tensor-core GEMM core (mma.sync fp16) ===============
#define ROWB 80
#define TILE_B (128 * ROWB)      // 10240
#define A_OFF 0
#define B_OFF (1 * TILE_B)
#define STAGE_B (2 * TILE_B)     // 20480
#define NSTAGE 4
#define TC_SMEM (NSTAGE * STAGE_B)  // 81920

// OUT: 0 = f32 only, 1 = fp16 only, 2 = f32 + fp16
template <int SOFTPLUS, int OUT>
__device__ __forceinline__ void tc_gemm_core(
    char* smem,
    const __half* __restrict__ A, const __half* __restrict__ B,
    const float* __restrict__ bias,
    float* __restrict__ Cf, __half* __restrict__ Ch,
    int N, int bm, int bn)
{
    const uint32_t sb = smem_to_u32(smem);
    const int t = threadIdx.x, lane = t & 31, w = t >> 5;
    const int wm = w & 3, wn = w >> 2;
    constexpr int KT = GK / 32;   // 16

    float acc[2][8][4] = {};

    const __half* pA[2];
    const __half* pB[2];
    uint32_t so[2];
#pragma unroll
    for (int i = 0; i < 2; i++) {
        const int id = t + i * 256;
        const int row = id >> 2, ch = id & 3;
        so[i] = row * ROWB + ch * 16;
        pA[i] = A + (size_t)(bm + row) * GK + ch * 8;
        pB[i] = B + (size_t)(bn + row) * GK + ch * 8;
    }

    auto issue = [&](int kcI, uint32_t stbase) {
#pragma unroll
        for (int i = 0; i < 2; i++) {
            cpasync16(stbase + A_OFF + so[i], pA[i] + kcI * 32);
            cpasync16(stbase + B_OFF + so[i], pB[i] + kcI * 32);
        }
    };

    const uint32_t aRow = (uint32_t)(wm * 32 + (lane & 15)) * ROWB + ((lane >> 4) << 4);
    const int n_off = (lane & 7) + ((lane >> 4) << 3);
    const int k_half = (lane >> 3) & 1;
    const uint32_t bRow = (uint32_t)(wn * 64 + n_off) * ROWB + (k_half << 4);

    issue(0, sb);               CP_COMMIT();
    issue(1, sb + STAGE_B);     CP_COMMIT();
    issue(2, sb + 2 * STAGE_B); CP_COMMIT();

#pragma unroll
    for (int kc = 0; kc < KT; kc++) {
        if (kc + 2 < KT)      { CP_WAIT(2); }
        else if (kc + 1 < KT) { CP_WAIT(1); }
        else                  { CP_WAIT(0); }
        __syncthreads();
        if (kc + 3 < KT) {
            issue(kc + 3, sb + ((kc + 3) & 3) * STAGE_B);
            CP_COMMIT();
        }
        const uint32_t cur = sb + (kc & 3) * STAGE_B;

#pragma unroll
        for (int ks = 0; ks < 2; ks++) {
            const uint32_t kb = ks * 32;
            uint32_t a[2][4], bh[4][4];
            ldmx4(a[0], cur + A_OFF + aRow + kb);
            ldmx4(a[1], cur + A_OFF + aRow + 16 * ROWB + kb);
#pragma unroll
            for (int jj = 0; jj < 4; jj++)
                ldmx4(bh[jj], cur + B_OFF + bRow + jj * 16 * ROWB + kb);
#pragma unroll
            for (int g = 0; g < 2; g++) {
#pragma unroll
                for (int j = 0; j < 8; j++) {
                    const int jj = j >> 1, hf = (j & 1) * 2;
                    mma16816(acc[g][j], a[g], bh[jj][hf], bh[jj][hf + 1]);
                }
            }
        }
    }

    float bcol[16];
    {
        const int col0 = bn + wn * 64 + (lane & 3) * 2;
#pragma unroll
        for (int j = 0; j < 8; j++) {
            bcol[j * 2]     = bias ? bias[col0 + j * 8]     : 0.f;
            bcol[j * 2 + 1] = bias ? bias[col0 + j * 8 + 1] : 0.f;
        }
    }
#pragma unroll
    for (int g = 0; g < 2; g++) {
#pragma unroll
        for (int j = 0; j < 8; j++) {
            const int row = bm + wm * 32 + g * 16 + (lane >> 2);
            const int col = bn + wn * 64 + j * 8 + (lane & 3) * 2;
            float v0 = acc[g][j][0] + bcol[j * 2], v1 = acc[g][j][1] + bcol[j * 2 + 1];
            float v2 = acc[g][j][2] + bcol[j * 2], v3 = acc[g][j][3] + bcol[j * 2 + 1];
            if (SOFTPLUS) {
                v0 = softplusf(v0) - LOG2F_; v1 = softplusf(v1) - LOG2F_;
                v2 = softplusf(v2) - LOG2F_; v3 = softplusf(v3) - LOG2F_;
            }
            if (OUT == 0 || OUT == 2) {
                *(float2*)(Cf + (size_t)row * N + col) = make_float2(v0, v1);
                *(float2*)(Cf + (size_t)(row + 8) * N + col) = make_float2(v2, v3);
            }
            if (OUT == 1 || OUT == 2) {
                *(uint32_t*)(Ch + (size_t)row * N + col) = packh2(v0, v1);
                *(uint32_t*)(Ch + (size_t)(row + 8) * N + col) = packh2(v2, v3);
            }
        }
    }
}

template <int SOFTPLUS, int OUT>
__global__ __launch_bounds__(256, 2) void tc_gemm(
    const __half* __restrict__ A, const __half* __restrict__ B,
    const float* __restrict__ bias,
    float* __restrict__ Cf, __half* __restrict__ Ch,
    int N)
{
    extern __shared__ char smem[];
    tc_gemm_core<SOFTPLUS, OUT>(smem, A, B, bias, Cf, Ch, N,
                                blockIdx.y * 128, blockIdx.x * 128);
}

// batched K/Q/V projection: blockIdx.z selects the triple
__global__ __launch_bounds__(256, 2) void tc_gemm_qkv(
    const __half* __restrict__ xK, const __half* __restrict__ xQ, const __half* __restrict__ xV,
    const __half* __restrict__ WkT, const __half* __restrict__ WqT, const __half* __restrict__ WvT,
    const float* __restrict__ bk, const float* __restrict__ bq, const float* __restrict__ bv,
    float* __restrict__ k_, float* __restrict__ q_, float* __restrict__ v_)
{
    extern __shared__ char smem[];
    const int z = blockIdx.z;
    const __half* A = (z == 0) ? xK : (z == 1) ? xQ : xV;
    const __half* B = (z == 0) ? WkT : (z == 1) ? WqT : WvT;
    const float* bias = (z == 0) ? bk : (z == 1) ? bq : bv;
    float* C = (z == 0) ? k_ : (z == 1) ? q_ : v_;
    tc_gemm_core<0, 0>(smem, A, B, bias, C, nullptr, 512,
                       blockIdx.y * 128, blockIdx.x * 128);
}

// ======================= MLP1 GEMM with fused f32->fp16 A conversion =======================
#define AF_A32 0
#define AF_B   18432
#define AF_STAGE (18432 + 10240) // 28672
#define AF_F16 (3 * AF_STAGE)    // 86016
#define AF_SMEM (AF_F16 + 10240) // 96256

__global__ __launch_bounds__(256, 2) void tc_gemm_f32a(
    const float* __restrict__ A, const __half* __restrict__ B,
    const float* __restrict__ bias, __half* __restrict__ Ch, int N)
{
    extern __shared__ char smem[];
    const uint32_t sb = smem_to_u32(smem);
    const int t = threadIdx.x, lane = t & 31, w = t >> 5;
    const int wm = w & 3, wn = w >> 2;
    const int bm = blockIdx.y * 128, bn = blockIdx.x * 128;
    constexpr int KT = GK / 32;   // 16

    float acc[2][8][4] = {};

    const float* pA[4];
    uint32_t soA[4];
#pragma unroll
    for (int i = 0; i < 4; i++) {
        const int id = t + i * 256;
        const int row = id >> 3, ch = id & 7;
        soA[i] = row * 144 + ch * 16;
        pA[i] = A + (size_t)(bm + row) * GK + ch * 4;
    }
    const __half* pB[2];
    uint32_t soB[2];
#pragma unroll
    for (int i = 0; i < 2; i++) {
        const int id = t + i * 256;
        const int row = id >> 2, ch = id & 3;
        soB[i] = row * ROWB + ch * 16;
        pB[i] = B + (size_t)(bn + row) * GK + ch * 8;
    }

    auto issue = [&](int kcI, uint32_t st) {
#pragma unroll
        for (int i = 0; i < 4; i++) cpasync16(st + AF_A32 + soA[i], pA[i] + kcI * 32);
#pragma unroll
        for (int i = 0; i < 2; i++) cpasync16(st + AF_B + soB[i], pB[i] + kcI * 32);
    };

    const uint32_t aRow = (uint32_t)(wm * 32 + (lane & 15)) * ROWB + ((lane >> 4) << 4);
    const int n_off = (lane & 7) + ((lane >> 4) << 3);
    const int k_half = (lane >> 3) & 1;
    const uint32_t bRow = (uint32_t)(wn * 64 + n_off) * ROWB + (k_half << 4);
    const uint32_t sF = sb + AF_F16;

    const int cr = t >> 1, chf = t & 1;
    const uint32_t cvtSrc = cr * 144 + chf * 64;
    char* const cvtDstP = smem + AF_F16 + cr * ROWB + chf * 32;

    issue(0, sb);            CP_COMMIT();
    issue(1, sb + AF_STAGE); CP_COMMIT();

#pragma unroll
    for (int kc = 0; kc < KT; kc++) {
        if (kc + 1 < KT) { CP_WAIT(1); } else { CP_WAIT(0); }
        __syncthreads();
        const int st = kc % 3;
        const uint32_t cur = sb + st * AF_STAGE;
        if (kc + 2 < KT) {
            issue(kc + 2, sb + ((kc + 2) % 3) * AF_STAGE);
            CP_COMMIT();
        }
        {
            const char* srcp = smem + st * AF_STAGE + cvtSrc;
            float4 f0 = *(const float4*)(srcp);
            float4 f1v = *(const float4*)(srcp + 16);
            float4 f2 = *(const float4*)(srcp + 32);
            float4 f3 = *(const float4*)(srcp + 48);
            uint4 u0, u1;
            u0.x = packh2(f0.x, f0.y);  u0.y = packh2(f0.z, f0.w);
            u0.z = packh2(f1v.x, f1v.y); u0.w = packh2(f1v.z, f1v.w);
            u1.x = packh2(f2.x, f2.y);  u1.y = packh2(f2.z, f2.w);
            u1.z = packh2(f3.x, f3.y);  u1.w = packh2(f3.z, f3.w);
            *(uint4*)(cvtDstP)      = u0;
            *(uint4*)(cvtDstP + 16) = u1;
        }
        __syncthreads();

#pragma unroll
        for (int ks = 0; ks < 2; ks++) {
            const uint32_t kb = ks * 32;
            uint32_t a[2][4], bh[4][4];
            ldmx4(a[0], sF + aRow + kb);
            ldmx4(a[1], sF + aRow + 16 * ROWB + kb);
#pragma unroll
            for (int jj = 0; jj < 4; jj++)
                ldmx4(bh[jj], cur + AF_B + bRow + jj * 16 * ROWB + kb);
#pragma unroll
            for (int g = 0; g < 2; g++) {
#pragma unroll
                for (int j = 0; j < 8; j++) {
                    const int jj = j >> 1, hf = (j & 1) * 2;
                    mma16816(acc[g][j], a[g], bh[jj][hf], bh[jj][hf + 1]);
                }
            }
        }
    }

    float bcol[16];
    {
        const int col0 = bn + wn * 64 + (lane & 3) * 2;
#pragma unroll
        for (int j = 0; j < 8; j++) {
            bcol[j * 2]     = bias[col0 + j * 8];
            bcol[j * 2 + 1] = bias[col0 + j * 8 + 1];
        }
    }
#pragma unroll
    for (int g = 0; g < 2; g++) {
#pragma unroll
        for (int j = 0; j < 8; j++) {
            const int row = bm + wm * 32 + g * 16 + (lane >> 2);
            const int col = bn + wn * 64 + j * 8 + (lane & 3) * 2;
            float v0 = softplusf(acc[g][j][0] + bcol[j * 2]) - LOG2F_;
            float v1 = softplusf(acc[g][j][1] + bcol[j * 2 + 1]) - LOG2F_;
            float v2 = softplusf(acc[g][j][2] + bcol[j * 2]) - LOG2F_;
            float v3 = softplusf(acc[g][j][3] + bcol[j * 2 + 1]) - LOG2F_;
            *(uint32_t*)(Ch + (size_t)row * N + col) = packh2(v0, v1);
            *(uint32_t*)(Ch + (size_t)(row + 8) * N + col) = packh2(v2, v3);
        }
    }
}

// key/query/value conversions in one launch, ILP4.
__global__ __launch_bounds__(256) void conv3_f16(
    const float* __restrict__ k, const float* __restrict__ q, const float* __restrict__ v,
    __half* __restrict__ xk, __half* __restrict__ xq, __half* __restrict__ xv)
{
    const int seg = blockIdx.x >> 9;
    const size_t base = (size_t)(blockIdx.x & 511) * 1024 + threadIdx.x;
    const float* x = (seg == 0) ? k : (seg == 1) ? q : v;
    __half* y = (seg == 0) ? xk : (seg == 1) ? xq : xv;
    float4 val[4];
#pragma unroll
    for (int kk = 0; kk < 4; kk++) val[kk] = ((const float4*)x)[base + kk * 256];
#pragma unroll
    for (int kk = 0; kk < 4; kk++) {
        uint2 u;
        u.x = packh2(val[kk].x, val[kk].y);
        u.y = packh2(val[kk].z, val[kk].w);
        *(uint2*)(y + (base + kk * 256) * 4) = u;
    }
}

// ---------------- weights: coalesced SMEM-tile transpose + fp16 ----------------
__global__ __launch_bounds__(256) void wsplit_all_t(
    const float* __restrict__ Wk, const float* __restrict__ Wq, const float* __restrict__ Wv,
    const float* __restrict__ Wo, const float* __restrict__ Wu1, const float* __restrict__ Wu2,
    const float* __restrict__ We1, const float* __restrict__ We2,
    const float* __restrict__ bu1,
    __half* __restrict__ WHi, float* __restrict__ biasPQ)
{
    __shared__ float S[64][68];
    const int bid = blockIdx.x, t = threadIdx.x;

    if (bid == 544) {
#pragma unroll
        for (int it = 0; it < 4; it++) {
            const int i = it * 256 + t;
            biasPQ[i] = (i < 512) ? bu1[i] : 0.f;
        }
        return;
    }

    const float* src;
    int segOut, Ndim, tk, tn;
    if (bid < 512) {
        const int seg = bid >> 6;
        switch (seg) {
            case 0: src = Wk; break;
            case 1: src = Wq; break;
            case 2: src = Wv; break;
            case 3: src = Wo; break;
            case 4: src = Wu1; break;
            case 5: src = Wu1 + 262144; break;
            case 6: src = Wu2; break;
            default: src = We1; break;
        }
        segOut = seg; Ndim = 512;
        const int tile = bid & 63;
        tk = tile >> 3; tn = tile & 7;
    } else {
        src = We2; segOut = 8; Ndim = 256;
        const int tile = bid - 512;
        tk = tile >> 2; tn = tile & 3;
    }

    {
        const int c4 = (t & 15) * 4;
#pragma unroll
        for (int it = 0; it < 4; it++) {
            const int r = it * 16 + (t >> 4);
            float4 v = *(const float4*)(src + (size_t)(tk * 64 + r) * Ndim + tn * 64 + c4);
            S[r][c4] = v.x; S[r][c4 + 1] = v.y; S[r][c4 + 2] = v.z; S[r][c4 + 3] = v.w;
        }
    }
    __syncthreads();

    {
        __half* dst = WHi + (size_t)segOut * 262144;
        const int kg = (t & 15) * 4;
#pragma unroll
        for (int it = 0; it < 4; it++) {
            const int n = it * 16 + (t >> 4);
            uint2 u;
            u.x = packh2(S[kg][n], S[kg + 1][n]);
            u.y = packh2(S[kg + 2][n], S[kg + 3][n]);
            *(uint2*)(dst + (size_t)(tn * 64 + n) * 512 + tk * 64 + kg) = u;
        }
    }
    if (segOut == 3) {
        __half* dst9 = WHi + (size_t)9 * 262144;
        const int c4 = (t & 15) * 4;
#pragma unroll
        for (int it = 0; it < 4; it++) {
            const int r = it * 16 + (t >> 4);
            uint2 u;
            u.x = packh2(S[r][c4], S[r][c4 + 1]);
            u.y = packh2(S[r][c4 + 2], S[r][c4 + 3]);
            *(uint2*)(dst9 + (size_t)(tk * 64 + r) * 512 + tn * 64 + c4) = u;
        }
    }
}

// b' = bo @ Wu1 + biasPQ  — one block per output n, 128-thread reduction
__global__ __launch_bounds__(128) void bfuse(
    const float* __restrict__ bo, const __half* __restrict__ Wu1T,
    const float* __restrict__ biasPQ, float* __restrict__ bPQ)
{
    const int n = blockIdx.x;           // 0..1023
    const int t = threadIdx.x;          // 0..127
    const __half* row = Wu1T + (size_t)n * 512;
    float s = 0.f;
#pragma unroll
    for (int i = 0; i < 4; i++) {
        const int j = t + i * 128;
        s = fmaf(bo[j], __half2float(row[j]), s);
    }
#pragma unroll
    for (int o = 16; o; o >>= 1) s += __shfl_xor_sync(0xffffffffu, s, o);
    __shared__ float ws[4];
    if ((t & 31) == 0) ws[t >> 5] = s;
    __syncthreads();
    if (t == 0) bPQ[n] = ws[0] + ws[1] + ws[2] + ws[3] + biasPQ[n];
}

// ---------------- local attention: one block per (b,i), ctx written fp16 ----------------
__global__ __launch_bounds__(256) void local_attn(
    const float* __restrict__ q, const float* __restrict__ k,
    const float* __restrict__ v, const float* __restrict__ ef,
    const int* __restrict__ pair_j, __half* __restrict__ ctx)
{
    const int bi = blockIdx.x;
    const int b = bi >> 9;
    const int t = threadIdx.x;

    __shared__ float qs[256];
    __shared__ int js[16];
    __shared__ float sc[16][8];
    __shared__ float wgt[16][8];

    if (t < 16) js[t] = pair_j[bi * 16 + t];
    qs[t] = q[(size_t)bi * DD + 256 + t];
    __syncthreads();

    if (t < 128) {
        const int d = t >> 3, h = t & 7;
        const int j = js[d];
        const float* kr = k + ((size_t)(b * NN + j)) * DD + 256 + h * 32;
        const float* er = ef + ((size_t)(bi * 16 + d)) * 256 + h * 32;
        const float* qr = qs + h * 32;
        float s = 0.f;
#pragma unroll
        for (int c4 = 0; c4 < 8; c4++) {
            float4 kk = *(const float4*)(kr + c4 * 4);
            float4 eee = *(const float4*)(er + c4 * 4);
            s = fmaf(qr[c4 * 4 + 0], kk.x * eee.x, s);
            s = fmaf(qr[c4 * 4 + 1], kk.y * eee.y, s);
            s = fmaf(qr[c4 * 4 + 2], kk.z * eee.z, s);
            s = fmaf(qr[c4 * 4 + 3], kk.w * eee.w, s);
        }
        sc[d][h] = s * SCALE;
    }
    __syncthreads();

    if (t < 8) {
        const int h = t;
        float m = -1e30f;
#pragma unroll
        for (int d = 0; d < 16; d++) {
            float s = sc[d][h];
            if (s > -10000.f && s > m) m = s;
        }
        float sum = 0.f;
#pragma unroll
        for (int d = 0; d < 16; d++) {
            float s = sc[d][h];
            float e = (s > -10000.f) ? expf(s - m) : 0.f;
            wgt[d][h] = e;
            sum += e;
        }
        float inv = (sum > 0.f) ? 1.f / sum : 0.f;
#pragma unroll
        for (int d = 0; d < 16; d++) wgt[d][h] *= inv;
    }
    __syncthreads();

    const int h = t >> 5, c = t & 31;
    float o = 0.f;
#pragma unroll
    for (int d = 0; d < 16; d++) {
        float w = wgt[d][h];
        o = fmaf(w, v[((size_t)(b * NN + js[d])) * DD + 256 + h * 32 + c], o);
    }
    ctx[(size_t)bi * DD + h * 64 + 32 + c] = __float2half_rn(o);
}

// ========== global attention: tensor-core flash kernel ==========
__global__ __launch_bounds__(128) void global_attn_tc(
    const float* __restrict__ qf, const float* __restrict__ kf,
    const float* __restrict__ vf, const unsigned char* __restrict__ mask,
    __half* __restrict__ ctx, float* __restrict__ top)
{
    const int qt = blockIdx.x, h = blockIdx.y, b = blockIdx.z;
    const int t = threadIdx.x, lane = t & 31, w = t >> 5;

    __shared__ __half Qhi[64 * 40], Qlo[64 * 40];
    __shared__ __half Khi[64 * 40], Klo[64 * 40];
    __shared__ __half Vt[32 * 72];
    __shared__ unsigned char Ms[64 * 64];

    const uint32_t sQh = smem_to_u32(Qhi), sQl = smem_to_u32(Qlo);
    const uint32_t sKh = smem_to_u32(Khi), sKl = smem_to_u32(Klo);
    const uint32_t sV = smem_to_u32(Vt);

#pragma unroll
    for (int i = 0; i < 4; i++) {
        const int id = t + i * 128;
        const int row = id >> 3, ch = id & 7;
        float4 v4 = *(const float4*)(qf + ((size_t)(b * NN) + qt * 64 + row) * DD + h * 32 + ch * 4);
        __half h0 = __float2half_rn(v4.x), h1 = __float2half_rn(v4.y);
        __half h2 = __float2half_rn(v4.z), h3 = __float2half_rn(v4.w);
        __half l0 = __float2half_rn(v4.x - __half2float(h0));
        __half l1 = __float2half_rn(v4.y - __half2float(h1));
        __half l2 = __float2half_rn(v4.z - __half2float(h2));
        __half l3 = __float2half_rn(v4.w - __half2float(h3));
        uint2 uh, ul;
        uh.x = ((uint32_t)__half_as_ushort(h1) << 16) | __half_as_ushort(h0);
        uh.y = ((uint32_t)__half_as_ushort(h3) << 16) | __half_as_ushort(h2);
        ul.x = ((uint32_t)__half_as_ushort(l1) << 16) | __half_as_ushort(l0);
        ul.y = ((uint32_t)__half_as_ushort(l3) << 16) | __half_as_ushort(l2);
        *(uint2*)&Qhi[row * 40 + ch * 4] = uh;
        *(uint2*)&Qlo[row * 40 + ch * 4] = ul;
    }

    const uint32_t aOff = (uint32_t)(w * 16 + (lane & 15)) * 80 + ((lane >> 4) << 4);
    const uint32_t bOffR = (uint32_t)((lane & 7) + ((lane >> 4) << 3));
    const uint32_t kOff = bOffR * 80 + (((lane >> 3) & 1) << 4);
    const uint32_t vOff = bOffR * 144 + (((lane >> 3) & 1) << 4);

    __syncthreads();
    uint32_t aHi[2][4], aLo[2][4];
    ldmx4(aHi[0], sQh + aOff);
    ldmx4(aHi[1], sQh + aOff + 32);
    ldmx4(aLo[0], sQl + aOff);
    ldmx4(aLo[1], sQl + aOff + 32);

    float o[4][4] = {};
    float mA = -1e30f, mB = -1e30f, lA = 0.f, lB = 0.f;
    const int rA = lane >> 2;
    const size_t qrow0 = (size_t)(b * NN) + qt * 64 + w * 16 + rA;

    for (int kt = 0; kt < 8; kt++) {
        __syncthreads();
#pragma unroll
        for (int i = 0; i < 4; i++) {
            const int id = t + i * 128;
            const int row = id >> 3, ch = id & 7;
            float4 v4 = *(const float4*)(kf + ((size_t)(b * NN) + kt * 64 + row) * DD + h * 32 + ch * 4);
            __half h0 = __float2half_rn(v4.x), h1 = __float2half_rn(v4.y);
            __half h2 = __float2half_rn(v4.z), h3 = __float2half_rn(v4.w);
            __half l0 = __float2half_rn(v4.x - __half2float(h0));
            __half l1 = __float2half_rn(v4.y - __half2float(h1));
            __half l2 = __float2half_rn(v4.z - __half2float(h2));
            __half l3 = __float2half_rn(v4.w - __half2float(h3));
            uint2 uh, ul;
            uh.x = ((uint32_t)__half_as_ushort(h1) << 16) | __half_as_ushort(h0);
            uh.y = ((uint32_t)__half_as_ushort(h3) << 16) | __half_as_ushort(h2);
            ul.x = ((uint32_t)__half_as_ushort(l1) << 16) | __half_as_ushort(l0);
            ul.y = ((uint32_t)__half_as_ushort(l3) << 16) | __half_as_ushort(l2);
            *(uint2*)&Khi[row * 40 + ch * 4] = uh;
            *(uint2*)&Klo[row * 40 + ch * 4] = ul;
        }
#pragma unroll
        for (int i = 0; i < 4; i++) {
            const int id = t + i * 128;
            const int key = id >> 3, dh = (id & 7) * 4;
            float4 v4 = *(const float4*)(vf + ((size_t)(b * NN) + kt * 64 + key) * DD + h * 32 + dh);
            Vt[(dh + 0) * 72 + key] = __float2half_rn(v4.x);
            Vt[(dh + 1) * 72 + key] = __float2half_rn(v4.y);
            Vt[(dh + 2) * 72 + key] = __float2half_rn(v4.z);
            Vt[(dh + 3) * 72 + key] = __float2half_rn(v4.w);
        }
#pragma unroll
        for (int i = 0; i < 2; i++) {
            const int id = t + i * 128;
            const int row = id >> 2, ch = id & 3;
            *(uint4*)&Ms[row * 64 + ch * 16] =
                *(const uint4*)(mask + ((size_t)(b * NN) + qt * 64 + row) * NN + kt * 64 + ch * 16);
        }
        __syncthreads();

        float s[8][4];
#pragma unroll
        for (int n = 0; n < 8; n++) { s[n][0] = s[n][1] = s[n][2] = s[n][3] = 0.f; }
#pragma unroll
        for (int ks = 0; ks < 2; ks++) {
#pragma unroll
            for (int jj = 0; jj < 4; jj++) {
                uint32_t bh[4], bl[4];
                ldmx4(bh, sKh + kOff + jj * (16 * 80) + ks * 32);
                ldmx4(bl, sKl + kOff + jj * (16 * 80) + ks * 32);
                mma16816(s[jj * 2],     aHi[ks], bh[0], bh[1]);
                mma16816(s[jj * 2 + 1], aHi[ks], bh[2], bh[3]);
                mma16816(s[jj * 2],     aHi[ks], bl[0], bl[1]);
                mma16816(s[jj * 2 + 1], aHi[ks], bl[2], bl[3]);
                mma16816(s[jj * 2],     aLo[ks], bh[0], bh[1]);
                mma16816(s[jj * 2 + 1], aLo[ks], bh[2], bh[3]);
            }
        }
#pragma unroll
        for (int n = 0; n < 8; n++) {
            s[n][0] *= SCALE; s[n][1] *= SCALE; s[n][2] *= SCALE; s[n][3] *= SCALE;
        }

        if (h == 0) {
#pragma unroll
            for (int n = 0; n < 8; n++) {
                const int col = kt * 64 + n * 8 + (lane & 3) * 2;
                *(float2*)(top + qrow0 * NN + col) = make_float2(s[n][0], s[n][1]);
                *(float2*)(top + (qrow0 + 8) * NN + col) = make_float2(s[n][2], s[n][3]);
            }
        }
        {
            const int lr = w * 16 + rA;
#pragma unroll
            for (int n = 0; n < 8; n++) {
                const int col = n * 8 + (lane & 3) * 2;
                if (Ms[lr * 64 + col])           s[n][0] = -1e18f;
                if (Ms[lr * 64 + col + 1])       s[n][1] = -1e18f;
                if (Ms[(lr + 8) * 64 + col])     s[n][2] = -1e18f;
                if (Ms[(lr + 8) * 64 + col + 1]) s[n][3] = -1e18f;
            }
        }

        float tmA = -1e30f, tmB = -1e30f;
#pragma unroll
        for (int n = 0; n < 8; n++) {
            tmA = fmaxf(tmA, fmaxf(s[n][0], s[n][1]));
            tmB = fmaxf(tmB, fmaxf(s[n][2], s[n][3]));
        }
        tmA = fmaxf(tmA, __shfl_xor_sync(0xffffffffu, tmA, 1));
        tmA = fmaxf(tmA, __shfl_xor_sync(0xffffffffu, tmA, 2));
        tmB = fmaxf(tmB, __shfl_xor_sync(0xffffffffu, tmB, 1));
        tmB = fmaxf(tmB, __shfl_xor_sync(0xffffffffu, tmB, 2));
        const float mAn = fmaxf(mA, tmA), mBn = fmaxf(mB, tmB);
        const float fAc = __expf(mA - mAn), fBc = __expf(mB - mBn);
        float sumA = 0.f, sumB = 0.f;
        uint32_t pf[4][4];
#pragma unroll
        for (int n = 0; n < 8; n++) {
            float p0 = __expf(s[n][0] - mAn), p1 = __expf(s[n][1] - mAn);
            float p2 = __expf(s[n][2] - mBn), p3 = __expf(s[n][3] - mBn);
            sumA += p0 + p1; sumB += p2 + p3;
            pf[n >> 1][(n & 1) * 2]     = packh2(p0, p1);
            pf[n >> 1][(n & 1) * 2 + 1] = packh2(p2, p3);
        }
        sumA += __shfl_xor_sync(0xffffffffu, sumA, 1);
        sumA += __shfl_xor_sync(0xffffffffu, sumA, 2);
        sumB += __shfl_xor_sync(0xffffffffu, sumB, 1);
        sumB += __shfl_xor_sync(0xffffffffu, sumB, 2);
        lA = lA * fAc + sumA;
        lB = lB * fBc + sumB;
#pragma unroll
        for (int n = 0; n < 4; n++) {
            o[n][0] *= fAc; o[n][1] *= fAc; o[n][2] *= fBc; o[n][3] *= fBc;
        }
        mA = mAn; mB = mBn;

#pragma unroll
        for (int kfi = 0; kfi < 4; kfi++) {
#pragma unroll
            for (int jj = 0; jj < 2; jj++) {
                uint32_t bv[4];
                ldmx4(bv, sV + vOff + jj * (16 * 144) + kfi * 32);
                mma16816(o[jj * 2],     pf[kfi], bv[0], bv[1]);
                mma16816(o[jj * 2 + 1], pf[kfi], bv[2], bv[3]);
            }
        }
    }

    const float iA = 1.f / lA, iB = 1.f / lB;
#pragma unroll
    for (int n = 0; n < 4; n++) {
        const int col = h * 64 + n * 8 + (lane & 3) * 2;
        *(uint32_t*)(ctx + qrow0 * DD + col) = packh2(o[n][0] * iA, o[n][1] * iA);
        *(uint32_t*)(ctx + (qrow0 + 8) * DD + col) = packh2(o[n][2] * iB, o[n][3] * iB);
    }
}

// ---------------- eu: one block per (b,i); 256 threads, 2 rows in flight ----------------
__global__ __launch_bounds__(256) void eu_kernel(
    const float* __restrict__ PQ,
    const int* __restrict__ pair_j,
    __half* __restrict__ eu)
{
    const int bi = blockIdx.x;
    const int b = bi >> 9;
    const int t = threadIdx.x;
    const int half = t >> 7;
    const int tc = t & 127;

    __shared__ int js[16];
    if (t < 16) js[t] = pair_j[bi * 16 + t];

    const float4 p = *(const float4*)(PQ + (size_t)bi * 1024 + tc * 4);
    __syncthreads();

#pragma unroll
    for (int dd = 0; dd < 8; dd += 2) {
        const int d0 = half * 8 + dd, d1 = d0 + 1;
        const int j0 = js[d0], j1 = js[d1];
        float4 c0 = *(const float4*)(PQ + ((size_t)(b * NN + j0)) * 1024 + 512 + tc * 4);
        float4 c1 = *(const float4*)(PQ + ((size_t)(b * NN + j1)) * 1024 + 512 + tc * 4);
        uint2 u0, u1;
        u0.x = packh2(softplusf(p.x + c0.x) - LOG2F_, softplusf(p.y + c0.y) - LOG2F_);
        u0.y = packh2(softplusf(p.z + c0.z) - LOG2F_, softplusf(p.w + c0.w) - LOG2F_);
        u1.x = packh2(softplusf(p.x + c1.x) - LOG2F_, softplusf(p.y + c1.y) - LOG2F_);
        u1.y = packh2(softplusf(p.z + c1.z) - LOG2F_, softplusf(p.w + c1.w) - LOG2F_);
        *(uint2*)(eu + ((size_t)(bi * 16 + d0)) * DD + tc * 4) = u0;
        *(uint2*)(eu + ((size_t)(bi * 16 + d1)) * DD + tc * 4) = u1;
    }
}

// ---------------- launch (fork-join on two streams) ----------------
extern "C" void kernel_launch(void* const* d_in, const int* in_sizes, int n_in,
                              void* d_out, int out_size)
{
    const float* key    = (const float*)d_in[0];
    const float* value  = (const float*)d_in[1];
    const float* query  = (const float*)d_in[2];
    const unsigned char* mask = (const unsigned char*)d_in[3];
    const float* edgef  = (const float*)d_in[4];
    const int* pair_b   = (const int*)d_in[5];
    const int* pair_i   = (const int*)d_in[6];
    const int* pair_j   = (const int*)d_in[7];
    const float* Wq = (const float*)d_in[8],  *bq = (const float*)d_in[9];
    const float* Wk = (const float*)d_in[10], *bk = (const float*)d_in[11];
    const float* Wv = (const float*)d_in[12], *bv = (const float*)d_in[13];
    const float* Wo = (const float*)d_in[14], *bo = (const float*)d_in[15];
    const float* We1 = (const float*)d_in[16], *be1 = (const float*)d_in[17];
    const float* We2 = (const float*)d_in[18], *be2 = (const float*)d_in[19];
    const float* Wu1 = (const float*)d_in[20], *bu1 = (const float*)d_in[21];
    const float* Wu2 = (const float*)d_in[22], *bu2 = (const float*)d_in[23];

    float* out  = (float*)d_out;
    float* top  = out + 2097152;
    float* eupd = out + 4194304;

    float *q_, *k_, *v_, *PQ_, *ef_, *biasPQ_, *bPQ_;
    __half *f1_, *eu_, *xK_, *xQ_, *xV_, *xC_, *WHi_, *WPQ_;
    cudaGetSymbolAddress((void**)&q_, g_q);
    cudaGetSymbolAddress((void**)&k_, g_k);
    cudaGetSymbolAddress((void**)&v_, g_v);
    cudaGetSymbolAddress((void**)&PQ_, g_PQ);
    cudaGetSymbolAddress((void**)&ef_, g_ef);
    cudaGetSymbolAddress((void**)&f1_, g_f1);
    cudaGetSymbolAddress((void**)&eu_, g_eu);
    cudaGetSymbolAddress((void**)&xK_, g_xK);
    cudaGetSymbolAddress((void**)&xQ_, g_xQ);
    cudaGetSymbolAddress((void**)&xV_, g_xV);
    cudaGetSymbolAddress((void**)&xC_, g_xC);
    cudaGetSymbolAddress((void**)&WHi_, g_WHi);
    cudaGetSymbolAddress((void**)&WPQ_, g_WPQ);
    cudaGetSymbolAddress((void**)&biasPQ_, g_biasPQ);
    cudaGetSymbolAddress((void**)&bPQ_, g_bPQ);

    cudaFuncSetAttribute((const void*)tc_gemm<0, 0>,
                         cudaFuncAttributeMaxDynamicSharedMemorySize, TC_SMEM);
    cudaFuncSetAttribute((const void*)tc_gemm<0, 1>,
                         cudaFuncAttributeMaxDynamicSharedMemorySize, TC_SMEM);
    cudaFuncSetAttribute((const void*)tc_gemm_qkv,
                         cudaFuncAttributeMaxDynamicSharedMemorySize, TC_SMEM);
    cudaFuncSetAttribute((const void*)tc_gemm_f32a,
                         cudaFuncAttributeMaxDynamicSharedMemorySize, AF_SMEM);

    const int WSZ = 262144;

    cudaStream_t s2;
    cudaStreamCreateWithFlags(&s2, cudaStreamNonBlocking);
    cudaEvent_t eW, eQKV, eL, eG, eP;
    cudaEventCreateWithFlags(&eW, cudaEventDisableTiming);
    cudaEventCreateWithFlags(&eQKV, cudaEventDisableTiming);
    cudaEventCreateWithFlags(&eL, cudaEventDisableTiming);
    cudaEventCreateWithFlags(&eG, cudaEventDisableTiming);
    cudaEventCreateWithFlags(&eP, cudaEventDisableTiming);

    // s0: weight prep, then fork
    wsplit_all_t<<<545, 256>>>(Wk, Wq, Wv, Wo, Wu1, Wu2, We1, We2, bu1,
                               WHi_, biasPQ_);
    cudaEventRecord(eW, 0);

    // s2 (edge chain): MLP1 (fused f32 A) -> MLP2 -> ef
    cudaStreamWaitEvent(s2, eW, 0);
    tc_gemm_f32a<<<dim3(4, 512), 256, AF_SMEM, s2>>>(edgef, WHi_ + 7 * WSZ, be1, f1_, 512);
    tc_gemm<0, 0><<<dim3(2, 512), 256, TC_SMEM, s2>>>(f1_, WHi_ + 8 * WSZ,
                                                      be2, ef_, nullptr, 256);

    // s0: fused PQ weight W'^T = Wu1^T @ Wo (+ fused bias), then node chain
    bfuse<<<1024, 128>>>(bo, WHi_ + 4 * WSZ, biasPQ_, bPQ_);
    tc_gemm<0, 1><<<dim3(4, 8), 256, TC_SMEM>>>(WHi_ + 4 * WSZ, WHi_ + 9 * WSZ,
                                                nullptr, nullptr, WPQ_, 512);
    conv3_f16<<<1536, 256>>>(key, query, value, xK_, xQ_, xV_);
    tc_gemm_qkv<<<dim3(4, 32, 3), 256, TC_SMEM>>>(xK_, xQ_, xV_,
                                                  WHi_ + 0 * WSZ, WHi_ + 1 * WSZ, WHi_ + 2 * WSZ,
                                                  bk, bq, bv, k_, q_, v_);
    cudaEventRecord(eQKV, 0);

    // s2: local attention (needs ef + qkv)
    cudaStreamWaitEvent(s2, eQKV, 0);
    local_attn<<<ROWS, 256, 0, s2>>>(q_, k_, v_, ef_, pair_j, xC_);
    cudaEventRecord(eL, s2);

    // s0: global attention (disjoint ctx columns)
    global_attn_tc<<<dim3(8, 8, 8), 128>>>(q_, k_, v_, mask, xC_, top);
    cudaEventRecord(eG, 0);

    // s2: PQ = ctx @ W' + b'  (full ctx: eL in-stream on s2, wait eG) — runs concurrent with Wo
    cudaStreamWaitEvent(s2, eG, 0);
    tc_gemm<0, 0><<<dim3(8, 32), 256, TC_SMEM, s2>>>(xC_, WPQ_, bPQ_, PQ_, nullptr, 1024);
    cudaEventRecord(eP, s2);

    // s0: output projection (full ctx: eG in-stream on s0, wait eL)
    cudaStreamWaitEvent(0, eL, 0);
    tc_gemm<0, 0><<<dim3(4, 32), 256, TC_SMEM>>>(xC_, WHi_ + 3 * WSZ,
                                                 bo, out, nullptr, 512);

    // s0: eu (needs PQ), then Wu2 — serial as in R12
    cudaStreamWaitEvent(0, eP, 0);
    eu_kernel<<<ROWS, 256>>>(PQ_, pair_j, eu_);
    tc_gemm<0, 0><<<dim3(4, 512), 256, TC_SMEM>>>(eu_, WHi_ + 6 * WSZ,
                                                  bu2, eupd, nullptr, 512);

    cudaEventDestroy(eW);
    cudaEventDestroy(eQKV);
    cudaEventDestroy(eL);
    cudaEventDestroy(eG);
    cudaEventDestroy(eP);
    cudaStreamDestroy(s2);
}

// round 16
// speedup vs baseline: 1.1145x; 1.0559x over previous
#include <cuda_runtime.h>
#include <cuda_bf16.h>
#include <cuda_fp16.h>
#include <math.h>
#include <stdint.h>

// Problem constants
#define BB 8
#define NN 512
#define DD 512
#define DEG_ 16
#define EE 65536   // B*N*DEG
#define ROWS 4096  // B*N
#define GK 512     // K dim of all big GEMMs
#define SCALE 0.17677669529663687f  // 1/sqrt(32)
#define LOG2F_ 0.6931471805599453f

// ---------------- scratch (device globals; no allocs allowed) ----------------
__device__ float g_q[ROWS * DD];
__device__ float g_k[ROWS * DD];
__device__ float g_v[ROWS * DD];
__device__ float g_PQ[ROWS * 1024];
__device__ float g_ef[(size_t)EE * 256];

__device__ __half g_f1[(size_t)EE * DD];
__device__ __half g_eu[(size_t)EE * DD];
__device__ __half g_xK[ROWS * DD];
__device__ __half g_xQ[ROWS * DD];
__device__ __half g_xV[ROWS * DD];
__device__ __half g_xC[ROWS * DD];   // ctx in fp16
__device__ __half g_o[ROWS * DD];    // Wo output fp16 for PQ

// weights fp16: 0 WkT,1 WqT,2 WvT,3 WoT,4 Wu1T(1024x512),6 Wu2T,7 We1T,8 We2T(256x512)
__device__ __half g_WHi[9 * 262144];
__device__ float g_biasPQ[1024];

__device__ __forceinline__ float softplusf(float x) {
    return fmaxf(x, 0.f) + log1pf(expf(-fabsf(x)));
}

__device__ __forceinline__ uint32_t smem_to_u32(const void* smem_ptr) {
    uint32_t addr;
    asm("{ .reg .u64 tmp; cvta.to.shared.u64 tmp, %1; cvt.u32.u64 %0, tmp; }"
        : "=r"(addr) : "l"(smem_ptr));
    return addr;
}

// ---------------- PTX: cp.async / ldmatrix / mma (base-arch legal) ----------------
__device__ __forceinline__ void cpasync16(uint32_t saddr, const void* g) {
    asm volatile("cp.async.cg.shared.global [%0], [%1], 16;" :: "r"(saddr), "l"(g));
}
#define CP_COMMIT() asm volatile("cp.async.commit_group;")
#define CP_WAIT(n)  asm volatile("cp.async.wait_group %0;" :: "n"(n))

__device__ __forceinline__ void ldmx4(uint32_t r[4], uint32_t addr) {
    asm volatile("ldmatrix.sync.aligned.m8n8.x4.shared.b16 {%0,%1,%2,%3}, [%4];"
                 : "=r"(r[0]), "=r"(r[1]), "=r"(r[2]), "=r"(r[3]) : "r"(addr));
}

__device__ __forceinline__ void mma16816(float c[4], const uint32_t a[4],
                                         uint32_t b0, uint32_t b1) {
    asm volatile("mma.sync.aligned.m16n8k16.row.col.f32.f16.f16.f32 "
                 "{%0,%1,%2,%3}, {%4,%5,%6,%7}, {%8,%9}, {%0,%1,%2,%3};"
                 : "+f"(c[0]), "+f"(c[1]), "+f"(c[2]), "+f"(c[3])
                 : "r"(a[0]), "r"(a[1]), "r"(a[2]), "r"(a[3]), "r"(b0), "r"(b1));
}

__device__ __forceinline__ uint32_t packh2(float x, float y) {
    __half2 h = __floats2half2_rn(x, y);
    return *(uint32_t*)&h;
}

// ======================= tensor-core GEMM core (mma.sync fp16) ===============
#define ROWB 80
#define TILE_B (128 * ROWB)      // 10240
#define A_OFF 0
#define B_OFF (1 * TILE_B)
#define STAGE_B (2 * TILE_B)     // 20480
#define NSTAGE 4
#define TC_SMEM (NSTAGE * STAGE_B)  // 81920

// OUT: 0 = f32 only, 1 = fp16 only, 2 = f32 + fp16
template <int SOFTPLUS, int OUT>
__device__ __forceinline__ void tc_gemm_core(
    char* smem,
    const __half* __restrict__ A, const __half* __restrict__ B,
    const float* __restrict__ bias,
    float* __restrict__ Cf, __half* __restrict__ Ch,
    int N, int bm, int bn)
{
    const uint32_t sb = smem_to_u32(smem);
    const int t = threadIdx.x, lane = t & 31, w = t >> 5;
    const int wm = w & 3, wn = w >> 2;
    constexpr int KT = GK / 32;   // 16

    float acc[2][8][4] = {};

    const __half* pA[2];
    const __half* pB[2];
    uint32_t so[2];
#pragma unroll
    for (int i = 0; i < 2; i++) {
        const int id = t + i * 256;
        const int row = id >> 2, ch = id & 3;
        so[i] = row * ROWB + ch * 16;
        pA[i] = A + (size_t)(bm + row) * GK + ch * 8;
        pB[i] = B + (size_t)(bn + row) * GK + ch * 8;
    }

    auto issue = [&](int kcI, uint32_t stbase) {
#pragma unroll
        for (int i = 0; i < 2; i++) {
            cpasync16(stbase + A_OFF + so[i], pA[i] + kcI * 32);
            cpasync16(stbase + B_OFF + so[i], pB[i] + kcI * 32);
        }
    };

    const uint32_t aRow = (uint32_t)(wm * 32 + (lane & 15)) * ROWB + ((lane >> 4) << 4);
    const int n_off = (lane & 7) + ((lane >> 4) << 3);
    const int k_half = (lane >> 3) & 1;
    const uint32_t bRow = (uint32_t)(wn * 64 + n_off) * ROWB + (k_half << 4);

    issue(0, sb);               CP_COMMIT();
    issue(1, sb + STAGE_B);     CP_COMMIT();
    issue(2, sb + 2 * STAGE_B); CP_COMMIT();

#pragma unroll
    for (int kc = 0; kc < KT; kc++) {
        if (kc + 2 < KT)      { CP_WAIT(2); }
        else if (kc + 1 < KT) { CP_WAIT(1); }
        else                  { CP_WAIT(0); }
        __syncthreads();
        if (kc + 3 < KT) {
            issue(kc + 3, sb + ((kc + 3) & 3) * STAGE_B);
            CP_COMMIT();
        }
        const uint32_t cur = sb + (kc & 3) * STAGE_B;

#pragma unroll
        for (int ks = 0; ks < 2; ks++) {
            const uint32_t kb = ks * 32;
            uint32_t a[2][4], bh[4][4];
            ldmx4(a[0], cur + A_OFF + aRow + kb);
            ldmx4(a[1], cur + A_OFF + aRow + 16 * ROWB + kb);
#pragma unroll
            for (int jj = 0; jj < 4; jj++)
                ldmx4(bh[jj], cur + B_OFF + bRow + jj * 16 * ROWB + kb);
#pragma unroll
            for (int g = 0; g < 2; g++) {
#pragma unroll
                for (int j = 0; j < 8; j++) {
                    const int jj = j >> 1, hf = (j & 1) * 2;
                    mma16816(acc[g][j], a[g], bh[jj][hf], bh[jj][hf + 1]);
                }
            }
        }
    }

    float bcol[16];
    {
        const int col0 = bn + wn * 64 + (lane & 3) * 2;
#pragma unroll
        for (int j = 0; j < 8; j++) {
            bcol[j * 2]     = bias ? bias[col0 + j * 8]     : 0.f;
            bcol[j * 2 + 1] = bias ? bias[col0 + j * 8 + 1] : 0.f;
        }
    }
#pragma unroll
    for (int g = 0; g < 2; g++) {
#pragma unroll
        for (int j = 0; j < 8; j++) {
            const int row = bm + wm * 32 + g * 16 + (lane >> 2);
            const int col = bn + wn * 64 + j * 8 + (lane & 3) * 2;
            float v0 = acc[g][j][0] + bcol[j * 2], v1 = acc[g][j][1] + bcol[j * 2 + 1];
            float v2 = acc[g][j][2] + bcol[j * 2], v3 = acc[g][j][3] + bcol[j * 2 + 1];
            if (SOFTPLUS) {
                v0 = softplusf(v0) - LOG2F_; v1 = softplusf(v1) - LOG2F_;
                v2 = softplusf(v2) - LOG2F_; v3 = softplusf(v3) - LOG2F_;
            }
            if (OUT == 0 || OUT == 2) {
                *(float2*)(Cf + (size_t)row * N + col) = make_float2(v0, v1);
                *(float2*)(Cf + (size_t)(row + 8) * N + col) = make_float2(v2, v3);
            }
            if (OUT == 1 || OUT == 2) {
                *(uint32_t*)(Ch + (size_t)row * N + col) = packh2(v0, v1);
                *(uint32_t*)(Ch + (size_t)(row + 8) * N + col) = packh2(v2, v3);
            }
        }
    }
}

// bm0: row offset for half-grid launches
template <int SOFTPLUS, int OUT>
__global__ __launch_bounds__(256, 2) void tc_gemm(
    const __half* __restrict__ A, const __half* __restrict__ B,
    const float* __restrict__ bias,
    float* __restrict__ Cf, __half* __restrict__ Ch,
    int N, int bm0)
{
    extern __shared__ char smem[];
    tc_gemm_core<SOFTPLUS, OUT>(smem, A, B, bias, Cf, Ch, N,
                                bm0 + blockIdx.y * 128, blockIdx.x * 128);
}

// batched K/Q/V projection: blockIdx.z selects the triple
__global__ __launch_bounds__(256, 2) void tc_gemm_qkv(
    const __half* __restrict__ xK, const __half* __restrict__ xQ, const __half* __restrict__ xV,
    const __half* __restrict__ WkT, const __half* __restrict__ WqT, const __half* __restrict__ WvT,
    const float* __restrict__ bk, const float* __restrict__ bq, const float* __restrict__ bv,
    float* __restrict__ k_, float* __restrict__ q_, float* __restrict__ v_)
{
    extern __shared__ char smem[];
    const int z = blockIdx.z;
    const __half* A = (z == 0) ? xK : (z == 1) ? xQ : xV;
    const __half* B = (z == 0) ? WkT : (z == 1) ? WqT : WvT;
    const float* bias = (z == 0) ? bk : (z == 1) ? bq : bv;
    float* C = (z == 0) ? k_ : (z == 1) ? q_ : v_;
    tc_gemm_core<0, 0>(smem, A, B, bias, C, nullptr, 512,
                       blockIdx.y * 128, blockIdx.x * 128);
}

// ======================= MLP1 GEMM with fused f32->fp16 A conversion =======================
#define AF_A32 0
#define AF_B   18432
#define AF_STAGE (18432 + 10240) // 28672
#define AF_F16 (3 * AF_STAGE)    // 86016
#define AF_SMEM (AF_F16 + 10240) // 96256

__global__ __launch_bounds__(256, 2) void tc_gemm_f32a(
    const float* __restrict__ A, const __half* __restrict__ B,
    const float* __restrict__ bias, __half* __restrict__ Ch, int N, int bm0)
{
    extern __shared__ char smem[];
    const uint32_t sb = smem_to_u32(smem);
    const int t = threadIdx.x, lane = t & 31, w = t >> 5;
    const int wm = w & 3, wn = w >> 2;
    const int bm = bm0 + blockIdx.y * 128, bn = blockIdx.x * 128;
    constexpr int KT = GK / 32;   // 16

    float acc[2][8][4] = {};

    const float* pA[4];
    uint32_t soA[4];
#pragma unroll
    for (int i = 0; i < 4; i++) {
        const int id = t + i * 256;
        const int row = id >> 3, ch = id & 7;
        soA[i] = row * 144 + ch * 16;
        pA[i] = A + (size_t)(bm + row) * GK + ch * 4;
    }
    const __half* pB[2];
    uint32_t soB[2];
#pragma unroll
    for (int i = 0; i < 2; i++) {
        const int id = t + i * 256;
        const int row = id >> 2, ch = id & 3;
        soB[i] = row * ROWB + ch * 16;
        pB[i] = B + (size_t)(bn + row) * GK + ch * 8;
    }

    auto issue = [&](int kcI, uint32_t st) {
#pragma unroll
        for (int i = 0; i < 4; i++) cpasync16(st + AF_A32 + soA[i], pA[i] + kcI * 32);
#pragma unroll
        for (int i = 0; i < 2; i++) cpasync16(st + AF_B + soB[i], pB[i] + kcI * 32);
    };

    const uint32_t aRow = (uint32_t)(wm * 32 + (lane & 15)) * ROWB + ((lane >> 4) << 4);
    const int n_off = (lane & 7) + ((lane >> 4) << 3);
    const int k_half = (lane >> 3) & 1;
    const uint32_t bRow = (uint32_t)(wn * 64 + n_off) * ROWB + (k_half << 4);
    const uint32_t sF = sb + AF_F16;

    const int cr = t >> 1, chf = t & 1;
    const uint32_t cvtSrc = cr * 144 + chf * 64;
    char* const cvtDstP = smem + AF_F16 + cr * ROWB + chf * 32;

    issue(0, sb);            CP_COMMIT();
    issue(1, sb + AF_STAGE); CP_COMMIT();

#pragma unroll
    for (int kc = 0; kc < KT; kc++) {
        if (kc + 1 < KT) { CP_WAIT(1); } else { CP_WAIT(0); }
        __syncthreads();
        const int st = kc % 3;
        const uint32_t cur = sb + st * AF_STAGE;
        if (kc + 2 < KT) {
            issue(kc + 2, sb + ((kc + 2) % 3) * AF_STAGE);
            CP_COMMIT();
        }
        {
            const char* srcp = smem + st * AF_STAGE + cvtSrc;
            float4 f0 = *(const float4*)(srcp);
            float4 f1v = *(const float4*)(srcp + 16);
            float4 f2 = *(const float4*)(srcp + 32);
            float4 f3 = *(const float4*)(srcp + 48);
            uint4 u0, u1;
            u0.x = packh2(f0.x, f0.y);  u0.y = packh2(f0.z, f0.w);
            u0.z = packh2(f1v.x, f1v.y); u0.w = packh2(f1v.z, f1v.w);
            u1.x = packh2(f2.x, f2.y);  u1.y = packh2(f2.z, f2.w);
            u1.z = packh2(f3.x, f3.y);  u1.w = packh2(f3.z, f3.w);
            *(uint4*)(cvtDstP)      = u0;
            *(uint4*)(cvtDstP + 16) = u1;
        }
        __syncthreads();

#pragma unroll
        for (int ks = 0; ks < 2; ks++) {
            const uint32_t kb = ks * 32;
            uint32_t a[2][4], bh[4][4];
            ldmx4(a[0], sF + aRow + kb);
            ldmx4(a[1], sF + aRow + 16 * ROWB + kb);
#pragma unroll
            for (int jj = 0; jj < 4; jj++)
                ldmx4(bh[jj], cur + AF_B + bRow + jj * 16 * ROWB + kb);
#pragma unroll
            for (int g = 0; g < 2; g++) {
#pragma unroll
                for (int j = 0; j < 8; j++) {
                    const int jj = j >> 1, hf = (j & 1) * 2;
                    mma16816(acc[g][j], a[g], bh[jj][hf], bh[jj][hf + 1]);
                }
            }
        }
    }

    float bcol[16];
    {
        const int col0 = bn + wn * 64 + (lane & 3) * 2;
#pragma unroll
        for (int j = 0; j < 8; j++) {
            bcol[j * 2]     = bias[col0 + j * 8];
            bcol[j * 2 + 1] = bias[col0 + j * 8 + 1];
        }
    }
#pragma unroll
    for (int g = 0; g < 2; g++) {
#pragma unroll
        for (int j = 0; j < 8; j++) {
            const int row = bm + wm * 32 + g * 16 + (lane >> 2);
            const int col = bn + wn * 64 + j * 8 + (lane & 3) * 2;
            float v0 = softplusf(acc[g][j][0] + bcol[j * 2]) - LOG2F_;
            float v1 = softplusf(acc[g][j][1] + bcol[j * 2 + 1]) - LOG2F_;
            float v2 = softplusf(acc[g][j][2] + bcol[j * 2]) - LOG2F_;
            float v3 = softplusf(acc[g][j][3] + bcol[j * 2 + 1]) - LOG2F_;
            *(uint32_t*)(Ch + (size_t)row * N + col) = packh2(v0, v1);
            *(uint32_t*)(Ch + (size_t)(row + 8) * N + col) = packh2(v2, v3);
        }
    }
}

// key/query/value conversions in one launch, ILP4.
__global__ __launch_bounds__(256) void conv3_f16(
    const float* __restrict__ k, const float* __restrict__ q, const float* __restrict__ v,
    __half* __restrict__ xk, __half* __restrict__ xq, __half* __restrict__ xv)
{
    const int seg = blockIdx.x >> 9;
    const size_t base = (size_t)(blockIdx.x & 511) * 1024 + threadIdx.x;
    const float* x = (seg == 0) ? k : (seg == 1) ? q : v;
    __half* y = (seg == 0) ? xk : (seg == 1) ? xq : xv;
    float4 val[4];
#pragma unroll
    for (int kk = 0; kk < 4; kk++) val[kk] = ((const float4*)x)[base + kk * 256];
#pragma unroll
    for (int kk = 0; kk < 4; kk++) {
        uint2 u;
        u.x = packh2(val[kk].x, val[kk].y);
        u.y = packh2(val[kk].z, val[kk].w);
        *(uint2*)(y + (base + kk * 256) * 4) = u;
    }
}

// ---------------- weights: coalesced SMEM-tile transpose + fp16 ----------------
__global__ __launch_bounds__(256) void wsplit_all_t(
    const float* __restrict__ Wk, const float* __restrict__ Wq, const float* __restrict__ Wv,
    const float* __restrict__ Wo, const float* __restrict__ Wu1, const float* __restrict__ Wu2,
    const float* __restrict__ We1, const float* __restrict__ We2,
    const float* __restrict__ bu1,
    __half* __restrict__ WHi, float* __restrict__ biasPQ)
{
    __shared__ float S[64][68];
    const int bid = blockIdx.x, t = threadIdx.x;

    if (bid == 544) {
#pragma unroll
        for (int it = 0; it < 4; it++) {
            const int i = it * 256 + t;
            biasPQ[i] = (i < 512) ? bu1[i] : 0.f;
        }
        return;
    }

    const float* src;
    int segOut, Ndim, tk, tn;
    if (bid < 512) {
        const int seg = bid >> 6;
        switch (seg) {
            case 0: src = Wk; break;
            case 1: src = Wq; break;
            case 2: src = Wv; break;
            case 3: src = Wo; break;
            case 4: src = Wu1; break;
            case 5: src = Wu1 + 262144; break;
            case 6: src = Wu2; break;
            default: src = We1; break;
        }
        segOut = seg; Ndim = 512;
        const int tile = bid & 63;
        tk = tile >> 3; tn = tile & 7;
    } else {
        src = We2; segOut = 8; Ndim = 256;
        const int tile = bid - 512;
        tk = tile >> 2; tn = tile & 3;
    }

    {
        const int c4 = (t & 15) * 4;
#pragma unroll
        for (int it = 0; it < 4; it++) {
            const int r = it * 16 + (t >> 4);
            float4 v = *(const float4*)(src + (size_t)(tk * 64 + r) * Ndim + tn * 64 + c4);
            S[r][c4] = v.x; S[r][c4 + 1] = v.y; S[r][c4 + 2] = v.z; S[r][c4 + 3] = v.w;
        }
    }
    __syncthreads();

    {
        __half* dst = WHi + (size_t)segOut * 262144;
        const int kg = (t & 15) * 4;
#pragma unroll
        for (int it = 0; it < 4; it++) {
            const int n = it * 16 + (t >> 4);
            uint2 u;
            u.x = packh2(S[kg][n], S[kg + 1][n]);
            u.y = packh2(S[kg + 2][n], S[kg + 3][n]);
            *(uint2*)(dst + (size_t)(tn * 64 + n) * 512 + tk * 64 + kg) = u;
        }
    }
}

// ---------------- local attention: one block per (b,i), ctx written fp16 ----------------
__global__ __launch_bounds__(256) void local_attn(
    const float* __restrict__ q, const float* __restrict__ k,
    const float* __restrict__ v, const float* __restrict__ ef,
    const int* __restrict__ pair_j, __half* __restrict__ ctx)
{
    const int bi = blockIdx.x;
    const int b = bi >> 9;
    const int t = threadIdx.x;

    __shared__ float qs[256];
    __shared__ int js[16];
    __shared__ float sc[16][8];
    __shared__ float wgt[16][8];

    if (t < 16) js[t] = pair_j[bi * 16 + t];
    qs[t] = q[(size_t)bi * DD + 256 + t];
    __syncthreads();

    if (t < 128) {
        const int d = t >> 3, h = t & 7;
        const int j = js[d];
        const float* kr = k + ((size_t)(b * NN + j)) * DD + 256 + h * 32;
        const float* er = ef + ((size_t)(bi * 16 + d)) * 256 + h * 32;
        const float* qr = qs + h * 32;
        float s = 0.f;
#pragma unroll
        for (int c4 = 0; c4 < 8; c4++) {
            float4 kk = *(const float4*)(kr + c4 * 4);
            float4 eee = *(const float4*)(er + c4 * 4);
            s = fmaf(qr[c4 * 4 + 0], kk.x * eee.x, s);
            s = fmaf(qr[c4 * 4 + 1], kk.y * eee.y, s);
            s = fmaf(qr[c4 * 4 + 2], kk.z * eee.z, s);
            s = fmaf(qr[c4 * 4 + 3], kk.w * eee.w, s);
        }
        sc[d][h] = s * SCALE;
    }
    __syncthreads();

    if (t < 8) {
        const int h = t;
        float m = -1e30f;
#pragma unroll
        for (int d = 0; d < 16; d++) {
            float s = sc[d][h];
            if (s > -10000.f && s > m) m = s;
        }
        float sum = 0.f;
#pragma unroll
        for (int d = 0; d < 16; d++) {
            float s = sc[d][h];
            float e = (s > -10000.f) ? expf(s - m) : 0.f;
            wgt[d][h] = e;
            sum += e;
        }
        float inv = (sum > 0.f) ? 1.f / sum : 0.f;
#pragma unroll
        for (int d = 0; d < 16; d++) wgt[d][h] *= inv;
    }
    __syncthreads();

    const int h = t >> 5, c = t & 31;
    float o = 0.f;
#pragma unroll
    for (int d = 0; d < 16; d++) {
        float w = wgt[d][h];
        o = fmaf(w, v[((size_t)(b * NN + js[d])) * DD + 256 + h * 32 + c], o);
    }
    ctx[(size_t)bi * DD + h * 64 + 32 + c] = __float2half_rn(o);
}

// ========== global attention: tensor-core flash kernel ==========
__global__ __launch_bounds__(128) void global_attn_tc(
    const float* __restrict__ qf, const float* __restrict__ kf,
    const float* __restrict__ vf, const unsigned char* __restrict__ mask,
    __half* __restrict__ ctx, float* __restrict__ top)
{
    const int qt = blockIdx.x, h = blockIdx.y, b = blockIdx.z;
    const int t = threadIdx.x, lane = t & 31, w = t >> 5;

    __shared__ __half Qhi[64 * 40], Qlo[64 * 40];
    __shared__ __half Khi[64 * 40], Klo[64 * 40];
    __shared__ __half Vt[32 * 72];
    __shared__ unsigned char Ms[64 * 64];

    const uint32_t sQh = smem_to_u32(Qhi), sQl = smem_to_u32(Qlo);
    const uint32_t sKh = smem_to_u32(Khi), sKl = smem_to_u32(Klo);
    const uint32_t sV = smem_to_u32(Vt);

#pragma unroll
    for (int i = 0; i < 4; i++) {
        const int id = t + i * 128;
        const int row = id >> 3, ch = id & 7;
        float4 v4 = *(const float4*)(qf + ((size_t)(b * NN) + qt * 64 + row) * DD + h * 32 + ch * 4);
        __half h0 = __float2half_rn(v4.x), h1 = __float2half_rn(v4.y);
        __half h2 = __float2half_rn(v4.z), h3 = __float2half_rn(v4.w);
        __half l0 = __float2half_rn(v4.x - __half2float(h0));
        __half l1 = __float2half_rn(v4.y - __half2float(h1));
        __half l2 = __float2half_rn(v4.z - __half2float(h2));
        __half l3 = __float2half_rn(v4.w - __half2float(h3));
        uint2 uh, ul;
        uh.x = ((uint32_t)__half_as_ushort(h1) << 16) | __half_as_ushort(h0);
        uh.y = ((uint32_t)__half_as_ushort(h3) << 16) | __half_as_ushort(h2);
        ul.x = ((uint32_t)__half_as_ushort(l1) << 16) | __half_as_ushort(l0);
        ul.y = ((uint32_t)__half_as_ushort(l3) << 16) | __half_as_ushort(l2);
        *(uint2*)&Qhi[row * 40 + ch * 4] = uh;
        *(uint2*)&Qlo[row * 40 + ch * 4] = ul;
    }

    const uint32_t aOff = (uint32_t)(w * 16 + (lane & 15)) * 80 + ((lane >> 4) << 4);
    const uint32_t bOffR = (uint32_t)((lane & 7) + ((lane >> 4) << 3));
    const uint32_t kOff = bOffR * 80 + (((lane >> 3) & 1) << 4);
    const uint32_t vOff = bOffR * 144 + (((lane >> 3) & 1) << 4);

    __syncthreads();
    uint32_t aHi[2][4], aLo[2][4];
    ldmx4(aHi[0], sQh + aOff);
    ldmx4(aHi[1], sQh + aOff + 32);
    ldmx4(aLo[0], sQl + aOff);
    ldmx4(aLo[1], sQl + aOff + 32);

    float o[4][4] = {};
    float mA = -1e30f, mB = -1e30f, lA = 0.f, lB = 0.f;
    const int rA = lane >> 2;
    const size_t qrow0 = (size_t)(b * NN) + qt * 64 + w * 16 + rA;

    for (int kt = 0; kt < 8; kt++) {
        __syncthreads();
#pragma unroll
        for (int i = 0; i < 4; i++) {
            const int id = t + i * 128;
            const int row = id >> 3, ch = id & 7;
            float4 v4 = *(const float4*)(kf + ((size_t)(b * NN) + kt * 64 + row) * DD + h * 32 + ch * 4);
            __half h0 = __float2half_rn(v4.x), h1 = __float2half_rn(v4.y);
            __half h2 = __float2half_rn(v4.z), h3 = __float2half_rn(v4.w);
            __half l0 = __float2half_rn(v4.x - __half2float(h0));
            __half l1 = __float2half_rn(v4.y - __half2float(h1));
            __half l2 = __float2half_rn(v4.z - __half2float(h2));
            __half l3 = __float2half_rn(v4.w - __half2float(h3));
            uint2 uh, ul;
            uh.x = ((uint32_t)__half_as_ushort(h1) << 16) | __half_as_ushort(h0);
            uh.y = ((uint32_t)__half_as_ushort(h3) << 16) | __half_as_ushort(h2);
            ul.x = ((uint32_t)__half_as_ushort(l1) << 16) | __half_as_ushort(l0);
            ul.y = ((uint32_t)__half_as_ushort(l3) << 16) | __half_as_ushort(l2);
            *(uint2*)&Khi[row * 40 + ch * 4] = uh;
            *(uint2*)&Klo[row * 40 + ch * 4] = ul;
        }
#pragma unroll
        for (int i = 0; i < 4; i++) {
            const int id = t + i * 128;
            const int key = id >> 3, dh = (id & 7) * 4;
            float4 v4 = *(const float4*)(vf + ((size_t)(b * NN) + kt * 64 + key) * DD + h * 32 + dh);
            Vt[(dh + 0) * 72 + key] = __float2half_rn(v4.x);
            Vt[(dh + 1) * 72 + key] = __float2half_rn(v4.y);
            Vt[(dh + 2) * 72 + key] = __float2half_rn(v4.z);
            Vt[(dh + 3) * 72 + key] = __float2half_rn(v4.w);
        }
#pragma unroll
        for (int i = 0; i < 2; i++) {
            const int id = t + i * 128;
            const int row = id >> 2, ch = id & 3;
            *(uint4*)&Ms[row * 64 + ch * 16] =
                *(const uint4*)(mask + ((size_t)(b * NN) + qt * 64 + row) * NN + kt * 64 + ch * 16);
        }
        __syncthreads();

        float s[8][4];
#pragma unroll
        for (int n = 0; n < 8; n++) { s[n][0] = s[n][1] = s[n][2] = s[n][3] = 0.f; }
#pragma unroll
        for (int ks = 0; ks < 2; ks++) {
#pragma unroll
            for (int jj = 0; jj < 4; jj++) {
                uint32_t bh[4], bl[4];
                ldmx4(bh, sKh + kOff + jj * (16 * 80) + ks * 32);
                ldmx4(bl, sKl + kOff + jj * (16 * 80) + ks * 32);
                mma16816(s[jj * 2],     aHi[ks], bh[0], bh[1]);
                mma16816(s[jj * 2 + 1], aHi[ks], bh[2], bh[3]);
                mma16816(s[jj * 2],     aHi[ks], bl[0], bl[1]);
                mma16816(s[jj * 2 + 1], aHi[ks], bl[2], bl[3]);
                mma16816(s[jj * 2],     aLo[ks], bh[0], bh[1]);
                mma16816(s[jj * 2 + 1], aLo[ks], bh[2], bh[3]);
            }
        }
#pragma unroll
        for (int n = 0; n < 8; n++) {
            s[n][0] *= SCALE; s[n][1] *= SCALE; s[n][2] *= SCALE; s[n][3] *= SCALE;
        }

        if (h == 0) {
#pragma unroll
            for (int n = 0; n < 8; n++) {
                const int col = kt * 64 + n * 8 + (lane & 3) * 2;
                *(float2*)(top + qrow0 * NN + col) = make_float2(s[n][0], s[n][1]);
                *(float2*)(top + (qrow0 + 8) * NN + col) = make_float2(s[n][2], s[n][3]);
            }
        }
        {
            const int lr = w * 16 + rA;
#pragma unroll
            for (int n = 0; n < 8; n++) {
                const int col = n * 8 + (lane & 3) * 2;
                if (Ms[lr * 64 + col])           s[n][0] = -1e18f;
                if (Ms[lr * 64 + col + 1])       s[n][1] = -1e18f;
                if (Ms[(lr + 8) * 64 + col])     s[n][2] = -1e18f;
                if (Ms[(lr + 8) * 64 + col + 1]) s[n][3] = -1e18f;
            }
        }

        float tmA = -1e30f, tmB = -1e30f;
#pragma unroll
        for (int n = 0; n < 8; n++) {
            tmA = fmaxf(tmA, fmaxf(s[n][0], s[n][1]));
            tmB = fmaxf(tmB, fmaxf(s[n][2], s[n][3]));
        }
        tmA = fmaxf(tmA, __shfl_xor_sync(0xffffffffu, tmA, 1));
        tmA = fmaxf(tmA, __shfl_xor_sync(0xffffffffu, tmA, 2));
        tmB = fmaxf(tmB, __shfl_xor_sync(0xffffffffu, tmB, 1));
        tmB = fmaxf(tmB, __shfl_xor_sync(0xffffffffu, tmB, 2));
        const float mAn = fmaxf(mA, tmA), mBn = fmaxf(mB, tmB);
        const float fAc = __expf(mA - mAn), fBc = __expf(mB - mBn);
        float sumA = 0.f, sumB = 0.f;
        uint32_t pf[4][4];
#pragma unroll
        for (int n = 0; n < 8; n++) {
            float p0 = __expf(s[n][0] - mAn), p1 = __expf(s[n][1] - mAn);
            float p2 = __expf(s[n][2] - mBn), p3 = __expf(s[n][3] - mBn);
            sumA += p0 + p1; sumB += p2 + p3;
            pf[n >> 1][(n & 1) * 2]     = packh2(p0, p1);
            pf[n >> 1][(n & 1) * 2 + 1] = packh2(p2, p3);
        }
        sumA += __shfl_xor_sync(0xffffffffu, sumA, 1);
        sumA += __shfl_xor_sync(0xffffffffu, sumA, 2);
        sumB += __shfl_xor_sync(0xffffffffu, sumB, 1);
        sumB += __shfl_xor_sync(0xffffffffu, sumB, 2);
        lA = lA * fAc + sumA;
        lB = lB * fBc + sumB;
#pragma unroll
        for (int n = 0; n < 4; n++) {
            o[n][0] *= fAc; o[n][1] *= fAc; o[n][2] *= fBc; o[n][3] *= fBc;
        }
        mA = mAn; mB = mBn;

#pragma unroll
        for (int kfi = 0; kfi < 4; kfi++) {
#pragma unroll
            for (int jj = 0; jj < 2; jj++) {
                uint32_t bv[4];
                ldmx4(bv, sV + vOff + jj * (16 * 144) + kfi * 32);
                mma16816(o[jj * 2],     pf[kfi], bv[0], bv[1]);
                mma16816(o[jj * 2 + 1], pf[kfi], bv[2], bv[3]);
            }
        }
    }

    const float iA = 1.f / lA, iB = 1.f / lB;
#pragma unroll
    for (int n = 0; n < 4; n++) {
        const int col = h * 64 + n * 8 + (lane & 3) * 2;
        *(uint32_t*)(ctx + qrow0 * DD + col) = packh2(o[n][0] * iA, o[n][1] * iA);
        *(uint32_t*)(ctx + (qrow0 + 8) * DD + col) = packh2(o[n][2] * iB, o[n][3] * iB);
    }
}

// ---------------- eu: one block per (b,i); 256 threads, 2 rows in flight ----------------
__global__ __launch_bounds__(256) void eu_kernel(
    const float* __restrict__ PQ,
    const int* __restrict__ pair_j,
    __half* __restrict__ eu)
{
    const int bi = blockIdx.x;
    const int b = bi >> 9;
    const int t = threadIdx.x;
    const int half = t >> 7;
    const int tc = t & 127;

    __shared__ int js[16];
    if (t < 16) js[t] = pair_j[bi * 16 + t];

    const float4 p = *(const float4*)(PQ + (size_t)bi * 1024 + tc * 4);
    __syncthreads();

#pragma unroll
    for (int dd = 0; dd < 8; dd += 2) {
        const int d0 = half * 8 + dd, d1 = d0 + 1;
        const int j0 = js[d0], j1 = js[d1];
        float4 c0 = *(const float4*)(PQ + ((size_t)(b * NN + j0)) * 1024 + 512 + tc * 4);
        float4 c1 = *(const float4*)(PQ + ((size_t)(b * NN + j1)) * 1024 + 512 + tc * 4);
        uint2 u0, u1;
        u0.x = packh2(softplusf(p.x + c0.x) - LOG2F_, softplusf(p.y + c0.y) - LOG2F_);
        u0.y = packh2(softplusf(p.z + c0.z) - LOG2F_, softplusf(p.w + c0.w) - LOG2F_);
        u1.x = packh2(softplusf(p.x + c1.x) - LOG2F_, softplusf(p.y + c1.y) - LOG2F_);
        u1.y = packh2(softplusf(p.z + c1.z) - LOG2F_, softplusf(p.w + c1.w) - LOG2F_);
        *(uint2*)(eu + ((size_t)(bi * 16 + d0)) * DD + tc * 4) = u0;
        *(uint2*)(eu + ((size_t)(bi * 16 + d1)) * DD + tc * 4) = u1;
    }
}

// ---------------- launch (fork-join on two streams; edge MLP pipelined halves) ----------------
extern "C" void kernel_launch(void* const* d_in, const int* in_sizes, int n_in,
                              void* d_out, int out_size)
{
    const float* key    = (const float*)d_in[0];
    const float* value  = (const float*)d_in[1];
    const float* query  = (const float*)d_in[2];
    const unsigned char* mask = (const unsigned char*)d_in[3];
    const float* edgef  = (const float*)d_in[4];
    const int* pair_b   = (const int*)d_in[5];
    const int* pair_i   = (const int*)d_in[6];
    const int* pair_j   = (const int*)d_in[7];
    const float* Wq = (const float*)d_in[8],  *bq = (const float*)d_in[9];
    const float* Wk = (const float*)d_in[10], *bk = (const float*)d_in[11];
    const float* Wv = (const float*)d_in[12], *bv = (const float*)d_in[13];
    const float* Wo = (const float*)d_in[14], *bo = (const float*)d_in[15];
    const float* We1 = (const float*)d_in[16], *be1 = (const float*)d_in[17];
    const float* We2 = (const float*)d_in[18], *be2 = (const float*)d_in[19];
    const float* Wu1 = (const float*)d_in[20], *bu1 = (const float*)d_in[21];
    const float* Wu2 = (const float*)d_in[22], *bu2 = (const float*)d_in[23];

    float* out  = (float*)d_out;
    float* top  = out + 2097152;
    float* eupd = out + 4194304;

    float *q_, *k_, *v_, *PQ_, *ef_, *biasPQ_;
    __half *f1_, *eu_, *xK_, *xQ_, *xV_, *xC_, *o_, *WHi_;
    cudaGetSymbolAddress((void**)&q_, g_q);
    cudaGetSymbolAddress((void**)&k_, g_k);
    cudaGetSymbolAddress((void**)&v_, g_v);
    cudaGetSymbolAddress((void**)&PQ_, g_PQ);
    cudaGetSymbolAddress((void**)&ef_, g_ef);
    cudaGetSymbolAddress((void**)&f1_, g_f1);
    cudaGetSymbolAddress((void**)&eu_, g_eu);
    cudaGetSymbolAddress((void**)&xK_, g_xK);
    cudaGetSymbolAddress((void**)&xQ_, g_xQ);
    cudaGetSymbolAddress((void**)&xV_, g_xV);
    cudaGetSymbolAddress((void**)&xC_, g_xC);
    cudaGetSymbolAddress((void**)&o_, g_o);
    cudaGetSymbolAddress((void**)&WHi_, g_WHi);
    cudaGetSymbolAddress((void**)&biasPQ_, g_biasPQ);

    cudaFuncSetAttribute((const void*)tc_gemm<0, 0>,
                         cudaFuncAttributeMaxDynamicSharedMemorySize, TC_SMEM);
    cudaFuncSetAttribute((const void*)tc_gemm<0, 2>,
                         cudaFuncAttributeMaxDynamicSharedMemorySize, TC_SMEM);
    cudaFuncSetAttribute((const void*)tc_gemm_qkv,
                         cudaFuncAttributeMaxDynamicSharedMemorySize, TC_SMEM);
    cudaFuncSetAttribute((const void*)tc_gemm_f32a,
                         cudaFuncAttributeMaxDynamicSharedMemorySize, AF_SMEM);

    const int WSZ = 262144;
    const int HALF_ROWS = 32768;   // EE/2

    cudaStream_t s2;
    cudaStreamCreateWithFlags(&s2, cudaStreamNonBlocking);
    cudaEvent_t eW, eM1a, eM2a, eL;
    cudaEventCreateWithFlags(&eW, cudaEventDisableTiming);
    cudaEventCreateWithFlags(&eM1a, cudaEventDisableTiming);
    cudaEventCreateWithFlags(&eM2a, cudaEventDisableTiming);
    cudaEventCreateWithFlags(&eL, cudaEventDisableTiming);

    // s0: weight prep, then fork
    wsplit_all_t<<<545, 256>>>(Wk, Wq, Wv, Wo, Wu1, Wu2, We1, We2, bu1,
                               WHi_, biasPQ_);
    cudaEventRecord(eW, 0);

    // s2 (edge chain): MLP1 halves
    cudaStreamWaitEvent(s2, eW, 0);
    tc_gemm_f32a<<<dim3(4, 256), 256, AF_SMEM, s2>>>(edgef, WHi_ + 7 * WSZ, be1, f1_, 512, 0);
    cudaEventRecord(eM1a, s2);
    tc_gemm_f32a<<<dim3(4, 256), 256, AF_SMEM, s2>>>(edgef, WHi_ + 7 * WSZ, be1, f1_, 512, HALF_ROWS);

    // s0 (node chain): conv3 -> qkv -> global
    conv3_f16<<<1536, 256>>>(key, query, value, xK_, xQ_, xV_);
    tc_gemm_qkv<<<dim3(4, 32, 3), 256, TC_SMEM>>>(xK_, xQ_, xV_,
                                                  WHi_ + 0 * WSZ, WHi_ + 1 * WSZ, WHi_ + 2 * WSZ,
                                                  bk, bq, bv, k_, q_, v_);
    global_attn_tc<<<dim3(8, 8, 8), 128>>>(q_, k_, v_, mask, xC_, top);

    // s0: MLP2a on idle s0 (needs MLP1a)
    cudaStreamWaitEvent(0, eM1a, 0);
    tc_gemm<0, 0><<<dim3(2, 256), 256, TC_SMEM>>>(f1_, WHi_ + 8 * WSZ,
                                                  be2, ef_, nullptr, 256, 0);
    cudaEventRecord(eM2a, 0);

    // s2: MLP2b (after MLP1b in-order), then local attention
    tc_gemm<0, 0><<<dim3(2, 256), 256, TC_SMEM, s2>>>(f1_, WHi_ + 8 * WSZ,
                                                      be2, ef_, nullptr, 256, HALF_ROWS);
    cudaStreamWaitEvent(s2, eM2a, 0);   // implies qkv done too (s0 order)
    local_attn<<<ROWS, 256, 0, s2>>>(q_, k_, v_, ef_, pair_j, xC_);
    cudaEventRecord(eL, s2);

    // s0 tail (R12 shape): Wo -> PQ -> eu -> Wu2
    cudaStreamWaitEvent(0, eL, 0);
    tc_gemm<0, 2><<<dim3(4, 32), 256, TC_SMEM>>>(xC_, WHi_ + 3 * WSZ,
                                                 bo, out, o_, 512, 0);
    tc_gemm<0, 0><<<dim3(8, 32), 256, TC_SMEM>>>(o_, WHi_ + 4 * WSZ,
                                                 biasPQ_, PQ_, nullptr, 1024, 0);
    eu_kernel<<<ROWS, 256>>>(PQ_, pair_j, eu_);
    tc_gemm<0, 0><<<dim3(4, 512), 256, TC_SMEM>>>(eu_, WHi_ + 6 * WSZ,
                                                  bu2, eupd, nullptr, 512, 0);

    cudaEventDestroy(eW);
    cudaEventDestroy(eM1a);
    cudaEventDestroy(eM2a);
    cudaEventDestroy(eL);
    cudaStreamDestroy(s2);
}

// round 17
// speedup vs baseline: 1.1299x; 1.0139x over previous
#include <cuda_runtime.h>
#include <cuda_bf16.h>
#include <cuda_fp16.h>
#include <math.h>
#include <stdint.h>

// Problem constants
#define BB 8
#define NN 512
#define DD 512
#define DEG_ 16
#define EE 65536   // B*N*DEG
#define ROWS 4096  // B*N
#define GK 512     // K dim of all big GEMMs
#define SCALE 0.17677669529663687f  // 1/sqrt(32)
#define LOG2F_ 0.6931471805599453f

// ---------------- scratch (device globals; no allocs allowed) ----------------
__device__ float g_q[ROWS * DD];
__device__ float g_k[ROWS * DD];
__device__ float g_v[ROWS * DD];
__device__ float g_PQ[ROWS * 1024];
__device__ float g_ef[(size_t)EE * 256];

__device__ __half g_f1[(size_t)EE * DD];
__device__ __half g_eu[(size_t)EE * DD];
__device__ __half g_xK[ROWS * DD];
__device__ __half g_xQ[ROWS * DD];
__device__ __half g_xV[ROWS * DD];
__device__ __half g_xC[ROWS * DD];   // ctx in fp16

// weights fp16: 0 WkT,1 WqT,2 WvT,3 WoT,4 Wu1T(1024x512),6 Wu2T,7 We1T,8 We2T(256x512),9 Wo natural
__device__ __half g_WHi[10 * 262144];
__device__ __half g_WPQ[1024 * 512];   // W'^T = (Wo@Wu1)^T, [1024,512]
__device__ float g_biasPQ[1024];
__device__ float g_bPQ[1024];          // b' = bo@Wu1 + biasPQ

__device__ __forceinline__ float softplusf(float x) {
    return fmaxf(x, 0.f) + log1pf(expf(-fabsf(x)));
}

__device__ __forceinline__ uint32_t smem_to_u32(const void* smem_ptr) {
    uint32_t addr;
    asm("{ .reg .u64 tmp; cvta.to.shared.u64 tmp, %1; cvt.u32.u64 %0, tmp; }"
        : "=r"(addr) : "l"(smem_ptr));
    return addr;
}

// ---------------- PTX: cp.async / ldmatrix / mma (base-arch legal) ----------------
__device__ __forceinline__ void cpasync16(uint32_t saddr, const void* g) {
    asm volatile("cp.async.cg.shared.global [%0], [%1], 16;" :: "r"(saddr), "l"(g));
}
#define CP_COMMIT() asm volatile("cp.async.commit_group;")
#define CP_WAIT(n)  asm volatile("cp.async.wait_group %0;" :: "n"(n))

__device__ __forceinline__ void ldmx4(uint32_t r[4], uint32_t addr) {
    asm volatile("ldmatrix.sync.aligned.m8n8.x4.shared.b16 {%0,%1,%2,%3}, [%4];"
                 : "=r"(r[0]), "=r"(r[1]), "=r"(r[2]), "=r"(r[3]) : "r"(addr));
}

__device__ __forceinline__ void mma16816(float c[4], const uint32_t a[4],
                                         uint32_t b0, uint32_t b1) {
    asm volatile("mma.sync.aligned.m16n8k16.row.col.f32.f16.f16.f32 "
                 "{%0,%1,%2,%3}, {%4,%5,%6,%7}, {%8,%9}, {%0,%1,%2,%3};"
                 : "+f"(c[0]), "+f"(c[1]), "+f"(c[2]), "+f"(c[3])
                 : "r"(a[0]), "r"(a[1]), "r"(a[2]), "r"(a[3]), "r"(b0), "r"(b1));
}

__device__ __forceinline__ uint32_t packh2(float x, float y) {
    __half2 h = __floats2half2_rn(x, y);
    return *(uint32_t*)&h;
}

// ======================= tensor-core GEMM core (mma.sync fp16) ===============
#define ROWB 80
#define TILE_B (128 * ROWB)      // 10240
#define A_OFF 0
#define B_OFF (1 * TILE_B)
#define STAGE_B (2 * TILE_B)     // 20480
#define NSTAGE 4
#define TC_SMEM (NSTAGE * STAGE_B)  // 81920

// OUT: 0 = f32 only, 1 = fp16 only, 2 = f32 + fp16
template <int SOFTPLUS, int OUT>
__device__ __forceinline__ void tc_gemm_core(
    char* smem,
    const __half* __restrict__ A, const __half* __restrict__ B,
    const float* __restrict__ bias,
    float* __restrict__ Cf, __half* __restrict__ Ch,
    int N, int bm, int bn)
{
    const uint32_t sb = smem_to_u32(smem);
    const int t = threadIdx.x, lane = t & 31, w = t >> 5;
    const int wm = w & 3, wn = w >> 2;
    constexpr int KT = GK / 32;   // 16

    float acc[2][8][4] = {};

    const __half* pA[2];
    const __half* pB[2];
    uint32_t so[2];
#pragma unroll
    for (int i = 0; i < 2; i++) {
        const int id = t + i * 256;
        const int row = id >> 2, ch = id & 3;
        so[i] = row * ROWB + ch * 16;
        pA[i] = A + (size_t)(bm + row) * GK + ch * 8;
        pB[i] = B + (size_t)(bn + row) * GK + ch * 8;
    }

    auto issue = [&](int kcI, uint32_t stbase) {
#pragma unroll
        for (int i = 0; i < 2; i++) {
            cpasync16(stbase + A_OFF + so[i], pA[i] + kcI * 32);
            cpasync16(stbase + B_OFF + so[i], pB[i] + kcI * 32);
        }
    };

    const uint32_t aRow = (uint32_t)(wm * 32 + (lane & 15)) * ROWB + ((lane >> 4) << 4);
    const int n_off = (lane & 7) + ((lane >> 4) << 3);
    const int k_half = (lane >> 3) & 1;
    const uint32_t bRow = (uint32_t)(wn * 64 + n_off) * ROWB + (k_half << 4);

    issue(0, sb);               CP_COMMIT();
    issue(1, sb + STAGE_B);     CP_COMMIT();
    issue(2, sb + 2 * STAGE_B); CP_COMMIT();

#pragma unroll
    for (int kc = 0; kc < KT; kc++) {
        if (kc + 2 < KT)      { CP_WAIT(2); }
        else if (kc + 1 < KT) { CP_WAIT(1); }
        else                  { CP_WAIT(0); }
        __syncthreads();
        if (kc + 3 < KT) {
            issue(kc + 3, sb + ((kc + 3) & 3) * STAGE_B);
            CP_COMMIT();
        }
        const uint32_t cur = sb + (kc & 3) * STAGE_B;

#pragma unroll
        for (int ks = 0; ks < 2; ks++) {
            const uint32_t kb = ks * 32;
            uint32_t a[2][4], bh[4][4];
            ldmx4(a[0], cur + A_OFF + aRow + kb);
            ldmx4(a[1], cur + A_OFF + aRow + 16 * ROWB + kb);
#pragma unroll
            for (int jj = 0; jj < 4; jj++)
                ldmx4(bh[jj], cur + B_OFF + bRow + jj * 16 * ROWB + kb);
#pragma unroll
            for (int g = 0; g < 2; g++) {
#pragma unroll
                for (int j = 0; j < 8; j++) {
                    const int jj = j >> 1, hf = (j & 1) * 2;
                    mma16816(acc[g][j], a[g], bh[jj][hf], bh[jj][hf + 1]);
                }
            }
        }
    }

    float bcol[16];
    {
        const int col0 = bn + wn * 64 + (lane & 3) * 2;
#pragma unroll
        for (int j = 0; j < 8; j++) {
            bcol[j * 2]     = bias ? bias[col0 + j * 8]     : 0.f;
            bcol[j * 2 + 1] = bias ? bias[col0 + j * 8 + 1] : 0.f;
        }
    }
#pragma unroll
    for (int g = 0; g < 2; g++) {
#pragma unroll
        for (int j = 0; j < 8; j++) {
            const int row = bm + wm * 32 + g * 16 + (lane >> 2);
            const int col = bn + wn * 64 + j * 8 + (lane & 3) * 2;
            float v0 = acc[g][j][0] + bcol[j * 2], v1 = acc[g][j][1] + bcol[j * 2 + 1];
            float v2 = acc[g][j][2] + bcol[j * 2], v3 = acc[g][j][3] + bcol[j * 2 + 1];
            if (SOFTPLUS) {
                v0 = softplusf(v0) - LOG2F_; v1 = softplusf(v1) - LOG2F_;
                v2 = softplusf(v2) - LOG2F_; v3 = softplusf(v3) - LOG2F_;
            }
            if (OUT == 0 || OUT == 2) {
                *(float2*)(Cf + (size_t)row * N + col) = make_float2(v0, v1);
                *(float2*)(Cf + (size_t)(row + 8) * N + col) = make_float2(v2, v3);
            }
            if (OUT == 1 || OUT == 2) {
                *(uint32_t*)(Ch + (size_t)row * N + col) = packh2(v0, v1);
                *(uint32_t*)(Ch + (size_t)(row + 8) * N + col) = packh2(v2, v3);
            }
        }
    }
}

template <int SOFTPLUS, int OUT>
__global__ __launch_bounds__(256, 2) void tc_gemm(
    const __half* __restrict__ A, const __half* __restrict__ B,
    const float* __restrict__ bias,
    float* __restrict__ Cf, __half* __restrict__ Ch,
    int N)
{
    extern __shared__ char smem[];
    tc_gemm_core<SOFTPLUS, OUT>(smem, A, B, bias, Cf, Ch, N,
                                blockIdx.y * 128, blockIdx.x * 128);
}

// batched K/Q/V projection: blockIdx.z selects the triple
__global__ __launch_bounds__(256, 2) void tc_gemm_qkv(
    const __half* __restrict__ xK, const __half* __restrict__ xQ, const __half* __restrict__ xV,
    const __half* __restrict__ WkT, const __half* __restrict__ WqT, const __half* __restrict__ WvT,
    const float* __restrict__ bk, const float* __restrict__ bq, const float* __restrict__ bv,
    float* __restrict__ k_, float* __restrict__ q_, float* __restrict__ v_)
{
    extern __shared__ char smem[];
    const int z = blockIdx.z;
    const __half* A = (z == 0) ? xK : (z == 1) ? xQ : xV;
    const __half* B = (z == 0) ? WkT : (z == 1) ? WqT : WvT;
    const float* bias = (z == 0) ? bk : (z == 1) ? bq : bv;
    float* C = (z == 0) ? k_ : (z == 1) ? q_ : v_;
    tc_gemm_core<0, 0>(smem, A, B, bias, C, nullptr, 512,
                       blockIdx.y * 128, blockIdx.x * 128);
}

// ======================= MLP1 GEMM with fused f32->fp16 A conversion =======================
#define AF_A32 0
#define AF_B   18432
#define AF_STAGE (18432 + 10240) // 28672
#define AF_F16 (3 * AF_STAGE)    // 86016
#define AF_SMEM (AF_F16 + 10240) // 96256

__global__ __launch_bounds__(256, 2) void tc_gemm_f32a(
    const float* __restrict__ A, const __half* __restrict__ B,
    const float* __restrict__ bias, __half* __restrict__ Ch, int N)
{
    extern __shared__ char smem[];
    const uint32_t sb = smem_to_u32(smem);
    const int t = threadIdx.x, lane = t & 31, w = t >> 5;
    const int wm = w & 3, wn = w >> 2;
    const int bm = blockIdx.y * 128, bn = blockIdx.x * 128;
    constexpr int KT = GK / 32;   // 16

    float acc[2][8][4] = {};

    const float* pA[4];
    uint32_t soA[4];
#pragma unroll
    for (int i = 0; i < 4; i++) {
        const int id = t + i * 256;
        const int row = id >> 3, ch = id & 7;
        soA[i] = row * 144 + ch * 16;
        pA[i] = A + (size_t)(bm + row) * GK + ch * 4;
    }
    const __half* pB[2];
    uint32_t soB[2];
#pragma unroll
    for (int i = 0; i < 2; i++) {
        const int id = t + i * 256;
        const int row = id >> 2, ch = id & 3;
        soB[i] = row * ROWB + ch * 16;
        pB[i] = B + (size_t)(bn + row) * GK + ch * 8;
    }

    auto issue = [&](int kcI, uint32_t st) {
#pragma unroll
        for (int i = 0; i < 4; i++) cpasync16(st + AF_A32 + soA[i], pA[i] + kcI * 32);
#pragma unroll
        for (int i = 0; i < 2; i++) cpasync16(st + AF_B + soB[i], pB[i] + kcI * 32);
    };

    const uint32_t aRow = (uint32_t)(wm * 32 + (lane & 15)) * ROWB + ((lane >> 4) << 4);
    const int n_off = (lane & 7) + ((lane >> 4) << 3);
    const int k_half = (lane >> 3) & 1;
    const uint32_t bRow = (uint32_t)(wn * 64 + n_off) * ROWB + (k_half << 4);
    const uint32_t sF = sb + AF_F16;

    const int cr = t >> 1, chf = t & 1;
    const uint32_t cvtSrc = cr * 144 + chf * 64;
    char* const cvtDstP = smem + AF_F16 + cr * ROWB + chf * 32;

    issue(0, sb);            CP_COMMIT();
    issue(1, sb + AF_STAGE); CP_COMMIT();

#pragma unroll
    for (int kc = 0; kc < KT; kc++) {
        if (kc + 1 < KT) { CP_WAIT(1); } else { CP_WAIT(0); }
        __syncthreads();
        const int st = kc % 3;
        const uint32_t cur = sb + st * AF_STAGE;
        if (kc + 2 < KT) {
            issue(kc + 2, sb + ((kc + 2) % 3) * AF_STAGE);
            CP_COMMIT();
        }
        {
            const char* srcp = smem + st * AF_STAGE + cvtSrc;
            float4 f0 = *(const float4*)(srcp);
            float4 f1v = *(const float4*)(srcp + 16);
            float4 f2 = *(const float4*)(srcp + 32);
            float4 f3 = *(const float4*)(srcp + 48);
            uint4 u0, u1;
            u0.x = packh2(f0.x, f0.y);  u0.y = packh2(f0.z, f0.w);
            u0.z = packh2(f1v.x, f1v.y); u0.w = packh2(f1v.z, f1v.w);
            u1.x = packh2(f2.x, f2.y);  u1.y = packh2(f2.z, f2.w);
            u1.z = packh2(f3.x, f3.y);  u1.w = packh2(f3.z, f3.w);
            *(uint4*)(cvtDstP)      = u0;
            *(uint4*)(cvtDstP + 16) = u1;
        }
        __syncthreads();

#pragma unroll
        for (int ks = 0; ks < 2; ks++) {
            const uint32_t kb = ks * 32;
            uint32_t a[2][4], bh[4][4];
            ldmx4(a[0], sF + aRow + kb);
            ldmx4(a[1], sF + aRow + 16 * ROWB + kb);
#pragma unroll
            for (int jj = 0; jj < 4; jj++)
                ldmx4(bh[jj], cur + AF_B + bRow + jj * 16 * ROWB + kb);
#pragma unroll
            for (int g = 0; g < 2; g++) {
#pragma unroll
                for (int j = 0; j < 8; j++) {
                    const int jj = j >> 1, hf = (j & 1) * 2;
                    mma16816(acc[g][j], a[g], bh[jj][hf], bh[jj][hf + 1]);
                }
            }
        }
    }

    float bcol[16];
    {
        const int col0 = bn + wn * 64 + (lane & 3) * 2;
#pragma unroll
        for (int j = 0; j < 8; j++) {
            bcol[j * 2]     = bias[col0 + j * 8];
            bcol[j * 2 + 1] = bias[col0 + j * 8 + 1];
        }
    }
#pragma unroll
    for (int g = 0; g < 2; g++) {
#pragma unroll
        for (int j = 0; j < 8; j++) {
            const int row = bm + wm * 32 + g * 16 + (lane >> 2);
            const int col = bn + wn * 64 + j * 8 + (lane & 3) * 2;
            float v0 = softplusf(acc[g][j][0] + bcol[j * 2]) - LOG2F_;
            float v1 = softplusf(acc[g][j][1] + bcol[j * 2 + 1]) - LOG2F_;
            float v2 = softplusf(acc[g][j][2] + bcol[j * 2]) - LOG2F_;
            float v3 = softplusf(acc[g][j][3] + bcol[j * 2 + 1]) - LOG2F_;
            *(uint32_t*)(Ch + (size_t)row * N + col) = packh2(v0, v1);
            *(uint32_t*)(Ch + (size_t)(row + 8) * N + col) = packh2(v2, v3);
        }
    }
}

// key/query/value conversions in one launch, ILP4.
__global__ __launch_bounds__(256) void conv3_f16(
    const float* __restrict__ k, const float* __restrict__ q, const float* __restrict__ v,
    __half* __restrict__ xk, __half* __restrict__ xq, __half* __restrict__ xv)
{
    const int seg = blockIdx.x >> 9;
    const size_t base = (size_t)(blockIdx.x & 511) * 1024 + threadIdx.x;
    const float* x = (seg == 0) ? k : (seg == 1) ? q : v;
    __half* y = (seg == 0) ? xk : (seg == 1) ? xq : xv;
    float4 val[4];
#pragma unroll
    for (int kk = 0; kk < 4; kk++) val[kk] = ((const float4*)x)[base + kk * 256];
#pragma unroll
    for (int kk = 0; kk < 4; kk++) {
        uint2 u;
        u.x = packh2(val[kk].x, val[kk].y);
        u.y = packh2(val[kk].z, val[kk].w);
        *(uint2*)(y + (base + kk * 256) * 4) = u;
    }
}

// ---------------- weights: coalesced SMEM-tile transpose + fp16 ----------------
// bids 0..511: eight 512x512 matrices (transposed); seg 3 (Wo) also writes natural copy slot 9;
// 512..543: We2; 544: biasPQ.
__global__ __launch_bounds__(256) void wsplit_all_t(
    const float* __restrict__ Wk, const float* __restrict__ Wq, const float* __restrict__ Wv,
    const float* __restrict__ Wo, const float* __restrict__ Wu1, const float* __restrict__ Wu2,
    const float* __restrict__ We1, const float* __restrict__ We2,
    const float* __restrict__ bu1,
    __half* __restrict__ WHi, float* __restrict__ biasPQ)
{
    __shared__ float S[64][68];
    const int bid = blockIdx.x, t = threadIdx.x;

    if (bid == 544) {
#pragma unroll
        for (int it = 0; it < 4; it++) {
            const int i = it * 256 + t;
            biasPQ[i] = (i < 512) ? bu1[i] : 0.f;
        }
        return;
    }

    const float* src;
    int segOut, Ndim, tk, tn;
    if (bid < 512) {
        const int seg = bid >> 6;
        switch (seg) {
            case 0: src = Wk; break;
            case 1: src = Wq; break;
            case 2: src = Wv; break;
            case 3: src = Wo; break;
            case 4: src = Wu1; break;
            case 5: src = Wu1 + 262144; break;
            case 6: src = Wu2; break;
            default: src = We1; break;
        }
        segOut = seg; Ndim = 512;
        const int tile = bid & 63;
        tk = tile >> 3; tn = tile & 7;
    } else {
        src = We2; segOut = 8; Ndim = 256;
        const int tile = bid - 512;
        tk = tile >> 2; tn = tile & 3;
    }

    {
        const int c4 = (t & 15) * 4;
#pragma unroll
        for (int it = 0; it < 4; it++) {
            const int r = it * 16 + (t >> 4);
            float4 v = *(const float4*)(src + (size_t)(tk * 64 + r) * Ndim + tn * 64 + c4);
            S[r][c4] = v.x; S[r][c4 + 1] = v.y; S[r][c4 + 2] = v.z; S[r][c4 + 3] = v.w;
        }
    }
    __syncthreads();

    {
        __half* dst = WHi + (size_t)segOut * 262144;
        const int kg = (t & 15) * 4;
#pragma unroll
        for (int it = 0; it < 4; it++) {
            const int n = it * 16 + (t >> 4);
            uint2 u;
            u.x = packh2(S[kg][n], S[kg + 1][n]);
            u.y = packh2(S[kg + 2][n], S[kg + 3][n]);
            *(uint2*)(dst + (size_t)(tn * 64 + n) * 512 + tk * 64 + kg) = u;
        }
    }
    if (segOut == 3) {
        __half* dst9 = WHi + (size_t)9 * 262144;
        const int c4 = (t & 15) * 4;
#pragma unroll
        for (int it = 0; it < 4; it++) {
            const int r = it * 16 + (t >> 4);
            uint2 u;
            u.x = packh2(S[r][c4], S[r][c4 + 1]);
            u.y = packh2(S[r][c4 + 2], S[r][c4 + 3]);
            *(uint2*)(dst9 + (size_t)(tk * 64 + r) * 512 + tn * 64 + c4) = u;
        }
    }
}

// b' = bo @ Wu1 + biasPQ  — one block per output n, 128-thread reduction
__global__ __launch_bounds__(128) void bfuse(
    const float* __restrict__ bo, const __half* __restrict__ Wu1T,
    const float* __restrict__ biasPQ, float* __restrict__ bPQ)
{
    const int n = blockIdx.x;           // 0..1023
    const int t = threadIdx.x;          // 0..127
    const __half* row = Wu1T + (size_t)n * 512;
    float s = 0.f;
#pragma unroll
    for (int i = 0; i < 4; i++) {
        const int j = t + i * 128;
        s = fmaf(bo[j], __half2float(row[j]), s);
    }
#pragma unroll
    for (int o = 16; o; o >>= 1) s += __shfl_xor_sync(0xffffffffu, s, o);
    __shared__ float ws[4];
    if ((t & 31) == 0) ws[t >> 5] = s;
    __syncthreads();
    if (t == 0) bPQ[n] = ws[0] + ws[1] + ws[2] + ws[3] + biasPQ[n];
}

// ---------------- local attention: one block per (b,i), ctx written fp16 ----------------
__global__ __launch_bounds__(256) void local_attn(
    const float* __restrict__ q, const float* __restrict__ k,
    const float* __restrict__ v, const float* __restrict__ ef,
    const int* __restrict__ pair_j, __half* __restrict__ ctx)
{
    const int bi = blockIdx.x;
    const int b = bi >> 9;
    const int t = threadIdx.x;

    __shared__ float qs[256];
    __shared__ int js[16];
    __shared__ float sc[16][8];
    __shared__ float wgt[16][8];

    if (t < 16) js[t] = pair_j[bi * 16 + t];
    qs[t] = q[(size_t)bi * DD + 256 + t];
    __syncthreads();

    if (t < 128) {
        const int d = t >> 3, h = t & 7;
        const int j = js[d];
        const float* kr = k + ((size_t)(b * NN + j)) * DD + 256 + h * 32;
        const float* er = ef + ((size_t)(bi * 16 + d)) * 256 + h * 32;
        const float* qr = qs + h * 32;
        float s = 0.f;
#pragma unroll
        for (int c4 = 0; c4 < 8; c4++) {
            float4 kk = *(const float4*)(kr + c4 * 4);
            float4 eee = *(const float4*)(er + c4 * 4);
            s = fmaf(qr[c4 * 4 + 0], kk.x * eee.x, s);
            s = fmaf(qr[c4 * 4 + 1], kk.y * eee.y, s);
            s = fmaf(qr[c4 * 4 + 2], kk.z * eee.z, s);
            s = fmaf(qr[c4 * 4 + 3], kk.w * eee.w, s);
        }
        sc[d][h] = s * SCALE;
    }
    __syncthreads();

    if (t < 8) {
        const int h = t;
        float m = -1e30f;
#pragma unroll
        for (int d = 0; d < 16; d++) {
            float s = sc[d][h];
            if (s > -10000.f && s > m) m = s;
        }
        float sum = 0.f;
#pragma unroll
        for (int d = 0; d < 16; d++) {
            float s = sc[d][h];
            float e = (s > -10000.f) ? expf(s - m) : 0.f;
            wgt[d][h] = e;
            sum += e;
        }
        float inv = (sum > 0.f) ? 1.f / sum : 0.f;
#pragma unroll
        for (int d = 0; d < 16; d++) wgt[d][h] *= inv;
    }
    __syncthreads();

    const int h = t >> 5, c = t & 31;
    float o = 0.f;
#pragma unroll
    for (int d = 0; d < 16; d++) {
        float w = wgt[d][h];
        o = fmaf(w, v[((size_t)(b * NN + js[d])) * DD + 256 + h * 32 + c], o);
    }
    ctx[(size_t)bi * DD + h * 64 + 32 + c] = __float2half_rn(o);
}

// ========== global attention: tensor-core flash kernel ==========
__global__ __launch_bounds__(128) void global_attn_tc(
    const float* __restrict__ qf, const float* __restrict__ kf,
    const float* __restrict__ vf, const unsigned char* __restrict__ mask,
    __half* __restrict__ ctx, float* __restrict__ top)
{
    const int qt = blockIdx.x, h = blockIdx.y, b = blockIdx.z;
    const int t = threadIdx.x, lane = t & 31, w = t >> 5;

    __shared__ __half Qhi[64 * 40], Qlo[64 * 40];
    __shared__ __half Khi[64 * 40], Klo[64 * 40];
    __shared__ __half Vt[32 * 72];
    __shared__ unsigned char Ms[64 * 64];

    const uint32_t sQh = smem_to_u32(Qhi), sQl = smem_to_u32(Qlo);
    const uint32_t sKh = smem_to_u32(Khi), sKl = smem_to_u32(Klo);
    const uint32_t sV = smem_to_u32(Vt);

#pragma unroll
    for (int i = 0; i < 4; i++) {
        const int id = t + i * 128;
        const int row = id >> 3, ch = id & 7;
        float4 v4 = *(const float4*)(qf + ((size_t)(b * NN) + qt * 64 + row) * DD + h * 32 + ch * 4);
        __half h0 = __float2half_rn(v4.x), h1 = __float2half_rn(v4.y);
        __half h2 = __float2half_rn(v4.z), h3 = __float2half_rn(v4.w);
        __half l0 = __float2half_rn(v4.x - __half2float(h0));
        __half l1 = __float2half_rn(v4.y - __half2float(h1));
        __half l2 = __float2half_rn(v4.z - __half2float(h2));
        __half l3 = __float2half_rn(v4.w - __half2float(h3));
        uint2 uh, ul;
        uh.x = ((uint32_t)__half_as_ushort(h1) << 16) | __half_as_ushort(h0);
        uh.y = ((uint32_t)__half_as_ushort(h3) << 16) | __half_as_ushort(h2);
        ul.x = ((uint32_t)__half_as_ushort(l1) << 16) | __half_as_ushort(l0);
        ul.y = ((uint32_t)__half_as_ushort(l3) << 16) | __half_as_ushort(l2);
        *(uint2*)&Qhi[row * 40 + ch * 4] = uh;
        *(uint2*)&Qlo[row * 40 + ch * 4] = ul;
    }

    const uint32_t aOff = (uint32_t)(w * 16 + (lane & 15)) * 80 + ((lane >> 4) << 4);
    const uint32_t bOffR = (uint32_t)((lane & 7) + ((lane >> 4) << 3));
    const uint32_t kOff = bOffR * 80 + (((lane >> 3) & 1) << 4);
    const uint32_t vOff = bOffR * 144 + (((lane >> 3) & 1) << 4);

    __syncthreads();
    uint32_t aHi[2][4], aLo[2][4];
    ldmx4(aHi[0], sQh + aOff);
    ldmx4(aHi[1], sQh + aOff + 32);
    ldmx4(aLo[0], sQl + aOff);
    ldmx4(aLo[1], sQl + aOff + 32);

    float o[4][4] = {};
    float mA = -1e30f, mB = -1e30f, lA = 0.f, lB = 0.f;
    const int rA = lane >> 2;
    const size_t qrow0 = (size_t)(b * NN) + qt * 64 + w * 16 + rA;

    for (int kt = 0; kt < 8; kt++) {
        __syncthreads();
#pragma unroll
        for (int i = 0; i < 4; i++) {
            const int id = t + i * 128;
            const int row = id >> 3, ch = id & 7;
            float4 v4 = *(const float4*)(kf + ((size_t)(b * NN) + kt * 64 + row) * DD + h * 32 + ch * 4);
            __half h0 = __float2half_rn(v4.x), h1 = __float2half_rn(v4.y);
            __half h2 = __float2half_rn(v4.z), h3 = __float2half_rn(v4.w);
            __half l0 = __float2half_rn(v4.x - __half2float(h0));
            __half l1 = __float2half_rn(v4.y - __half2float(h1));
            __half l2 = __float2half_rn(v4.z - __half2float(h2));
            __half l3 = __float2half_rn(v4.w - __half2float(h3));
            uint2 uh, ul;
            uh.x = ((uint32_t)__half_as_ushort(h1) << 16) | __half_as_ushort(h0);
            uh.y = ((uint32_t)__half_as_ushort(h3) << 16) | __half_as_ushort(h2);
            ul.x = ((uint32_t)__half_as_ushort(l1) << 16) | __half_as_ushort(l0);
            ul.y = ((uint32_t)__half_as_ushort(l3) << 16) | __half_as_ushort(l2);
            *(uint2*)&Khi[row * 40 + ch * 4] = uh;
            *(uint2*)&Klo[row * 40 + ch * 4] = ul;
        }
#pragma unroll
        for (int i = 0; i < 4; i++) {
            const int id = t + i * 128;
            const int key = id >> 3, dh = (id & 7) * 4;
            float4 v4 = *(const float4*)(vf + ((size_t)(b * NN) + kt * 64 + key) * DD + h * 32 + dh);
            Vt[(dh + 0) * 72 + key] = __float2half_rn(v4.x);
            Vt[(dh + 1) * 72 + key] = __float2half_rn(v4.y);
            Vt[(dh + 2) * 72 + key] = __float2half_rn(v4.z);
            Vt[(dh + 3) * 72 + key] = __float2half_rn(v4.w);
        }
#pragma unroll
        for (int i = 0; i < 2; i++) {
            const int id = t + i * 128;
            const int row = id >> 2, ch = id & 3;
            *(uint4*)&Ms[row * 64 + ch * 16] =
                *(const uint4*)(mask + ((size_t)(b * NN) + qt * 64 + row) * NN + kt * 64 + ch * 16);
        }
        __syncthreads();

        float s[8][4];
#pragma unroll
        for (int n = 0; n < 8; n++) { s[n][0] = s[n][1] = s[n][2] = s[n][3] = 0.f; }
#pragma unroll
        for (int ks = 0; ks < 2; ks++) {
#pragma unroll
            for (int jj = 0; jj < 4; jj++) {
                uint32_t bh[4], bl[4];
                ldmx4(bh, sKh + kOff + jj * (16 * 80) + ks * 32);
                ldmx4(bl, sKl + kOff + jj * (16 * 80) + ks * 32);
                mma16816(s[jj * 2],     aHi[ks], bh[0], bh[1]);
                mma16816(s[jj * 2 + 1], aHi[ks], bh[2], bh[3]);
                mma16816(s[jj * 2],     aHi[ks], bl[0], bl[1]);
                mma16816(s[jj * 2 + 1], aHi[ks], bl[2], bl[3]);
                mma16816(s[jj * 2],     aLo[ks], bh[0], bh[1]);
                mma16816(s[jj * 2 + 1], aLo[ks], bh[2], bh[3]);
            }
        }
#pragma unroll
        for (int n = 0; n < 8; n++) {
            s[n][0] *= SCALE; s[n][1] *= SCALE; s[n][2] *= SCALE; s[n][3] *= SCALE;
        }

        if (h == 0) {
#pragma unroll
            for (int n = 0; n < 8; n++) {
                const int col = kt * 64 + n * 8 + (lane & 3) * 2;
                *(float2*)(top + qrow0 * NN + col) = make_float2(s[n][0], s[n][1]);
                *(float2*)(top + (qrow0 + 8) * NN + col) = make_float2(s[n][2], s[n][3]);
            }
        }
        {
            const int lr = w * 16 + rA;
#pragma unroll
            for (int n = 0; n < 8; n++) {
                const int col = n * 8 + (lane & 3) * 2;
                if (Ms[lr * 64 + col])           s[n][0] = -1e18f;
                if (Ms[lr * 64 + col + 1])       s[n][1] = -1e18f;
                if (Ms[(lr + 8) * 64 + col])     s[n][2] = -1e18f;
                if (Ms[(lr + 8) * 64 + col + 1]) s[n][3] = -1e18f;
            }
        }

        float tmA = -1e30f, tmB = -1e30f;
#pragma unroll
        for (int n = 0; n < 8; n++) {
            tmA = fmaxf(tmA, fmaxf(s[n][0], s[n][1]));
            tmB = fmaxf(tmB, fmaxf(s[n][2], s[n][3]));
        }
        tmA = fmaxf(tmA, __shfl_xor_sync(0xffffffffu, tmA, 1));
        tmA = fmaxf(tmA, __shfl_xor_sync(0xffffffffu, tmA, 2));
        tmB = fmaxf(tmB, __shfl_xor_sync(0xffffffffu, tmB, 1));
        tmB = fmaxf(tmB, __shfl_xor_sync(0xffffffffu, tmB, 2));
        const float mAn = fmaxf(mA, tmA), mBn = fmaxf(mB, tmB);
        const float fAc = __expf(mA - mAn), fBc = __expf(mB - mBn);
        float sumA = 0.f, sumB = 0.f;
        uint32_t pf[4][4];
#pragma unroll
        for (int n = 0; n < 8; n++) {
            float p0 = __expf(s[n][0] - mAn), p1 = __expf(s[n][1] - mAn);
            float p2 = __expf(s[n][2] - mBn), p3 = __expf(s[n][3] - mBn);
            sumA += p0 + p1; sumB += p2 + p3;
            pf[n >> 1][(n & 1) * 2]     = packh2(p0, p1);
            pf[n >> 1][(n & 1) * 2 + 1] = packh2(p2, p3);
        }
        sumA += __shfl_xor_sync(0xffffffffu, sumA, 1);
        sumA += __shfl_xor_sync(0xffffffffu, sumA, 2);
        sumB += __shfl_xor_sync(0xffffffffu, sumB, 1);
        sumB += __shfl_xor_sync(0xffffffffu, sumB, 2);
        lA = lA * fAc + sumA;
        lB = lB * fBc + sumB;
#pragma unroll
        for (int n = 0; n < 4; n++) {
            o[n][0] *= fAc; o[n][1] *= fAc; o[n][2] *= fBc; o[n][3] *= fBc;
        }
        mA = mAn; mB = mBn;

#pragma unroll
        for (int kfi = 0; kfi < 4; kfi++) {
#pragma unroll
            for (int jj = 0; jj < 2; jj++) {
                uint32_t bv[4];
                ldmx4(bv, sV + vOff + jj * (16 * 144) + kfi * 32);
                mma16816(o[jj * 2],     pf[kfi], bv[0], bv[1]);
                mma16816(o[jj * 2 + 1], pf[kfi], bv[2], bv[3]);
            }
        }
    }

    const float iA = 1.f / lA, iB = 1.f / lB;
#pragma unroll
    for (int n = 0; n < 4; n++) {
        const int col = h * 64 + n * 8 + (lane & 3) * 2;
        *(uint32_t*)(ctx + qrow0 * DD + col) = packh2(o[n][0] * iA, o[n][1] * iA);
        *(uint32_t*)(ctx + (qrow0 + 8) * DD + col) = packh2(o[n][2] * iB, o[n][3] * iB);
    }
}

// ---------------- eu: one block per (b,i); 256 threads, 2 rows in flight ----------------
__global__ __launch_bounds__(256) void eu_kernel(
    const float* __restrict__ PQ,
    const int* __restrict__ pair_j,
    __half* __restrict__ eu)
{
    const int bi = blockIdx.x;
    const int b = bi >> 9;
    const int t = threadIdx.x;
    const int half = t >> 7;
    const int tc = t & 127;

    __shared__ int js[16];
    if (t < 16) js[t] = pair_j[bi * 16 + t];

    const float4 p = *(const float4*)(PQ + (size_t)bi * 1024 + tc * 4);
    __syncthreads();

#pragma unroll
    for (int dd = 0; dd < 8; dd += 2) {
        const int d0 = half * 8 + dd, d1 = d0 + 1;
        const int j0 = js[d0], j1 = js[d1];
        float4 c0 = *(const float4*)(PQ + ((size_t)(b * NN + j0)) * 1024 + 512 + tc * 4);
        float4 c1 = *(const float4*)(PQ + ((size_t)(b * NN + j1)) * 1024 + 512 + tc * 4);
        uint2 u0, u1;
        u0.x = packh2(softplusf(p.x + c0.x) - LOG2F_, softplusf(p.y + c0.y) - LOG2F_);
        u0.y = packh2(softplusf(p.z + c0.z) - LOG2F_, softplusf(p.w + c0.w) - LOG2F_);
        u1.x = packh2(softplusf(p.x + c1.x) - LOG2F_, softplusf(p.y + c1.y) - LOG2F_);
        u1.y = packh2(softplusf(p.z + c1.z) - LOG2F_, softplusf(p.w + c1.w) - LOG2F_);
        *(uint2*)(eu + ((size_t)(bi * 16 + d0)) * DD + tc * 4) = u0;
        *(uint2*)(eu + ((size_t)(bi * 16 + d1)) * DD + tc * 4) = u1;
    }
}

// ---------------- launch (three streams; fusion prep off critical path) ----------------
extern "C" void kernel_launch(void* const* d_in, const int* in_sizes, int n_in,
                              void* d_out, int out_size)
{
    const float* key    = (const float*)d_in[0];
    const float* value  = (const float*)d_in[1];
    const float* query  = (const float*)d_in[2];
    const unsigned char* mask = (const unsigned char*)d_in[3];
    const float* edgef  = (const float*)d_in[4];
    const int* pair_b   = (const int*)d_in[5];
    const int* pair_i   = (const int*)d_in[6];
    const int* pair_j   = (const int*)d_in[7];
    const float* Wq = (const float*)d_in[8],  *bq = (const float*)d_in[9];
    const float* Wk = (const float*)d_in[10], *bk = (const float*)d_in[11];
    const float* Wv = (const float*)d_in[12], *bv = (const float*)d_in[13];
    const float* Wo = (const float*)d_in[14], *bo = (const float*)d_in[15];
    const float* We1 = (const float*)d_in[16], *be1 = (const float*)d_in[17];
    const float* We2 = (const float*)d_in[18], *be2 = (const float*)d_in[19];
    const float* Wu1 = (const float*)d_in[20], *bu1 = (const float*)d_in[21];
    const float* Wu2 = (const float*)d_in[22], *bu2 = (const float*)d_in[23];

    float* out  = (float*)d_out;
    float* top  = out + 2097152;
    float* eupd = out + 4194304;

    float *q_, *k_, *v_, *PQ_, *ef_, *biasPQ_, *bPQ_;
    __half *f1_, *eu_, *xK_, *xQ_, *xV_, *xC_, *WHi_, *WPQ_;
    cudaGetSymbolAddress((void**)&q_, g_q);
    cudaGetSymbolAddress((void**)&k_, g_k);
    cudaGetSymbolAddress((void**)&v_, g_v);
    cudaGetSymbolAddress((void**)&PQ_, g_PQ);
    cudaGetSymbolAddress((void**)&ef_, g_ef);
    cudaGetSymbolAddress((void**)&f1_, g_f1);
    cudaGetSymbolAddress((void**)&eu_, g_eu);
    cudaGetSymbolAddress((void**)&xK_, g_xK);
    cudaGetSymbolAddress((void**)&xQ_, g_xQ);
    cudaGetSymbolAddress((void**)&xV_, g_xV);
    cudaGetSymbolAddress((void**)&xC_, g_xC);
    cudaGetSymbolAddress((void**)&WHi_, g_WHi);
    cudaGetSymbolAddress((void**)&WPQ_, g_WPQ);
    cudaGetSymbolAddress((void**)&biasPQ_, g_biasPQ);
    cudaGetSymbolAddress((void**)&bPQ_, g_bPQ);

    cudaFuncSetAttribute((const void*)tc_gemm<0, 0>,
                         cudaFuncAttributeMaxDynamicSharedMemorySize, TC_SMEM);
    cudaFuncSetAttribute((const void*)tc_gemm<0, 1>,
                         cudaFuncAttributeMaxDynamicSharedMemorySize, TC_SMEM);
    cudaFuncSetAttribute((const void*)tc_gemm_qkv,
                         cudaFuncAttributeMaxDynamicSharedMemorySize, TC_SMEM);
    cudaFuncSetAttribute((const void*)tc_gemm_f32a,
                         cudaFuncAttributeMaxDynamicSharedMemorySize, AF_SMEM);

    const int WSZ = 262144;

    cudaStream_t s2, s3;
    cudaStreamCreateWithFlags(&s2, cudaStreamNonBlocking);
    cudaStreamCreateWithFlags(&s3, cudaStreamNonBlocking);
    cudaEvent_t eW, eF, eQKV, eL, eG, eP;
    cudaEventCreateWithFlags(&eW, cudaEventDisableTiming);
    cudaEventCreateWithFlags(&eF, cudaEventDisableTiming);
    cudaEventCreateWithFlags(&eQKV, cudaEventDisableTiming);
    cudaEventCreateWithFlags(&eL, cudaEventDisableTiming);
    cudaEventCreateWithFlags(&eG, cudaEventDisableTiming);
    cudaEventCreateWithFlags(&eP, cudaEventDisableTiming);

    // s0: weight prep, then fork
    wsplit_all_t<<<545, 256>>>(Wk, Wq, Wv, Wo, Wu1, Wu2, We1, We2, bu1,
                               WHi_, biasPQ_);
    cudaEventRecord(eW, 0);

    // s3: fusion prep fully off the critical path (concurrent with MLP1/conv3)
    cudaStreamWaitEvent(s3, eW, 0);
    bfuse<<<1024, 128, 0, s3>>>(bo, WHi_ + 4 * WSZ, biasPQ_, bPQ_);
    tc_gemm<0, 1><<<dim3(4, 8), 256, TC_SMEM, s3>>>(WHi_ + 4 * WSZ, WHi_ + 9 * WSZ,
                                                    nullptr, nullptr, WPQ_, 512);
    cudaEventRecord(eF, s3);

    // s2 (edge chain): MLP1 (fused f32 A) -> MLP2
    cudaStreamWaitEvent(s2, eW, 0);
    tc_gemm_f32a<<<dim3(4, 512), 256, AF_SMEM, s2>>>(edgef, WHi_ + 7 * WSZ, be1, f1_, 512);
    tc_gemm<0, 0><<<dim3(2, 512), 256, TC_SMEM, s2>>>(f1_, WHi_ + 8 * WSZ,
                                                      be2, ef_, nullptr, 256);

    // s0 (node chain): conv3 -> qkv
    conv3_f16<<<1536, 256>>>(key, query, value, xK_, xQ_, xV_);
    tc_gemm_qkv<<<dim3(4, 32, 3), 256, TC_SMEM>>>(xK_, xQ_, xV_,
                                                  WHi_ + 0 * WSZ, WHi_ + 1 * WSZ, WHi_ + 2 * WSZ,
                                                  bk, bq, bv, k_, q_, v_);
    cudaEventRecord(eQKV, 0);

    // s2: local attention (needs ef + qkv)
    cudaStreamWaitEvent(s2, eQKV, 0);
    local_attn<<<ROWS, 256, 0, s2>>>(q_, k_, v_, ef_, pair_j, xC_);
    cudaEventRecord(eL, s2);

    // s0: global attention (disjoint ctx columns)
    global_attn_tc<<<dim3(8, 8, 8), 128>>>(q_, k_, v_, mask, xC_, top);
    cudaEventRecord(eG, 0);

    // s2: PQ = ctx @ W' + b'  (full ctx; WPQ ready via eF) — concurrent with Wo
    cudaStreamWaitEvent(s2, eG, 0);
    cudaStreamWaitEvent(s2, eF, 0);
    tc_gemm<0, 0><<<dim3(8, 32), 256, TC_SMEM, s2>>>(xC_, WPQ_, bPQ_, PQ_, nullptr, 1024);
    cudaEventRecord(eP, s2);

    // s0: output projection (full ctx: eG in-stream, wait eL)
    cudaStreamWaitEvent(0, eL, 0);
    tc_gemm<0, 0><<<dim3(4, 32), 256, TC_SMEM>>>(xC_, WHi_ + 3 * WSZ,
                                                 bo, out, nullptr, 512);

    // s0: eu (needs PQ), then Wu2
    cudaStreamWaitEvent(0, eP, 0);
    eu_kernel<<<ROWS, 256>>>(PQ_, pair_j, eu_);
    tc_gemm<0, 0><<<dim3(4, 512), 256, TC_SMEM>>>(eu_, WHi_ + 6 * WSZ,
                                                  bu2, eupd, nullptr, 512);

    cudaEventDestroy(eW);
    cudaEventDestroy(eF);
    cudaEventDestroy(eQKV);
    cudaEventDestroy(eL);
    cudaEventDestroy(eG);
    cudaEventDestroy(eP);
    cudaStreamDestroy(s2);
    cudaStreamDestroy(s3);
}